// round 1
// baseline (speedup 1.0000x reference)
#include <cuda_runtime.h>
#include <cuda_bf16.h>
#include <cstdint>

#define D_MODEL 1024
#define N_HEADS 16
#define DK 64
#define BATCH 2
#define TSEQ 2048
#define MROWS (BATCH*TSEQ)   /* 4096 */
#define CHUNK 128
#define NCHUNK (TSEQ/CHUNK)  /* 16 */
#define NBH (BATCH*N_HEADS)  /* 32 */

// ---------------- scratch (static device arrays; no allocation) ----------------
__device__ float g_q[NBH*TSEQ*DK];          // phi(q) in [bh, t, d] layout
__device__ float g_k[NBH*TSEQ*DK];          // phi(k)
__device__ float g_v[NBH*TSEQ*DK];          // v
__device__ float g_attn[MROWS*D_MODEL];     // attention output in [m, d_model]
__device__ float g_kv[NBH*NCHUNK*DK*DK];    // per-chunk K^T V sums -> exclusive prefix
__device__ float g_ks[NBH*NCHUNK*DK];       // per-chunk k sums    -> exclusive prefix

__device__ __forceinline__ float phi_fn(float x) {
    return x > 0.f ? x + 1.f : __expf(x);
}

// ---------------- GEMM: Y = X @ W^T + bias, fp32 tiled ----------------
// EP=0: phi -> g_q (head layout)   EP=1: phi -> g_k   EP=2: plain -> g_v
// EP=3: X := g_attn, plain -> outp ([m, n] layout)
#define BM 128
#define BN 64
#define BK 16

template<int EP>
__global__ __launch_bounds__(256) void gemm_xwt(
    const float* __restrict__ X, const float* __restrict__ W,
    const float* __restrict__ bias, float* __restrict__ outp)
{
    __shared__ float Xs[BK][BM+4];
    __shared__ float Ws[BK][BN+4];
    const float* Xp = (EP == 3) ? (const float*)g_attn : X;

    const int tid = threadIdx.x;
    const int tx = tid & 15;       // 0..15 -> 4 cols each
    const int ty = tid >> 4;       // 0..15 -> 8 rows each
    const int m0 = blockIdx.y * BM;
    const int n0 = blockIdx.x * BN;

    float acc[8][4];
    #pragma unroll
    for (int i = 0; i < 8; i++)
        #pragma unroll
        for (int j = 0; j < 4; j++) acc[i][j] = 0.f;

    for (int k0 = 0; k0 < D_MODEL; k0 += BK) {
        // load X tile [BM][BK] -> Xs[k][m]
        #pragma unroll
        for (int l = 0; l < 2; l++) {
            int idx = tid + l*256;           // 0..511
            int r   = idx >> 2;              // row 0..127
            int q4  = idx & 3;               // which float4 of the 16 k's
            float4 v = *(const float4*)(Xp + (size_t)(m0 + r)*D_MODEL + k0 + q4*4);
            Xs[q4*4+0][r] = v.x; Xs[q4*4+1][r] = v.y;
            Xs[q4*4+2][r] = v.z; Xs[q4*4+3][r] = v.w;
        }
        // load W tile [BN][BK] -> Ws[k][n]
        {
            int r  = tid >> 2;               // 0..63
            int q4 = tid & 3;
            float4 v = *(const float4*)(W + (size_t)(n0 + r)*D_MODEL + k0 + q4*4);
            Ws[q4*4+0][r] = v.x; Ws[q4*4+1][r] = v.y;
            Ws[q4*4+2][r] = v.z; Ws[q4*4+3][r] = v.w;
        }
        __syncthreads();

        #pragma unroll
        for (int kk = 0; kk < BK; kk++) {
            float4 a0 = *(const float4*)&Xs[kk][ty*8];
            float4 a1 = *(const float4*)&Xs[kk][ty*8 + 4];
            float4 b0 = *(const float4*)&Ws[kk][tx*4];
            float a[8] = {a0.x, a0.y, a0.z, a0.w, a1.x, a1.y, a1.z, a1.w};
            float b[4] = {b0.x, b0.y, b0.z, b0.w};
            #pragma unroll
            for (int i = 0; i < 8; i++)
                #pragma unroll
                for (int j = 0; j < 4; j++)
                    acc[i][j] += a[i] * b[j];
        }
        __syncthreads();
    }

    // epilogue
    float bb[4];
    #pragma unroll
    for (int j = 0; j < 4; j++) bb[j] = bias[n0 + tx*4 + j];

    const int h = n0 >> 6;  // BN==64 -> block covers exactly one head
    #pragma unroll
    for (int i = 0; i < 8; i++) {
        int m = m0 + ty*8 + i;
        float r0 = acc[i][0] + bb[0];
        float r1 = acc[i][1] + bb[1];
        float r2 = acc[i][2] + bb[2];
        float r3 = acc[i][3] + bb[3];
        if (EP == 0 || EP == 1) {
            r0 = phi_fn(r0); r1 = phi_fn(r1); r2 = phi_fn(r2); r3 = phi_fn(r3);
        }
        float4 w = make_float4(r0, r1, r2, r3);
        if (EP <= 2) {
            int b = m >> 11;          // /TSEQ
            int t = m & (TSEQ - 1);
            float* dst = (EP == 0) ? g_q : (EP == 1) ? g_k : g_v;
            *(float4*)(dst + ((size_t)(b*N_HEADS + h)*TSEQ + t)*DK + tx*4) = w;
        } else {
            *(float4*)(outp + (size_t)m*D_MODEL + n0 + tx*4) = w;
        }
    }
}

// ---------------- per-chunk K^T V and k-sum ----------------
__global__ __launch_bounds__(256) void chunk_kv_kernel()
{
    __shared__ float ks[16][64];
    __shared__ float vs[16][64];
    const int blk = blockIdx.x;             // bh*NCHUNK + c
    const int bh = blk >> 4, c = blk & 15;
    const int tid = threadIdx.x;
    const int tx = tid & 15, ty = tid >> 4;

    float acc[4][4];
    #pragma unroll
    for (int r = 0; r < 4; r++)
        #pragma unroll
        for (int j = 0; j < 4; j++) acc[r][j] = 0.f;
    float ksum[4] = {0.f, 0.f, 0.f, 0.f};

    const size_t base = (size_t)bh*TSEQ*DK + (size_t)c*CHUNK*DK;
    const int lrow = tid >> 4, lc4 = tid & 15;   // one float4 per thread per tile

    for (int t0 = 0; t0 < CHUNK; t0 += 16) {
        ((float4*)ks[lrow])[lc4] = *(const float4*)(g_k + base + (size_t)(t0+lrow)*DK + lc4*4);
        ((float4*)vs[lrow])[lc4] = *(const float4*)(g_v + base + (size_t)(t0+lrow)*DK + lc4*4);
        __syncthreads();
        #pragma unroll
        for (int tt = 0; tt < 16; tt++) {
            float a[4];
            #pragma unroll
            for (int r = 0; r < 4; r++) a[r] = ks[tt][ty + r*16];
            float4 bv = ((float4*)vs[tt])[tx];
            float b[4] = {bv.x, bv.y, bv.z, bv.w};
            #pragma unroll
            for (int r = 0; r < 4; r++)
                #pragma unroll
                for (int j = 0; j < 4; j++) acc[r][j] += a[r]*b[j];
            if (tx == 0) {
                #pragma unroll
                for (int r = 0; r < 4; r++) ksum[r] += a[r];
            }
        }
        __syncthreads();
    }

    float* kvout = g_kv + (size_t)blk*DK*DK;
    #pragma unroll
    for (int r = 0; r < 4; r++) {
        int d = ty + r*16;
        #pragma unroll
        for (int j = 0; j < 4; j++)
            kvout[(size_t)d*DK + tx*4 + j] = acc[r][j];
    }
    if (tx == 0) {
        #pragma unroll
        for (int r = 0; r < 4; r++)
            g_ks[(size_t)blk*DK + ty + r*16] = ksum[r];
    }
}

// ---------------- exclusive prefix scan over chunks (in place) ----------------
__global__ __launch_bounds__(256) void chunk_scan_kernel()
{
    const int bh = blockIdx.x;
    const int tid = threadIdx.x;
    for (int j = tid; j < DK*DK; j += 256) {
        float run = 0.f;
        #pragma unroll
        for (int c = 0; c < NCHUNK; c++) {
            float* p = g_kv + ((size_t)(bh*NCHUNK + c))*DK*DK + j;
            float tmp = *p; *p = run; run += tmp;
        }
    }
    if (tid < DK) {
        float run = 0.f;
        #pragma unroll
        for (int c = 0; c < NCHUNK; c++) {
            float* p = g_ks + (size_t)(bh*NCHUNK + c)*DK + tid;
            float tmp = *p; *p = run; run += tmp;
        }
    }
}

// ---------------- per-chunk attention output ----------------
// smem: Ks[128*64] Vs[128*64] Ss[64*64] sp[64]  = 82176 bytes
#define SMEM4 ((CHUNK*DK*2 + DK*DK + DK) * (int)sizeof(float))

extern __shared__ float s4[];
__global__ __launch_bounds__(256) void attn_chunk_kernel()
{
    float* Ks = s4;                       // 8192
    float* Vs = s4 + CHUNK*DK;            // 8192
    float* Ss = s4 + 2*CHUNK*DK;          // 4096
    float* sp = s4 + 2*CHUNK*DK + DK*DK;  // 64

    const int blk = blockIdx.x;
    const int bh = blk >> 4, c = blk & 15;
    const int tid = threadIdx.x;
    const size_t base = (size_t)bh*TSEQ*DK + (size_t)c*CHUNK*DK;

    for (int l = tid; l < CHUNK*DK/4; l += 256) {
        ((float4*)Ks)[l] = *(const float4*)(g_k + base + (size_t)l*4);
        ((float4*)Vs)[l] = *(const float4*)(g_v + base + (size_t)l*4);
    }
    for (int l = tid; l < DK*DK/4; l += 256)
        ((float4*)Ss)[l] = *(const float4*)(g_kv + (size_t)blk*DK*DK + (size_t)l*4);
    if (tid < DK/4)
        ((float4*)sp)[tid] = *(const float4*)(g_ks + (size_t)blk*DK + tid*4);
    __syncthreads();

    const int t  = tid & 127;       // row within chunk
    const int e0 = (tid >> 7) * 32; // output-dim half

    float q[64];
    #pragma unroll
    for (int d4 = 0; d4 < 16; d4++) {
        float4 w = *(const float4*)(g_q + base + (size_t)t*DK + d4*4);
        q[d4*4+0] = w.x; q[d4*4+1] = w.y; q[d4*4+2] = w.z; q[d4*4+3] = w.w;
    }

    float out[32];
    #pragma unroll
    for (int j = 0; j < 32; j++) out[j] = 0.f;
    float z = 0.f;

    // inter-chunk part: out += q @ S_prev ; z += q . ksum_prev
    #pragma unroll
    for (int d = 0; d < 64; d++) {
        float qd = q[d];
        const float* srow = Ss + d*DK + e0;
        #pragma unroll
        for (int j = 0; j < 32; j++) out[j] += qd * srow[j];
        z += qd * sp[d];
    }

    // intra-chunk causal part, 2-way i-unroll with split dot accumulators
    const int nIt = t + 1;
    int i = 0;
    for (; i + 1 < nIt; i += 2) {
        const float* k0p = Ks + (size_t)i*DK;
        const float* k1p = k0p + DK;
        float a00=0.f,a01=0.f,a02=0.f,a03=0.f;
        float a10=0.f,a11=0.f,a12=0.f,a13=0.f;
        #pragma unroll
        for (int d4 = 0; d4 < 16; d4++) {
            float4 k0v = ((const float4*)k0p)[d4];
            float4 k1v = ((const float4*)k1p)[d4];
            a00 += q[d4*4+0]*k0v.x; a01 += q[d4*4+1]*k0v.y;
            a02 += q[d4*4+2]*k0v.z; a03 += q[d4*4+3]*k0v.w;
            a10 += q[d4*4+0]*k1v.x; a11 += q[d4*4+1]*k1v.y;
            a12 += q[d4*4+2]*k1v.z; a13 += q[d4*4+3]*k1v.w;
        }
        float a0 = (a00+a01)+(a02+a03);
        float a1 = (a10+a11)+(a12+a13);
        z += a0 + a1;
        const float* v0p = Vs + (size_t)i*DK + e0;
        const float* v1p = v0p + DK;
        #pragma unroll
        for (int j4 = 0; j4 < 8; j4++) {
            float4 v0 = ((const float4*)v0p)[j4];
            float4 v1 = ((const float4*)v1p)[j4];
            out[j4*4+0] += a0*v0.x; out[j4*4+0] += a1*v1.x;
            out[j4*4+1] += a0*v0.y; out[j4*4+1] += a1*v1.y;
            out[j4*4+2] += a0*v0.z; out[j4*4+2] += a1*v1.z;
            out[j4*4+3] += a0*v0.w; out[j4*4+3] += a1*v1.w;
        }
    }
    if (i < nIt) {
        const float* kp = Ks + (size_t)i*DK;
        float a0=0.f,a1=0.f,a2=0.f,a3=0.f;
        #pragma unroll
        for (int d4 = 0; d4 < 16; d4++) {
            float4 kv = ((const float4*)kp)[d4];
            a0 += q[d4*4+0]*kv.x; a1 += q[d4*4+1]*kv.y;
            a2 += q[d4*4+2]*kv.z; a3 += q[d4*4+3]*kv.w;
        }
        float a = (a0+a1)+(a2+a3);
        z += a;
        const float* vp = Vs + (size_t)i*DK + e0;
        #pragma unroll
        for (int j = 0; j < 32; j++) out[j] += a * vp[j];
    }

    const float inv = 1.f / (z + 1e-6f);
    const int b = bh >> 4, h = bh & 15;
    float* dst = g_attn + ((size_t)(b*TSEQ + c*CHUNK + t))*D_MODEL + h*DK + e0;
    #pragma unroll
    for (int j = 0; j < 32; j += 4) {
        float4 w = make_float4(out[j]*inv, out[j+1]*inv, out[j+2]*inv, out[j+3]*inv);
        *(float4*)(dst + j) = w;
    }
}

// ---------------- launch ----------------
extern "C" void kernel_launch(void* const* d_in, const int* in_sizes, int n_in,
                              void* d_out, int out_size)
{
    (void)in_sizes; (void)n_in; (void)out_size;
    const float* x  = (const float*)d_in[0];
    const float* Wq = (const float*)d_in[1];
    const float* bq = (const float*)d_in[2];
    const float* Wk = (const float*)d_in[3];
    const float* bk = (const float*)d_in[4];
    const float* Wv = (const float*)d_in[5];
    const float* bv = (const float*)d_in[6];
    const float* Wo = (const float*)d_in[7];
    const float* bo = (const float*)d_in[8];
    float* out = (float*)d_out;

    cudaFuncSetAttribute(attn_chunk_kernel,
                         cudaFuncAttributeMaxDynamicSharedMemorySize, SMEM4);

    dim3 ggrid(D_MODEL/BN, MROWS/BM);   // (16, 32)

    gemm_xwt<0><<<ggrid, 256>>>(x, Wq, bq, nullptr);   // phi(q) -> g_q
    gemm_xwt<1><<<ggrid, 256>>>(x, Wk, bk, nullptr);   // phi(k) -> g_k
    gemm_xwt<2><<<ggrid, 256>>>(x, Wv, bv, nullptr);   // v      -> g_v

    chunk_kv_kernel<<<NBH*NCHUNK, 256>>>();            // 512 blocks
    chunk_scan_kernel<<<NBH, 256>>>();                 // exclusive prefix over chunks
    attn_chunk_kernel<<<NBH*NCHUNK, 256, SMEM4>>>();   // 512 blocks

    gemm_xwt<3><<<ggrid, 256>>>(nullptr, Wo, bo, out); // g_attn @ Wo^T + bo -> out
}

// round 3
// speedup vs baseline: 2.0828x; 2.0828x over previous
#include <cuda_runtime.h>
#include <cuda_bf16.h>
#include <cstdint>

#define D_MODEL 1024
#define N_HEADS 16
#define DK 64
#define BATCH 2
#define TSEQ 2048
#define MROWS (BATCH*TSEQ)   /* 4096 */
#define CHUNK 128
#define NCHUNK (TSEQ/CHUNK)  /* 16 */
#define NBH (BATCH*N_HEADS)  /* 32 */

// ---------------- scratch (static device arrays; no allocation) ----------------
__device__ float g_q[NBH*TSEQ*DK];
__device__ float g_k[NBH*TSEQ*DK];
__device__ float g_v[NBH*TSEQ*DK];
__device__ float g_kv[NBH*NCHUNK*DK*DK];
__device__ float g_ks[NBH*NCHUNK*DK];
// split-bf16 operands
__device__ __nv_bfloat16 g_x_hi[MROWS*D_MODEL];
__device__ __nv_bfloat16 g_x_lo[MROWS*D_MODEL];
__device__ __nv_bfloat16 g_w_hi[4*D_MODEL*D_MODEL];
__device__ __nv_bfloat16 g_w_lo[4*D_MODEL*D_MODEL];
__device__ __nv_bfloat16 g_a_hi[MROWS*D_MODEL];
__device__ __nv_bfloat16 g_a_lo[MROWS*D_MODEL];

__device__ __forceinline__ float phi_fn(float x) {
    return x > 0.f ? x + 1.f : __expf(x);
}

__device__ __forceinline__ uint32_t smem_to_u32(const void* smem_ptr) {
    uint32_t addr;
    asm("{ .reg .u64 tmp; cvta.to.shared.u64 tmp, %1; cvt.u32.u64 %0, tmp; }"
        : "=r"(addr) : "l"(smem_ptr));
    return addr;
}

// ---------------- mma.sync / ldmatrix / cp.async primitives ----------------
__device__ __forceinline__ void mma16816(float* d, const uint32_t* a, const uint32_t* b) {
    asm volatile(
        "mma.sync.aligned.m16n8k16.row.col.f32.bf16.bf16.f32 "
        "{%0,%1,%2,%3}, {%4,%5,%6,%7}, {%8,%9}, {%0,%1,%2,%3};"
        : "+f"(d[0]), "+f"(d[1]), "+f"(d[2]), "+f"(d[3])
        : "r"(a[0]), "r"(a[1]), "r"(a[2]), "r"(a[3]), "r"(b[0]), "r"(b[1]));
}
__device__ __forceinline__ void ldsm4(uint32_t* r, uint32_t addr) {
    asm volatile("ldmatrix.sync.aligned.m8n8.x4.shared.b16 {%0,%1,%2,%3}, [%4];"
        : "=r"(r[0]), "=r"(r[1]), "=r"(r[2]), "=r"(r[3]) : "r"(addr));
}
#define CP_ASYNC16(dst, src) \
    asm volatile("cp.async.cg.shared.global [%0], [%1], 16;" :: "r"(dst), "l"(src))
#define CP_COMMIT() asm volatile("cp.async.commit_group;" ::: "memory")
#define CP_WAIT1()  asm volatile("cp.async.wait_group 1;" ::: "memory")
#define CP_WAIT0()  asm volatile("cp.async.wait_group 0;" ::: "memory")

// ---------------- fp32 -> bf16 hi/lo split ----------------
__global__ __launch_bounds__(256) void split_kernel(const float* __restrict__ src,
                                                    int dst_sel, int n4)
{
    int i = blockIdx.x * 256 + threadIdx.x;
    if (i >= n4) return;
    __nv_bfloat16* hi = (dst_sel == 0) ? g_x_hi
                      : g_w_hi + (size_t)(dst_sel - 1) * D_MODEL * D_MODEL;
    __nv_bfloat16* lo = (dst_sel == 0) ? g_x_lo
                      : g_w_lo + (size_t)(dst_sel - 1) * D_MODEL * D_MODEL;
    float4 v = ((const float4*)src)[i];
    __nv_bfloat16 h0 = __float2bfloat16(v.x), h1 = __float2bfloat16(v.y);
    __nv_bfloat16 h2 = __float2bfloat16(v.z), h3 = __float2bfloat16(v.w);
    __nv_bfloat162 ph0; ph0.x = h0; ph0.y = h1;
    __nv_bfloat162 ph1; ph1.x = h2; ph1.y = h3;
    __nv_bfloat162 pl0;
    pl0.x = __float2bfloat16(v.x - __bfloat162float(h0));
    pl0.y = __float2bfloat16(v.y - __bfloat162float(h1));
    __nv_bfloat162 pl1;
    pl1.x = __float2bfloat16(v.z - __bfloat162float(h2));
    pl1.y = __float2bfloat16(v.w - __bfloat162float(h3));
    ((__nv_bfloat162*)(hi + 4*(size_t)i))[0] = ph0;
    ((__nv_bfloat162*)(hi + 4*(size_t)i))[1] = ph1;
    ((__nv_bfloat162*)(lo + 4*(size_t)i))[0] = pl0;
    ((__nv_bfloat162*)(lo + 4*(size_t)i))[1] = pl1;
}

// ---------------- split-bf16 GEMM via mma.sync: Y = X @ W^T + bias ----------------
// EP = 0(Wq->phi->g_q) 1(Wk->phi->g_k) 2(Wv->g_v) 3(g_a @ Wo^T -> outp)
// CTA tile 128x128, BK=32, double-buffered cp.async.
// smem tile: 128 rows x 80B pitch (64B data + 16B pad) = 10240 B
#define PITCH 80
#define TILE_B (128*PITCH)          /* 10240 */
#define STAGE_B (4*TILE_B)          /* AH AL BH BL = 40960 */
#define GEMM_SMEM (2*STAGE_B)       /* 81920 */
#define NSTG 32                     /* K / 32 */

template<int EP>
__global__ __launch_bounds__(256) void gemm_mma(const float* __restrict__ bias,
                                                float* __restrict__ outp)
{
    extern __shared__ char smem[];
    const uint32_t sb = smem_to_u32(smem);
    const int tid = threadIdx.x;
    const int lane = tid & 31, wid = tid >> 5;
    const int wm = wid & 1, wn = wid >> 1;      // 2 x 4 warp grid
    const int m0 = blockIdx.y * 128;
    const int n0 = blockIdx.x * 128;

    const __nv_bfloat16* Xh = (EP == 3) ? g_a_hi : g_x_hi;
    const __nv_bfloat16* Xl = (EP == 3) ? g_a_lo : g_x_lo;
    const __nv_bfloat16* Wh = g_w_hi + (size_t)EP * D_MODEL * D_MODEL;
    const __nv_bfloat16* Wl = g_w_lo + (size_t)EP * D_MODEL * D_MODEL;

    float acc[4][4][4];
    #pragma unroll
    for (int i = 0; i < 4; i++)
        #pragma unroll
        for (int j = 0; j < 4; j++)
            #pragma unroll
            for (int l = 0; l < 4; l++) acc[i][j][l] = 0.f;

    // per-thread load assignment: idx -> row idx>>2, 16B chunk idx&3
    const int r0l = tid >> 2, c0l = tid & 3;
    const int r1l = (tid + 256) >> 2, c1l = tid & 3;

    auto load_stage = [&](int buf, int k0) {
        uint32_t base = sb + buf * STAGE_B;
        #pragma unroll
        for (int t = 0; t < 4; t++) {
            const __nv_bfloat16* src = (t == 0) ? Xh : (t == 1) ? Xl : (t == 2) ? Wh : Wl;
            const int row0 = (t < 2) ? m0 : n0;
            CP_ASYNC16(base + t*TILE_B + r0l*PITCH + c0l*16,
                       src + (size_t)(row0 + r0l)*D_MODEL + k0 + c0l*8);
            CP_ASYNC16(base + t*TILE_B + r1l*PITCH + c1l*16,
                       src + (size_t)(row0 + r1l)*D_MODEL + k0 + c1l*8);
        }
        CP_COMMIT();
    };

    load_stage(0, 0);

    // ldmatrix relative offsets
    const uint32_t a_off = (uint32_t)((wm*64 + (lane & 15)) * PITCH + (lane >> 4) * 16);
    const uint32_t b_off = (uint32_t)((wn*32 + ((lane >> 4) << 3) + (lane & 7)) * PITCH
                                      + ((lane >> 3) & 1) * 16);

    for (int kc = 0; kc < NSTG; kc++) {
        if (kc < NSTG-1) { load_stage((kc+1) & 1, (kc+1)*32); CP_WAIT1(); }
        else             { CP_WAIT0(); }
        __syncthreads();

        const uint32_t base = sb + (kc & 1) * STAGE_B;
        #pragma unroll
        for (int ks = 0; ks < 2; ks++) {
            const uint32_t koff = ks * 32;   // 16 bf16 = 32 bytes
            uint32_t ah[4][4], al[4][4], bh[2][4], bl[2][4];
            #pragma unroll
            for (int mt = 0; mt < 4; mt++) {
                ldsm4(ah[mt], base + 0*TILE_B + a_off + mt*16*PITCH + koff);
                ldsm4(al[mt], base + 1*TILE_B + a_off + mt*16*PITCH + koff);
            }
            #pragma unroll
            for (int op = 0; op < 2; op++) {
                ldsm4(bh[op], base + 2*TILE_B + b_off + op*16*PITCH + koff);
                ldsm4(bl[op], base + 3*TILE_B + b_off + op*16*PITCH + koff);
            }
            #pragma unroll
            for (int mt = 0; mt < 4; mt++)
                #pragma unroll
                for (int nt = 0; nt < 4; nt++) {
                    const uint32_t* bhp = &bh[nt >> 1][(nt & 1) * 2];
                    const uint32_t* blp = &bl[nt >> 1][(nt & 1) * 2];
                    mma16816(acc[mt][nt], ah[mt], bhp);
                    mma16816(acc[mt][nt], al[mt], bhp);
                    mma16816(acc[mt][nt], ah[mt], blp);
                }
        }
        __syncthreads();
    }

    // ---- epilogue ----
    const int m_base = m0 + wm*64;
    #pragma unroll
    for (int mt = 0; mt < 4; mt++) {
        #pragma unroll
        for (int nt = 0; nt < 4; nt++) {
            const int n = n0 + wn*32 + nt*8 + (lane & 3)*2;
            const float b0v = bias[n], b1v = bias[n+1];
            #pragma unroll
            for (int half = 0; half < 2; half++) {
                const int m = m_base + mt*16 + (lane >> 2) + half*8;
                float y0 = acc[mt][nt][half*2+0] + b0v;
                float y1 = acc[mt][nt][half*2+1] + b1v;
                if (EP <= 1) { y0 = phi_fn(y0); y1 = phi_fn(y1); }
                if (EP <= 2) {
                    const int h = n >> 6, d = n & 63;
                    const int b = m >> 11, t = m & (TSEQ-1);
                    float* dst = (EP == 0) ? g_q : (EP == 1) ? g_k : g_v;
                    *(float2*)(dst + ((size_t)((b*N_HEADS + h)*TSEQ + t))*DK + d)
                        = make_float2(y0, y1);
                } else {
                    *(float2*)(outp + (size_t)m*D_MODEL + n) = make_float2(y0, y1);
                }
            }
        }
    }
}

// ---------------- per-chunk K^T V and k-sum ----------------
__global__ __launch_bounds__(256) void chunk_kv_kernel()
{
    __shared__ float ks[16][64];
    __shared__ float vs[16][64];
    const int blk = blockIdx.x;
    const int bh = blk >> 4, c = blk & 15;
    const int tid = threadIdx.x;
    const int tx = tid & 15, ty = tid >> 4;

    float acc[4][4];
    #pragma unroll
    for (int r = 0; r < 4; r++)
        #pragma unroll
        for (int j = 0; j < 4; j++) acc[r][j] = 0.f;
    float ksum[4] = {0.f, 0.f, 0.f, 0.f};

    const size_t base = (size_t)bh*TSEQ*DK + (size_t)c*CHUNK*DK;
    const int lrow = tid >> 4, lc4 = tid & 15;

    for (int t0 = 0; t0 < CHUNK; t0 += 16) {
        ((float4*)ks[lrow])[lc4] = *(const float4*)(g_k + base + (size_t)(t0+lrow)*DK + lc4*4);
        ((float4*)vs[lrow])[lc4] = *(const float4*)(g_v + base + (size_t)(t0+lrow)*DK + lc4*4);
        __syncthreads();
        #pragma unroll
        for (int tt = 0; tt < 16; tt++) {
            float a[4];
            #pragma unroll
            for (int r = 0; r < 4; r++) a[r] = ks[tt][ty + r*16];
            float4 bv = ((float4*)vs[tt])[tx];
            float b[4] = {bv.x, bv.y, bv.z, bv.w};
            #pragma unroll
            for (int r = 0; r < 4; r++)
                #pragma unroll
                for (int j = 0; j < 4; j++) acc[r][j] += a[r]*b[j];
            if (tx == 0) {
                #pragma unroll
                for (int r = 0; r < 4; r++) ksum[r] += a[r];
            }
        }
        __syncthreads();
    }

    float* kvout = g_kv + (size_t)blk*DK*DK;
    #pragma unroll
    for (int r = 0; r < 4; r++) {
        int d = ty + r*16;
        #pragma unroll
        for (int j = 0; j < 4; j++)
            kvout[(size_t)d*DK + tx*4 + j] = acc[r][j];
    }
    if (tx == 0) {
        #pragma unroll
        for (int r = 0; r < 4; r++)
            g_ks[(size_t)blk*DK + ty + r*16] = ksum[r];
    }
}

// ---------------- exclusive prefix scan over chunks (in place) ----------------
__global__ __launch_bounds__(256) void chunk_scan_kernel()
{
    const int bh = blockIdx.x;
    const int tid = threadIdx.x;
    for (int j = tid; j < DK*DK; j += 256) {
        float run = 0.f;
        #pragma unroll
        for (int c = 0; c < NCHUNK; c++) {
            float* p = g_kv + ((size_t)(bh*NCHUNK + c))*DK*DK + j;
            float tmp = *p; *p = run; run += tmp;
        }
    }
    if (tid < DK) {
        float run = 0.f;
        #pragma unroll
        for (int c = 0; c < NCHUNK; c++) {
            float* p = g_ks + (size_t)(bh*NCHUNK + c)*DK + tid;
            float tmp = *p; *p = run; run += tmp;
        }
    }
}

// ---------------- per-chunk attention output ----------------
#define SMEM4 ((CHUNK*DK*2 + DK*DK + DK) * (int)sizeof(float))

extern __shared__ float s4[];
__global__ __launch_bounds__(256) void attn_chunk_kernel()
{
    float* Ks = s4;
    float* Vs = s4 + CHUNK*DK;
    float* Ss = s4 + 2*CHUNK*DK;
    float* sp = s4 + 2*CHUNK*DK + DK*DK;

    const int blk = blockIdx.x;
    const int bh = blk >> 4, c = blk & 15;
    const int tid = threadIdx.x;
    const size_t base = (size_t)bh*TSEQ*DK + (size_t)c*CHUNK*DK;

    for (int l = tid; l < CHUNK*DK/4; l += 256) {
        ((float4*)Ks)[l] = *(const float4*)(g_k + base + (size_t)l*4);
        ((float4*)Vs)[l] = *(const float4*)(g_v + base + (size_t)l*4);
    }
    for (int l = tid; l < DK*DK/4; l += 256)
        ((float4*)Ss)[l] = *(const float4*)(g_kv + (size_t)blk*DK*DK + (size_t)l*4);
    if (tid < DK/4)
        ((float4*)sp)[tid] = *(const float4*)(g_ks + (size_t)blk*DK + tid*4);
    __syncthreads();

    const int t  = tid & 127;
    const int e0 = (tid >> 7) * 32;

    float q[64];
    #pragma unroll
    for (int d4 = 0; d4 < 16; d4++) {
        float4 w = *(const float4*)(g_q + base + (size_t)t*DK + d4*4);
        q[d4*4+0] = w.x; q[d4*4+1] = w.y; q[d4*4+2] = w.z; q[d4*4+3] = w.w;
    }

    float out[32];
    #pragma unroll
    for (int j = 0; j < 32; j++) out[j] = 0.f;
    float z = 0.f;

    #pragma unroll
    for (int d = 0; d < 64; d++) {
        float qd = q[d];
        const float* srow = Ss + d*DK + e0;
        #pragma unroll
        for (int j = 0; j < 32; j++) out[j] += qd * srow[j];
        z += qd * sp[d];
    }

    const int nIt = t + 1;
    int i = 0;
    for (; i + 1 < nIt; i += 2) {
        const float* k0p = Ks + (size_t)i*DK;
        const float* k1p = k0p + DK;
        float a00=0.f,a01=0.f,a02=0.f,a03=0.f;
        float a10=0.f,a11=0.f,a12=0.f,a13=0.f;
        #pragma unroll
        for (int d4 = 0; d4 < 16; d4++) {
            float4 k0v = ((const float4*)k0p)[d4];
            float4 k1v = ((const float4*)k1p)[d4];
            a00 += q[d4*4+0]*k0v.x; a01 += q[d4*4+1]*k0v.y;
            a02 += q[d4*4+2]*k0v.z; a03 += q[d4*4+3]*k0v.w;
            a10 += q[d4*4+0]*k1v.x; a11 += q[d4*4+1]*k1v.y;
            a12 += q[d4*4+2]*k1v.z; a13 += q[d4*4+3]*k1v.w;
        }
        float a0 = (a00+a01)+(a02+a03);
        float a1 = (a10+a11)+(a12+a13);
        z += a0 + a1;
        const float* v0p = Vs + (size_t)i*DK + e0;
        const float* v1p = v0p + DK;
        #pragma unroll
        for (int j4 = 0; j4 < 8; j4++) {
            float4 v0 = ((const float4*)v0p)[j4];
            float4 v1 = ((const float4*)v1p)[j4];
            out[j4*4+0] += a0*v0.x; out[j4*4+0] += a1*v1.x;
            out[j4*4+1] += a0*v0.y; out[j4*4+1] += a1*v1.y;
            out[j4*4+2] += a0*v0.z; out[j4*4+2] += a1*v1.z;
            out[j4*4+3] += a0*v0.w; out[j4*4+3] += a1*v1.w;
        }
    }
    if (i < nIt) {
        const float* kp = Ks + (size_t)i*DK;
        float a0=0.f,a1=0.f,a2=0.f,a3=0.f;
        #pragma unroll
        for (int d4 = 0; d4 < 16; d4++) {
            float4 kv = ((const float4*)kp)[d4];
            a0 += q[d4*4+0]*kv.x; a1 += q[d4*4+1]*kv.y;
            a2 += q[d4*4+2]*kv.z; a3 += q[d4*4+3]*kv.w;
        }
        float a = (a0+a1)+(a2+a3);
        z += a;
        const float* vp = Vs + (size_t)i*DK + e0;
        #pragma unroll
        for (int j = 0; j < 32; j++) out[j] += a * vp[j];
    }

    const float inv = 1.f / (z + 1e-6f);
    const int b = bh >> 4, h = bh & 15;
    const size_t off = ((size_t)(b*TSEQ + c*CHUNK + t))*D_MODEL + h*DK + e0;
    __nv_bfloat16* dhi = g_a_hi + off;
    __nv_bfloat16* dlo = g_a_lo + off;
    #pragma unroll
    for (int j = 0; j < 32; j += 2) {
        float o0 = out[j]*inv, o1 = out[j+1]*inv;
        __nv_bfloat16 h0 = __float2bfloat16(o0);
        __nv_bfloat16 h1 = __float2bfloat16(o1);
        __nv_bfloat162 ph; ph.x = h0; ph.y = h1;
        __nv_bfloat162 pl;
        pl.x = __float2bfloat16(o0 - __bfloat162float(h0));
        pl.y = __float2bfloat16(o1 - __bfloat162float(h1));
        *(__nv_bfloat162*)(dhi + j) = ph;
        *(__nv_bfloat162*)(dlo + j) = pl;
    }
}

// ---------------- launch ----------------
extern "C" void kernel_launch(void* const* d_in, const int* in_sizes, int n_in,
                              void* d_out, int out_size)
{
    (void)in_sizes; (void)n_in; (void)out_size;
    const float* x  = (const float*)d_in[0];
    const float* Wq = (const float*)d_in[1];
    const float* bq = (const float*)d_in[2];
    const float* Wk = (const float*)d_in[3];
    const float* bk = (const float*)d_in[4];
    const float* Wv = (const float*)d_in[5];
    const float* bv = (const float*)d_in[6];
    const float* Wo = (const float*)d_in[7];
    const float* bo = (const float*)d_in[8];
    float* out = (float*)d_out;

    cudaFuncSetAttribute(attn_chunk_kernel,
                         cudaFuncAttributeMaxDynamicSharedMemorySize, SMEM4);
    cudaFuncSetAttribute(gemm_mma<0>, cudaFuncAttributeMaxDynamicSharedMemorySize, GEMM_SMEM);
    cudaFuncSetAttribute(gemm_mma<1>, cudaFuncAttributeMaxDynamicSharedMemorySize, GEMM_SMEM);
    cudaFuncSetAttribute(gemm_mma<2>, cudaFuncAttributeMaxDynamicSharedMemorySize, GEMM_SMEM);
    cudaFuncSetAttribute(gemm_mma<3>, cudaFuncAttributeMaxDynamicSharedMemorySize, GEMM_SMEM);

    split_kernel<<<(MROWS*D_MODEL/4 + 255)/256, 256>>>(x, 0, MROWS*D_MODEL/4);
    split_kernel<<<(D_MODEL*D_MODEL/4 + 255)/256, 256>>>(Wq, 1, D_MODEL*D_MODEL/4);
    split_kernel<<<(D_MODEL*D_MODEL/4 + 255)/256, 256>>>(Wk, 2, D_MODEL*D_MODEL/4);
    split_kernel<<<(D_MODEL*D_MODEL/4 + 255)/256, 256>>>(Wv, 3, D_MODEL*D_MODEL/4);
    split_kernel<<<(D_MODEL*D_MODEL/4 + 255)/256, 256>>>(Wo, 4, D_MODEL*D_MODEL/4);

    dim3 ggrid(D_MODEL/128, MROWS/128);   // (8, 32)
    gemm_mma<0><<<ggrid, 256, GEMM_SMEM>>>(bq, nullptr);
    gemm_mma<1><<<ggrid, 256, GEMM_SMEM>>>(bk, nullptr);
    gemm_mma<2><<<ggrid, 256, GEMM_SMEM>>>(bv, nullptr);

    chunk_kv_kernel<<<NBH*NCHUNK, 256>>>();
    chunk_scan_kernel<<<NBH, 256>>>();
    attn_chunk_kernel<<<NBH*NCHUNK, 256, SMEM4>>>();

    gemm_mma<3><<<ggrid, 256, GEMM_SMEM>>>(bo, out);
}

// round 4
// speedup vs baseline: 2.2164x; 1.0641x over previous
#include <cuda_runtime.h>
#include <cuda_bf16.h>
#include <cstdint>

#define D_MODEL 1024
#define N_HEADS 16
#define DK 64
#define BATCH 2
#define TSEQ 2048
#define MROWS (BATCH*TSEQ)   /* 4096 */
#define CHUNK 128
#define NCHUNK (TSEQ/CHUNK)  /* 16 */
#define NBH (BATCH*N_HEADS)  /* 32 */
#define KVE 72               /* KV ext cols: 64 + ksum + pad */

// ---------------- scratch (static device arrays; no allocation) ----------------
__device__ float g_kv[NBH*NCHUNK*DK*DK];     // per-chunk K^T V (fp32)
__device__ float g_ksum[NBH*NCHUNK*DK];      // per-chunk k column sums
// bf16 hi/lo operands
__device__ __nv_bfloat16 g_x_hi[MROWS*D_MODEL];
__device__ __nv_bfloat16 g_x_lo[MROWS*D_MODEL];
__device__ __nv_bfloat16 g_w_hi[4*D_MODEL*D_MODEL];
__device__ __nv_bfloat16 g_w_lo[4*D_MODEL*D_MODEL];
__device__ __nv_bfloat16 g_a_hi[MROWS*D_MODEL];
__device__ __nv_bfloat16 g_a_lo[MROWS*D_MODEL];
__device__ __nv_bfloat16 g_qh[NBH*TSEQ*DK], g_ql[NBH*TSEQ*DK];
__device__ __nv_bfloat16 g_kh[NBH*TSEQ*DK], g_kl[NBH*TSEQ*DK];
__device__ __nv_bfloat16 g_vh[NBH*TSEQ*DK], g_vl[NBH*TSEQ*DK];
__device__ __nv_bfloat16 g_kvh[NBH*NCHUNK*DK*KVE];  // exclusive-prefix KV ext, [d][e]
__device__ __nv_bfloat16 g_kvl[NBH*NCHUNK*DK*KVE];

__device__ __forceinline__ float phi_fn(float x) {
    return x > 0.f ? x + 1.f : __expf(x);
}
__device__ __forceinline__ uint32_t smem_to_u32(const void* smem_ptr) {
    uint32_t addr;
    asm("{ .reg .u64 tmp; cvta.to.shared.u64 tmp, %1; cvt.u32.u64 %0, tmp; }"
        : "=r"(addr) : "l"(smem_ptr));
    return addr;
}

// ---------------- mma / ldmatrix / cp.async primitives ----------------
__device__ __forceinline__ void mma16816(float* d, const uint32_t* a, const uint32_t* b) {
    asm volatile(
        "mma.sync.aligned.m16n8k16.row.col.f32.bf16.bf16.f32 "
        "{%0,%1,%2,%3}, {%4,%5,%6,%7}, {%8,%9}, {%0,%1,%2,%3};"
        : "+f"(d[0]), "+f"(d[1]), "+f"(d[2]), "+f"(d[3])
        : "r"(a[0]), "r"(a[1]), "r"(a[2]), "r"(a[3]), "r"(b[0]), "r"(b[1]));
}
__device__ __forceinline__ void ldsm4(uint32_t* r, uint32_t addr) {
    asm volatile("ldmatrix.sync.aligned.m8n8.x4.shared.b16 {%0,%1,%2,%3}, [%4];"
        : "=r"(r[0]), "=r"(r[1]), "=r"(r[2]), "=r"(r[3]) : "r"(addr));
}
__device__ __forceinline__ void ldsm4t(uint32_t* r, uint32_t addr) {
    asm volatile("ldmatrix.sync.aligned.m8n8.x4.trans.shared.b16 {%0,%1,%2,%3}, [%4];"
        : "=r"(r[0]), "=r"(r[1]), "=r"(r[2]), "=r"(r[3]) : "r"(addr));
}
__device__ __forceinline__ void ldsm2t(uint32_t* r, uint32_t addr) {
    asm volatile("ldmatrix.sync.aligned.m8n8.x2.trans.shared.b16 {%0,%1}, [%2];"
        : "=r"(r[0]), "=r"(r[1]) : "r"(addr));
}
#define CP_ASYNC16(dst, src) \
    asm volatile("cp.async.cg.shared.global [%0], [%1], 16;" :: "r"(dst), "l"(src))
#define CP_COMMIT() asm volatile("cp.async.commit_group;" ::: "memory")
#define CP_WAIT2()  asm volatile("cp.async.wait_group 2;" ::: "memory")
#define CP_WAIT1()  asm volatile("cp.async.wait_group 1;" ::: "memory")
#define CP_WAIT0()  asm volatile("cp.async.wait_group 0;" ::: "memory")

__device__ __forceinline__ uint32_t pack_bf16(float lo, float hi) {
    __nv_bfloat162 p = __floats2bfloat162_rn(lo, hi);   // .x = lo half
    return *reinterpret_cast<uint32_t*>(&p);
}
__device__ __forceinline__ void split_pair(float y, __nv_bfloat16& h, __nv_bfloat16& l) {
    h = __float2bfloat16(y);
    l = __float2bfloat16(y - __bfloat162float(h));
}

// ---------------- fp32 -> bf16 hi/lo splits ----------------
__global__ __launch_bounds__(256) void split_x_kernel(const float* __restrict__ src, int n4)
{
    int i = blockIdx.x * 256 + threadIdx.x;
    if (i >= n4) return;
    float4 v = ((const float4*)src)[i];
    __nv_bfloat16 h0,h1,h2,h3,l0,l1,l2,l3;
    split_pair(v.x,h0,l0); split_pair(v.y,h1,l1);
    split_pair(v.z,h2,l2); split_pair(v.w,h3,l3);
    __nv_bfloat162 ph0{h0,h1}, ph1{h2,h3}, pl0{l0,l1}, pl1{l2,l3};
    ((__nv_bfloat162*)(g_x_hi + 4*(size_t)i))[0] = ph0;
    ((__nv_bfloat162*)(g_x_hi + 4*(size_t)i))[1] = ph1;
    ((__nv_bfloat162*)(g_x_lo + 4*(size_t)i))[0] = pl0;
    ((__nv_bfloat162*)(g_x_lo + 4*(size_t)i))[1] = pl1;
}
__global__ __launch_bounds__(256) void split_w_kernel(
    const float* __restrict__ w0, const float* __restrict__ w1,
    const float* __restrict__ w2, const float* __restrict__ w3)
{
    const int per = D_MODEL*D_MODEL/4;   // 262144 float4 per W
    int i = blockIdx.x * 256 + threadIdx.x;
    int sel = i >> 18, loc = i & (per - 1);
    const float* src = (sel == 0) ? w0 : (sel == 1) ? w1 : (sel == 2) ? w2 : w3;
    float4 v = ((const float4*)src)[loc];
    size_t o = (size_t)sel * D_MODEL * D_MODEL + 4*(size_t)loc;
    __nv_bfloat16 h0,h1,h2,h3,l0,l1,l2,l3;
    split_pair(v.x,h0,l0); split_pair(v.y,h1,l1);
    split_pair(v.z,h2,l2); split_pair(v.w,h3,l3);
    __nv_bfloat162 ph0{h0,h1}, ph1{h2,h3}, pl0{l0,l1}, pl1{l2,l3};
    ((__nv_bfloat162*)(g_w_hi + o))[0] = ph0;
    ((__nv_bfloat162*)(g_w_hi + o))[1] = ph1;
    ((__nv_bfloat162*)(g_w_lo + o))[0] = pl0;
    ((__nv_bfloat162*)(g_w_lo + o))[1] = pl1;
}

// ---------------- split-bf16 GEMM via mma.sync, 3-stage cp.async ----------------
#define PITCH 80
#define TILE_B (128*PITCH)
#define STAGE_B (4*TILE_B)          /* 40960 */
#define GEMM_SMEM (3*STAGE_B)       /* 122880 */
#define NSTG 32

template<int EP>
__global__ __launch_bounds__(256) void gemm_mma(const float* __restrict__ bias,
                                                float* __restrict__ outp)
{
    extern __shared__ char smem[];
    const uint32_t sb = smem_to_u32(smem);
    const int tid = threadIdx.x;
    const int lane = tid & 31, wid = tid >> 5;
    const int wm = wid & 1, wn = wid >> 1;
    const int m0 = blockIdx.y * 128;
    const int n0 = blockIdx.x * 128;

    const __nv_bfloat16* Xh = (EP == 3) ? g_a_hi : g_x_hi;
    const __nv_bfloat16* Xl = (EP == 3) ? g_a_lo : g_x_lo;
    const __nv_bfloat16* Wh = g_w_hi + (size_t)EP * D_MODEL * D_MODEL;
    const __nv_bfloat16* Wl = g_w_lo + (size_t)EP * D_MODEL * D_MODEL;

    float acc[4][4][4];
    #pragma unroll
    for (int i = 0; i < 4; i++)
        #pragma unroll
        for (int j = 0; j < 4; j++)
            #pragma unroll
            for (int l = 0; l < 4; l++) acc[i][j][l] = 0.f;

    const int r0l = tid >> 2, c0l = tid & 3;
    const int r1l = (tid + 256) >> 2;

    auto load_stage = [&](int buf, int k0) {
        uint32_t base = sb + buf * STAGE_B;
        #pragma unroll
        for (int t = 0; t < 4; t++) {
            const __nv_bfloat16* src = (t == 0) ? Xh : (t == 1) ? Xl : (t == 2) ? Wh : Wl;
            const int row0 = (t < 2) ? m0 : n0;
            CP_ASYNC16(base + t*TILE_B + r0l*PITCH + c0l*16,
                       src + (size_t)(row0 + r0l)*D_MODEL + k0 + c0l*8);
            CP_ASYNC16(base + t*TILE_B + r1l*PITCH + c0l*16,
                       src + (size_t)(row0 + r1l)*D_MODEL + k0 + c0l*8);
        }
        CP_COMMIT();
    };

    load_stage(0, 0);
    load_stage(1, 32);

    const uint32_t a_off = (uint32_t)((wm*64 + (lane & 15)) * PITCH + (lane >> 4) * 16);
    const uint32_t b_off = (uint32_t)((wn*32 + ((lane >> 4) << 3) + (lane & 7)) * PITCH
                                      + ((lane >> 3) & 1) * 16);

    for (int kc = 0; kc < NSTG; kc++) {
        if (kc + 2 < NSTG) load_stage((kc + 2) % 3, (kc + 2) * 32);
        if (kc < NSTG-2)      { CP_WAIT2(); }
        else if (kc == NSTG-2){ CP_WAIT1(); }
        else                  { CP_WAIT0(); }
        __syncthreads();

        const uint32_t base = sb + (kc % 3) * STAGE_B;
        #pragma unroll
        for (int ks = 0; ks < 2; ks++) {
            const uint32_t koff = ks * 32;
            uint32_t ah[4][4], al[4][4], bh[2][4], bl[2][4];
            #pragma unroll
            for (int mt = 0; mt < 4; mt++) {
                ldsm4(ah[mt], base + 0*TILE_B + a_off + mt*16*PITCH + koff);
                ldsm4(al[mt], base + 1*TILE_B + a_off + mt*16*PITCH + koff);
            }
            #pragma unroll
            for (int op = 0; op < 2; op++) {
                ldsm4(bh[op], base + 2*TILE_B + b_off + op*16*PITCH + koff);
                ldsm4(bl[op], base + 3*TILE_B + b_off + op*16*PITCH + koff);
            }
            #pragma unroll
            for (int mt = 0; mt < 4; mt++)
                #pragma unroll
                for (int nt = 0; nt < 4; nt++) {
                    const uint32_t* bhp = &bh[nt >> 1][(nt & 1) * 2];
                    const uint32_t* blp = &bl[nt >> 1][(nt & 1) * 2];
                    mma16816(acc[mt][nt], ah[mt], bhp);
                    mma16816(acc[mt][nt], al[mt], bhp);
                    mma16816(acc[mt][nt], ah[mt], blp);
                }
        }
        __syncthreads();
    }

    // ---- epilogue ----
    const int m_base = m0 + wm*64;
    #pragma unroll
    for (int mt = 0; mt < 4; mt++) {
        #pragma unroll
        for (int nt = 0; nt < 4; nt++) {
            const int n = n0 + wn*32 + nt*8 + (lane & 3)*2;
            const float b0v = bias[n], b1v = bias[n+1];
            #pragma unroll
            for (int half = 0; half < 2; half++) {
                const int m = m_base + mt*16 + (lane >> 2) + half*8;
                float y0 = acc[mt][nt][half*2+0] + b0v;
                float y1 = acc[mt][nt][half*2+1] + b1v;
                if (EP <= 1) { y0 = phi_fn(y0); y1 = phi_fn(y1); }
                if (EP <= 2) {
                    const int h = n >> 6, d = n & 63;
                    const int b = m >> 11, t = m & (TSEQ-1);
                    const size_t off = ((size_t)((b*N_HEADS + h)*TSEQ + t))*DK + d;
                    __nv_bfloat16 h0,h1,l0,l1;
                    split_pair(y0,h0,l0); split_pair(y1,h1,l1);
                    __nv_bfloat162 ph{h0,h1}, pl{l0,l1};
                    __nv_bfloat16* dh = (EP == 0) ? g_qh : (EP == 1) ? g_kh : g_vh;
                    __nv_bfloat16* dl = (EP == 0) ? g_ql : (EP == 1) ? g_kl : g_vl;
                    *(__nv_bfloat162*)(dh + off) = ph;
                    *(__nv_bfloat162*)(dl + off) = pl;
                } else {
                    *(float2*)(outp + (size_t)m*D_MODEL + n) = make_float2(y0, y1);
                }
            }
        }
    }
}

// ================= attention on tensor cores =================
#define APITCH 144                 /* 64 bf16 = 128B data + 16B pad; 16B-aligned, conflict-free */
#define ATILE (128*APITCH)         /* 18432 */
#define KVTILE (DK*APITCH)         /* 9216 (72 bf16 = 144B rows, exact) */

// ---------------- per-chunk K^T V and k-sum (MMA) ----------------
#define CKV_SMEM (4*ATILE)         /* Kh Kl Vh Vl = 73728 */
__global__ __launch_bounds__(128) void chunk_kv_mma()
{
    extern __shared__ char smem[];
    const uint32_t sb = smem_to_u32(smem);
    const uint32_t SKH = 0, SKL = ATILE, SVH = 2*ATILE, SVL = 3*ATILE;
    const int blk = blockIdx.x;
    const int bh = blk >> 4, c = blk & 15;
    const int tid = threadIdx.x;
    const int lane = tid & 31, wid = tid >> 5;
    const size_t gbase = (size_t)bh*TSEQ*DK + (size_t)c*CHUNK*DK;

    // load tiles: 128 rows x 8 float4 each
    #pragma unroll
    for (int it = 0; it < 8; it++) {
        int idx = tid + it*128;
        int r = idx >> 3, cc = idx & 7;
        const size_t so = gbase + (size_t)r*DK + cc*8;
        *(float4*)(smem + SKH + r*APITCH + cc*16) = *(const float4*)(g_kh + so);
        *(float4*)(smem + SKL + r*APITCH + cc*16) = *(const float4*)(g_kl + so);
        *(float4*)(smem + SVH + r*APITCH + cc*16) = *(const float4*)(g_vh + so);
        *(float4*)(smem + SVL + r*APITCH + cc*16) = *(const float4*)(g_vl + so);
    }
    __syncthreads();

    // warp w: output rows d1 in [16w, 16w+16)
    float f[8][4];
    #pragma unroll
    for (int n = 0; n < 8; n++)
        #pragma unroll
        for (int l = 0; l < 4; l++) f[n][l] = 0.f;

    // A = K^T (trans), B = V (trans)
    const uint32_t ka_rel = (uint32_t)(( ((lane>>4)&1)*8 + (lane&7) )*APITCH
                                       + (wid*16 + ((lane>>3)&1)*8)*2);
    const uint32_t vb_rel = (uint32_t)(( ((lane>>3)&1)*8 + (lane&7) )*APITCH
                                       + ((lane>>4)*8)*2);
    #pragma unroll
    for (int ks = 0; ks < 8; ks++) {
        const uint32_t krow = (uint32_t)(ks*16)*APITCH;
        uint32_t kah[4], kal[4], vbh[4][4], vbl[4][4];
        ldsm4t(kah, sb + SKH + krow + ka_rel);
        ldsm4t(kal, sb + SKL + krow + ka_rel);
        #pragma unroll
        for (int p = 0; p < 4; p++) {
            ldsm4t(vbh[p], sb + SVH + krow + vb_rel + (uint32_t)(p*16*2));
            ldsm4t(vbl[p], sb + SVL + krow + vb_rel + (uint32_t)(p*16*2));
        }
        #pragma unroll
        for (int nt = 0; nt < 8; nt++) {
            const uint32_t* bhp = &vbh[nt>>1][(nt&1)*2];
            const uint32_t* blp = &vbl[nt>>1][(nt&1)*2];
            mma16816(f[nt], kah, bhp);
            mma16816(f[nt], kal, bhp);
            mma16816(f[nt], kah, blp);
        }
    }

    // store KV fp32
    float* kvout = g_kv + (size_t)blk*DK*DK;
    const int d0 = wid*16 + (lane>>2);
    #pragma unroll
    for (int nt = 0; nt < 8; nt++) {
        const int e = nt*8 + (lane&3)*2;
        *(float2*)(kvout + (size_t)d0*DK + e)     = make_float2(f[nt][0], f[nt][1]);
        *(float2*)(kvout + (size_t)(d0+8)*DK + e) = make_float2(f[nt][2], f[nt][3]);
    }

    // ksum: threads 0-63 sum column d over 128 rows (hi+lo)
    if (tid < 64) {
        float s = 0.f;
        #pragma unroll 4
        for (int t = 0; t < 128; t++) {
            s += __bfloat162float(*(const __nv_bfloat16*)(smem + SKH + t*APITCH + tid*2));
            s += __bfloat162float(*(const __nv_bfloat16*)(smem + SKL + t*APITCH + tid*2));
        }
        g_ksum[(size_t)blk*DK + tid] = s;
    }
}

// ---------------- exclusive prefix scan -> bf16 hi/lo ext [d][72] ----------------
__global__ __launch_bounds__(256) void chunk_scan_kernel()
{
    const int bh = blockIdx.x;
    const int tid = threadIdx.x;
    for (int pos = tid; pos < DK*KVE; pos += 256) {
        const int d = pos / KVE, e = pos % KVE;
        float run = 0.f;
        #pragma unroll
        for (int c = 0; c < NCHUNK; c++) {
            const size_t blk = (size_t)(bh*NCHUNK + c);
            __nv_bfloat16 h, l;
            split_pair(run, h, l);
            g_kvh[blk*DK*KVE + pos] = h;
            g_kvl[blk*DK*KVE + pos] = l;
            float val = 0.f;
            if (e < DK)       val = g_kv[blk*DK*DK + (size_t)d*DK + e];
            else if (e == DK) val = g_ksum[blk*DK + d];
            run += val;
        }
    }
}

// ---------------- per-chunk attention (MMA, causal) ----------------
#define ATT_SMEM (6*ATILE + 2*KVTILE)   /* 129024 */
__global__ __launch_bounds__(256) void attn_mma_kernel()
{
    extern __shared__ char smem[];
    const uint32_t sb = smem_to_u32(smem);
    const uint32_t SQH = 0, SQL = ATILE, SKH = 2*ATILE, SKL = 3*ATILE;
    const uint32_t SVH = 4*ATILE, SVL = 5*ATILE;
    const uint32_t SGH = 6*ATILE, SGL = 6*ATILE + KVTILE;

    const int blk = blockIdx.x;
    const int bh = blk >> 4, c = blk & 15;
    const int tid = threadIdx.x;
    const int lane = tid & 31, wid = tid >> 5;
    const size_t gbase = (size_t)bh*TSEQ*DK + (size_t)c*CHUNK*DK;

    // load q/k/v tiles: 1024 float4 per tile, 256 threads -> 4 iters
    #pragma unroll
    for (int it = 0; it < 4; it++) {
        int idx = tid + it*256;
        int r = idx >> 3, cc = idx & 7;
        const size_t so = gbase + (size_t)r*DK + cc*8;
        const uint32_t doff = r*APITCH + cc*16;
        *(float4*)(smem + SQH + doff) = *(const float4*)(g_qh + so);
        *(float4*)(smem + SQL + doff) = *(const float4*)(g_ql + so);
        *(float4*)(smem + SKH + doff) = *(const float4*)(g_kh + so);
        *(float4*)(smem + SKL + doff) = *(const float4*)(g_kl + so);
        *(float4*)(smem + SVH + doff) = *(const float4*)(g_vh + so);
        *(float4*)(smem + SVL + doff) = *(const float4*)(g_vl + so);
    }
    // KV ext: 64 rows x 9 float4 = 576 per tile
    {
        const size_t kvbase = (size_t)blk*DK*KVE;
        for (int idx = tid; idx < 576; idx += 256) {
            int r = idx / 9, cc = idx % 9;
            *(float4*)(smem + SGH + r*APITCH + cc*16) = *(const float4*)(g_kvh + kvbase + (size_t)r*KVE + cc*8);
            *(float4*)(smem + SGL + r*APITCH + cc*16) = *(const float4*)(g_kvl + kvbase + (size_t)r*KVE + cc*8);
        }
    }
    __syncthreads();

    const int rbase = wid * 16;          // 8 warps x 16 rows
    // persistent q A-frags (non-trans)
    const uint32_t qa_rel = (uint32_t)((rbase + (lane & 15))*APITCH + (lane >> 4)*16);
    uint32_t qh[4][4], ql[4][4];
    #pragma unroll
    for (int ks = 0; ks < 4; ks++) {
        ldsm4(qh[ks], sb + SQH + qa_rel + ks*32);
        ldsm4(ql[ks], sb + SQL + qa_rel + ks*32);
    }

    float o[9][4];
    #pragma unroll
    for (int n = 0; n < 9; n++)
        #pragma unroll
        for (int l = 0; l < 4; l++) o[n][l] = 0.f;

    // ---- inter-chunk: o += q @ KV_prev (B = KV ext, trans) ----
    const uint32_t gb_rel = (uint32_t)(( ((lane>>3)&1)*8 + (lane&7) )*APITCH + ((lane>>4)*8)*2);
    #pragma unroll
    for (int ks = 0; ks < 4; ks++) {
        const uint32_t krow = (uint32_t)(ks*16)*APITCH;
        uint32_t gbh[4][4], gbl[4][4], g2h[2], g2l[2];
        #pragma unroll
        for (int p = 0; p < 4; p++) {
            ldsm4t(gbh[p], sb + SGH + krow + gb_rel + (uint32_t)(p*16*2));
            ldsm4t(gbl[p], sb + SGL + krow + gb_rel + (uint32_t)(p*16*2));
        }
        // ntile 8 (cols 64-71) via x2
        const uint32_t g2_rel = (uint32_t)(( ((lane>>3)&1)*8 + (lane&7) )*APITCH + 64*2);
        ldsm2t(g2h, sb + SGH + krow + g2_rel);
        ldsm2t(g2l, sb + SGL + krow + g2_rel);
        #pragma unroll
        for (int nt = 0; nt < 8; nt++) {
            const uint32_t* bhp = &gbh[nt>>1][(nt&1)*2];
            const uint32_t* blp = &gbl[nt>>1][(nt&1)*2];
            mma16816(o[nt], qh[ks], bhp);
            mma16816(o[nt], ql[ks], bhp);
            mma16816(o[nt], qh[ks], blp);
        }
        mma16816(o[8], qh[ks], g2h);
        mma16816(o[8], ql[ks], g2h);
        mma16816(o[8], qh[ks], g2l);
    }

    // ---- intra-chunk causal ----
    float zacc0 = 0.f, zacc1 = 0.f;
    const int row0 = rbase + (lane >> 2), row1 = row0 + 8;
    const int ncc = wid/2 + 1;            // chunks of 32 cols, causal-trimmed
    const uint32_t kb_col = (uint32_t)(((lane>>3)&1)*16);
    const uint32_t vb_rel = (uint32_t)(( ((lane>>3)&1)*8 + (lane&7) )*APITCH + ((lane>>4)*8)*2);

    for (int cc = 0; cc < ncc; cc++) {
        const int c0 = cc*32;
        // S = q k^T over this 32-col strip
        float s[4][4];
        #pragma unroll
        for (int n = 0; n < 4; n++)
            #pragma unroll
            for (int l = 0; l < 4; l++) s[n][l] = 0.f;
        #pragma unroll
        for (int ks = 0; ks < 4; ks++) {
            uint32_t kbh[2][4], kbl[2][4];
            #pragma unroll
            for (int p = 0; p < 2; p++) {
                const uint32_t kb = (uint32_t)((c0 + 16*p + ((lane>>4)<<3) + (lane&7))*APITCH)
                                    + kb_col + (uint32_t)(ks*32);
                ldsm4(kbh[p], sb + SKH + kb);
                ldsm4(kbl[p], sb + SKL + kb);
            }
            #pragma unroll
            for (int nt = 0; nt < 4; nt++) {
                const uint32_t* bhp = &kbh[nt>>1][(nt&1)*2];
                const uint32_t* blp = &kbl[nt>>1][(nt&1)*2];
                mma16816(s[nt], qh[ks], bhp);
                mma16816(s[nt], ql[ks], bhp);
                mma16816(s[nt], qh[ks], blp);
            }
        }
        // mask, z, convert to A-frags (S hi/lo)
        uint32_t ah[2][4], al[2][4];
        #pragma unroll
        for (int nt = 0; nt < 4; nt++) {
            const int colj = c0 + nt*8 + (lane&3)*2;
            float e0 = (colj   <= row0) ? s[nt][0] : 0.f;
            float e1 = (colj+1 <= row0) ? s[nt][1] : 0.f;
            float e2 = (colj   <= row1) ? s[nt][2] : 0.f;
            float e3 = (colj+1 <= row1) ? s[nt][3] : 0.f;
            zacc0 += e0 + e1;
            zacc1 += e2 + e3;
            float h0 = __bfloat162float(__float2bfloat16(e0));
            float h1 = __bfloat162float(__float2bfloat16(e1));
            float h2 = __bfloat162float(__float2bfloat16(e2));
            float h3 = __bfloat162float(__float2bfloat16(e3));
            const int kk = nt >> 1, half = nt & 1;
            ah[kk][half*2+0] = pack_bf16(h0, h1);
            ah[kk][half*2+1] = pack_bf16(h2, h3);
            al[kk][half*2+0] = pack_bf16(e0-h0, e1-h1);
            al[kk][half*2+1] = pack_bf16(e2-h2, e3-h3);
        }
        // o += S @ V over this strip
        #pragma unroll
        for (int kk = 0; kk < 2; kk++) {
            const uint32_t krow = (uint32_t)((c0 + kk*16))*APITCH;
            uint32_t vbh[4][4], vbl[4][4];
            #pragma unroll
            for (int p = 0; p < 4; p++) {
                ldsm4t(vbh[p], sb + SVH + krow + vb_rel + (uint32_t)(p*16*2));
                ldsm4t(vbl[p], sb + SVL + krow + vb_rel + (uint32_t)(p*16*2));
            }
            #pragma unroll
            for (int nt = 0; nt < 8; nt++) {
                const uint32_t* bhp = &vbh[nt>>1][(nt&1)*2];
                const uint32_t* blp = &vbl[nt>>1][(nt&1)*2];
                mma16816(o[nt], ah[kk], bhp);
                mma16816(o[nt], al[kk], bhp);
                mma16816(o[nt], ah[kk], blp);
            }
        }
    }

    // ---- z: intra (quad reduce) + inter (col 64 of o[8]) ----
    float z0 = zacc0 + ((lane & 3) == 0 ? o[8][0] : 0.f);
    float z1 = zacc1 + ((lane & 3) == 0 ? o[8][2] : 0.f);
    z0 += __shfl_xor_sync(0xffffffff, z0, 1);
    z0 += __shfl_xor_sync(0xffffffff, z0, 2);
    z1 += __shfl_xor_sync(0xffffffff, z1, 1);
    z1 += __shfl_xor_sync(0xffffffff, z1, 2);
    const float inv0 = 1.f / (z0 + 1e-6f);
    const float inv1 = 1.f / (z1 + 1e-6f);

    // ---- write g_a hi/lo ----
    const int b = bh >> 4, h = bh & 15;
    const size_t mbase0 = ((size_t)(b*TSEQ + c*CHUNK + row0))*D_MODEL + h*DK;
    const size_t mbase1 = ((size_t)(b*TSEQ + c*CHUNK + row1))*D_MODEL + h*DK;
    #pragma unroll
    for (int nt = 0; nt < 8; nt++) {
        const int e = nt*8 + (lane&3)*2;
        float y0 = o[nt][0]*inv0, y1 = o[nt][1]*inv0;
        float y2 = o[nt][2]*inv1, y3 = o[nt][3]*inv1;
        __nv_bfloat16 h0,h1,h2,h3,l0,l1,l2,l3;
        split_pair(y0,h0,l0); split_pair(y1,h1,l1);
        split_pair(y2,h2,l2); split_pair(y3,h3,l3);
        __nv_bfloat162 p0{h0,h1}, q0{l0,l1}, p1{h2,h3}, q1{l2,l3};
        *(__nv_bfloat162*)(g_a_hi + mbase0 + e) = p0;
        *(__nv_bfloat162*)(g_a_lo + mbase0 + e) = q0;
        *(__nv_bfloat162*)(g_a_hi + mbase1 + e) = p1;
        *(__nv_bfloat162*)(g_a_lo + mbase1 + e) = q1;
    }
}

// ---------------- launch ----------------
extern "C" void kernel_launch(void* const* d_in, const int* in_sizes, int n_in,
                              void* d_out, int out_size)
{
    (void)in_sizes; (void)n_in; (void)out_size;
    const float* x  = (const float*)d_in[0];
    const float* Wq = (const float*)d_in[1];
    const float* bq = (const float*)d_in[2];
    const float* Wk = (const float*)d_in[3];
    const float* bk = (const float*)d_in[4];
    const float* Wv = (const float*)d_in[5];
    const float* bv = (const float*)d_in[6];
    const float* Wo = (const float*)d_in[7];
    const float* bo = (const float*)d_in[8];
    float* out = (float*)d_out;

    cudaFuncSetAttribute(gemm_mma<0>, cudaFuncAttributeMaxDynamicSharedMemorySize, GEMM_SMEM);
    cudaFuncSetAttribute(gemm_mma<1>, cudaFuncAttributeMaxDynamicSharedMemorySize, GEMM_SMEM);
    cudaFuncSetAttribute(gemm_mma<2>, cudaFuncAttributeMaxDynamicSharedMemorySize, GEMM_SMEM);
    cudaFuncSetAttribute(gemm_mma<3>, cudaFuncAttributeMaxDynamicSharedMemorySize, GEMM_SMEM);
    cudaFuncSetAttribute(chunk_kv_mma,   cudaFuncAttributeMaxDynamicSharedMemorySize, CKV_SMEM);
    cudaFuncSetAttribute(attn_mma_kernel,cudaFuncAttributeMaxDynamicSharedMemorySize, ATT_SMEM);

    split_x_kernel<<<(MROWS*D_MODEL/4 + 255)/256, 256>>>(x, MROWS*D_MODEL/4);
    split_w_kernel<<<(4*D_MODEL*D_MODEL/4 + 255)/256, 256>>>(Wq, Wk, Wv, Wo);

    dim3 ggrid(D_MODEL/128, MROWS/128);   // (8, 32)
    gemm_mma<0><<<ggrid, 256, GEMM_SMEM>>>(bq, nullptr);
    gemm_mma<1><<<ggrid, 256, GEMM_SMEM>>>(bk, nullptr);
    gemm_mma<2><<<ggrid, 256, GEMM_SMEM>>>(bv, nullptr);

    chunk_kv_mma<<<NBH*NCHUNK, 128, CKV_SMEM>>>();
    chunk_scan_kernel<<<NBH, 256>>>();
    attn_mma_kernel<<<NBH*NCHUNK, 256, ATT_SMEM>>>();

    gemm_mma<3><<<ggrid, 256, GEMM_SMEM>>>(bo, out);
}

// round 5
// speedup vs baseline: 2.4410x; 1.1014x over previous
#include <cuda_runtime.h>
#include <cuda_bf16.h>
#include <cstdint>

#define D_MODEL 1024
#define N_HEADS 16
#define DK 64
#define BATCH 2
#define TSEQ 2048
#define MROWS (BATCH*TSEQ)   /* 4096 */
#define CHUNK 128
#define NCHUNK (TSEQ/CHUNK)  /* 16 */
#define NBH (BATCH*N_HEADS)  /* 32 */
#define KVE 72               /* KV ext cols: 64 + ksum + pad */

// ---------------- scratch (static device arrays; no allocation) ----------------
__device__ float g_kv[NBH*NCHUNK*DK*DK];     // per-chunk K^T V (fp32)
__device__ float g_ksum[NBH*NCHUNK*DK];      // per-chunk k column sums
// bf16 hi/lo operands
__device__ __nv_bfloat16 g_x_hi[MROWS*D_MODEL];
__device__ __nv_bfloat16 g_x_lo[MROWS*D_MODEL];
__device__ __nv_bfloat16 g_w_hi[4*D_MODEL*D_MODEL];
__device__ __nv_bfloat16 g_w_lo[4*D_MODEL*D_MODEL];
__device__ __nv_bfloat16 g_a_hi[MROWS*D_MODEL];
__device__ __nv_bfloat16 g_a_lo[MROWS*D_MODEL];
__device__ __nv_bfloat16 g_qh[NBH*TSEQ*DK], g_ql[NBH*TSEQ*DK];
__device__ __nv_bfloat16 g_kh[NBH*TSEQ*DK], g_kl[NBH*TSEQ*DK];
__device__ __nv_bfloat16 g_vh[NBH*TSEQ*DK], g_vl[NBH*TSEQ*DK];
__device__ __nv_bfloat16 g_kvh[NBH*NCHUNK*DK*KVE];  // exclusive-prefix KV ext, [d][e]
__device__ __nv_bfloat16 g_kvl[NBH*NCHUNK*DK*KVE];

__device__ __forceinline__ float phi_fn(float x) {
    return x > 0.f ? x + 1.f : __expf(x);
}
__device__ __forceinline__ uint32_t smem_to_u32(const void* smem_ptr) {
    uint32_t addr;
    asm("{ .reg .u64 tmp; cvta.to.shared.u64 tmp, %1; cvt.u32.u64 %0, tmp; }"
        : "=r"(addr) : "l"(smem_ptr));
    return addr;
}

// ---------------- mma / ldmatrix / cp.async primitives ----------------
__device__ __forceinline__ void mma16816(float* d, const uint32_t* a, const uint32_t* b) {
    asm volatile(
        "mma.sync.aligned.m16n8k16.row.col.f32.bf16.bf16.f32 "
        "{%0,%1,%2,%3}, {%4,%5,%6,%7}, {%8,%9}, {%0,%1,%2,%3};"
        : "+f"(d[0]), "+f"(d[1]), "+f"(d[2]), "+f"(d[3])
        : "r"(a[0]), "r"(a[1]), "r"(a[2]), "r"(a[3]), "r"(b[0]), "r"(b[1]));
}
__device__ __forceinline__ void ldsm4(uint32_t* r, uint32_t addr) {
    asm volatile("ldmatrix.sync.aligned.m8n8.x4.shared.b16 {%0,%1,%2,%3}, [%4];"
        : "=r"(r[0]), "=r"(r[1]), "=r"(r[2]), "=r"(r[3]) : "r"(addr));
}
__device__ __forceinline__ void ldsm4t(uint32_t* r, uint32_t addr) {
    asm volatile("ldmatrix.sync.aligned.m8n8.x4.trans.shared.b16 {%0,%1,%2,%3}, [%4];"
        : "=r"(r[0]), "=r"(r[1]), "=r"(r[2]), "=r"(r[3]) : "r"(addr));
}
__device__ __forceinline__ void ldsm2t(uint32_t* r, uint32_t addr) {
    asm volatile("ldmatrix.sync.aligned.m8n8.x2.trans.shared.b16 {%0,%1}, [%2];"
        : "=r"(r[0]), "=r"(r[1]) : "r"(addr));
}
#define CP_ASYNC16(dst, src) \
    asm volatile("cp.async.cg.shared.global [%0], [%1], 16;" :: "r"(dst), "l"(src))
#define CP_COMMIT() asm volatile("cp.async.commit_group;" ::: "memory")
#define CP_WAIT1()  asm volatile("cp.async.wait_group 1;" ::: "memory")
#define CP_WAIT0()  asm volatile("cp.async.wait_group 0;" ::: "memory")

__device__ __forceinline__ uint32_t pack_bf16(float lo, float hi) {
    __nv_bfloat162 p = __floats2bfloat162_rn(lo, hi);   // .x = lo half
    return *reinterpret_cast<uint32_t*>(&p);
}
__device__ __forceinline__ void split_pair(float y, __nv_bfloat16& h, __nv_bfloat16& l) {
    h = __float2bfloat16(y);
    l = __float2bfloat16(y - __bfloat162float(h));
}

// ---------------- fp32 -> bf16 hi/lo splits ----------------
__global__ __launch_bounds__(256) void split_x_kernel(const float* __restrict__ src, int n4)
{
    int i = blockIdx.x * 256 + threadIdx.x;
    if (i >= n4) return;
    float4 v = ((const float4*)src)[i];
    __nv_bfloat16 h0,h1,h2,h3,l0,l1,l2,l3;
    split_pair(v.x,h0,l0); split_pair(v.y,h1,l1);
    split_pair(v.z,h2,l2); split_pair(v.w,h3,l3);
    __nv_bfloat162 ph0{h0,h1}, ph1{h2,h3}, pl0{l0,l1}, pl1{l2,l3};
    ((__nv_bfloat162*)(g_x_hi + 4*(size_t)i))[0] = ph0;
    ((__nv_bfloat162*)(g_x_hi + 4*(size_t)i))[1] = ph1;
    ((__nv_bfloat162*)(g_x_lo + 4*(size_t)i))[0] = pl0;
    ((__nv_bfloat162*)(g_x_lo + 4*(size_t)i))[1] = pl1;
}
__global__ __launch_bounds__(256) void split_w_kernel(
    const float* __restrict__ w0, const float* __restrict__ w1,
    const float* __restrict__ w2, const float* __restrict__ w3)
{
    const int per = D_MODEL*D_MODEL/4;   // 262144 float4 per W
    int i = blockIdx.x * 256 + threadIdx.x;
    int sel = i >> 18, loc = i & (per - 1);
    const float* src = (sel == 0) ? w0 : (sel == 1) ? w1 : (sel == 2) ? w2 : w3;
    float4 v = ((const float4*)src)[loc];
    size_t o = (size_t)sel * D_MODEL * D_MODEL + 4*(size_t)loc;
    __nv_bfloat16 h0,h1,h2,h3,l0,l1,l2,l3;
    split_pair(v.x,h0,l0); split_pair(v.y,h1,l1);
    split_pair(v.z,h2,l2); split_pair(v.w,h3,l3);
    __nv_bfloat162 ph0{h0,h1}, ph1{h2,h3}, pl0{l0,l1}, pl1{l2,l3};
    ((__nv_bfloat162*)(g_w_hi + o))[0] = ph0;
    ((__nv_bfloat162*)(g_w_hi + o))[1] = ph1;
    ((__nv_bfloat162*)(g_w_lo + o))[0] = pl0;
    ((__nv_bfloat162*)(g_w_lo + o))[1] = pl1;
}

// ---------------- split-bf16 GEMM via mma.sync, 2-stage, 2 CTAs/SM ----------------
#define PITCH 80
#define TILE_B (128*PITCH)
#define STAGE_B (4*TILE_B)          /* 40960 */
#define GEMM_SMEM (2*STAGE_B)       /* 81920 -> 2 CTAs/SM */
#define NSTG 32

template<int EP>
__global__ __launch_bounds__(256, 2) void gemm_mma(const float* __restrict__ bias,
                                                   float* __restrict__ outp)
{
    extern __shared__ char smem[];
    const uint32_t sb = smem_to_u32(smem);
    const int tid = threadIdx.x;
    const int lane = tid & 31, wid = tid >> 5;
    const int wm = wid & 1, wn = wid >> 1;
    const int m0 = blockIdx.y * 128;
    const int n0 = blockIdx.x * 128;

    const __nv_bfloat16* Xh = (EP == 3) ? g_a_hi : g_x_hi;
    const __nv_bfloat16* Xl = (EP == 3) ? g_a_lo : g_x_lo;
    const __nv_bfloat16* Wh = g_w_hi + (size_t)EP * D_MODEL * D_MODEL;
    const __nv_bfloat16* Wl = g_w_lo + (size_t)EP * D_MODEL * D_MODEL;

    float acc[4][4][4];
    #pragma unroll
    for (int i = 0; i < 4; i++)
        #pragma unroll
        for (int j = 0; j < 4; j++)
            #pragma unroll
            for (int l = 0; l < 4; l++) acc[i][j][l] = 0.f;

    const int r0l = tid >> 2, c0l = tid & 3;
    const int r1l = (tid + 256) >> 2;

    auto load_stage = [&](int buf, int k0) {
        uint32_t base = sb + buf * STAGE_B;
        #pragma unroll
        for (int t = 0; t < 4; t++) {
            const __nv_bfloat16* src = (t == 0) ? Xh : (t == 1) ? Xl : (t == 2) ? Wh : Wl;
            const int row0 = (t < 2) ? m0 : n0;
            CP_ASYNC16(base + t*TILE_B + r0l*PITCH + c0l*16,
                       src + (size_t)(row0 + r0l)*D_MODEL + k0 + c0l*8);
            CP_ASYNC16(base + t*TILE_B + r1l*PITCH + c0l*16,
                       src + (size_t)(row0 + r1l)*D_MODEL + k0 + c0l*8);
        }
        CP_COMMIT();
    };

    load_stage(0, 0);

    const uint32_t a_off = (uint32_t)((wm*64 + (lane & 15)) * PITCH + (lane >> 4) * 16);
    const uint32_t b_off = (uint32_t)((wn*32 + ((lane >> 4) << 3) + (lane & 7)) * PITCH
                                      + ((lane >> 3) & 1) * 16);

    for (int kc = 0; kc < NSTG; kc++) {
        if (kc < NSTG-1) { load_stage((kc+1) & 1, (kc+1)*32); CP_WAIT1(); }
        else             { CP_WAIT0(); }
        __syncthreads();

        const uint32_t base = sb + (kc & 1) * STAGE_B;
        #pragma unroll
        for (int ks = 0; ks < 2; ks++) {
            const uint32_t koff = ks * 32;
            uint32_t ah[4][4], al[4][4], bh[2][4], bl[2][4];
            #pragma unroll
            for (int mt = 0; mt < 4; mt++) {
                ldsm4(ah[mt], base + 0*TILE_B + a_off + mt*16*PITCH + koff);
                ldsm4(al[mt], base + 1*TILE_B + a_off + mt*16*PITCH + koff);
            }
            #pragma unroll
            for (int op = 0; op < 2; op++) {
                ldsm4(bh[op], base + 2*TILE_B + b_off + op*16*PITCH + koff);
                ldsm4(bl[op], base + 3*TILE_B + b_off + op*16*PITCH + koff);
            }
            #pragma unroll
            for (int mt = 0; mt < 4; mt++)
                #pragma unroll
                for (int nt = 0; nt < 4; nt++) {
                    const uint32_t* bhp = &bh[nt >> 1][(nt & 1) * 2];
                    const uint32_t* blp = &bl[nt >> 1][(nt & 1) * 2];
                    mma16816(acc[mt][nt], ah[mt], bhp);
                    mma16816(acc[mt][nt], al[mt], bhp);
                    mma16816(acc[mt][nt], ah[mt], blp);
                }
        }
        __syncthreads();
    }

    // ---- epilogue ----
    const int m_base = m0 + wm*64;
    #pragma unroll
    for (int mt = 0; mt < 4; mt++) {
        #pragma unroll
        for (int nt = 0; nt < 4; nt++) {
            const int n = n0 + wn*32 + nt*8 + (lane & 3)*2;
            const float b0v = bias[n], b1v = bias[n+1];
            #pragma unroll
            for (int half = 0; half < 2; half++) {
                const int m = m_base + mt*16 + (lane >> 2) + half*8;
                float y0 = acc[mt][nt][half*2+0] + b0v;
                float y1 = acc[mt][nt][half*2+1] + b1v;
                if (EP <= 1) { y0 = phi_fn(y0); y1 = phi_fn(y1); }
                if (EP <= 2) {
                    const int h = n >> 6, d = n & 63;
                    const int b = m >> 11, t = m & (TSEQ-1);
                    const size_t off = ((size_t)((b*N_HEADS + h)*TSEQ + t))*DK + d;
                    __nv_bfloat16 h0,h1,l0,l1;
                    split_pair(y0,h0,l0); split_pair(y1,h1,l1);
                    __nv_bfloat162 ph{h0,h1}, pl{l0,l1};
                    __nv_bfloat16* dh = (EP == 0) ? g_qh : (EP == 1) ? g_kh : g_vh;
                    __nv_bfloat16* dl = (EP == 0) ? g_ql : (EP == 1) ? g_kl : g_vl;
                    *(__nv_bfloat162*)(dh + off) = ph;
                    *(__nv_bfloat162*)(dl + off) = pl;
                } else {
                    *(float2*)(outp + (size_t)m*D_MODEL + n) = make_float2(y0, y1);
                }
            }
        }
    }
}

// ================= attention on tensor cores =================
#define APITCH 144                 /* 64 bf16 = 128B data + 16B pad */
#define ATILE (128*APITCH)         /* 18432 */
#define KVTILE (DK*APITCH)         /* 9216 */

// ---------------- per-chunk K^T V and k-sum (MMA) ----------------
#define CKV_SMEM (4*ATILE)         /* 73728 */
__global__ __launch_bounds__(128) void chunk_kv_mma()
{
    extern __shared__ char smem[];
    const uint32_t sb = smem_to_u32(smem);
    const uint32_t SKH = 0, SKL = ATILE, SVH = 2*ATILE, SVL = 3*ATILE;
    const int blk = blockIdx.x;
    const int bh = blk >> 4, c = blk & 15;
    const int tid = threadIdx.x;
    const int lane = tid & 31, wid = tid >> 5;
    const size_t gbase = (size_t)bh*TSEQ*DK + (size_t)c*CHUNK*DK;

    #pragma unroll
    for (int it = 0; it < 8; it++) {
        int idx = tid + it*128;
        int r = idx >> 3, cc = idx & 7;
        const size_t so = gbase + (size_t)r*DK + cc*8;
        *(float4*)(smem + SKH + r*APITCH + cc*16) = *(const float4*)(g_kh + so);
        *(float4*)(smem + SKL + r*APITCH + cc*16) = *(const float4*)(g_kl + so);
        *(float4*)(smem + SVH + r*APITCH + cc*16) = *(const float4*)(g_vh + so);
        *(float4*)(smem + SVL + r*APITCH + cc*16) = *(const float4*)(g_vl + so);
    }
    __syncthreads();

    float f[8][4];
    #pragma unroll
    for (int n = 0; n < 8; n++)
        #pragma unroll
        for (int l = 0; l < 4; l++) f[n][l] = 0.f;

    const uint32_t ka_rel = (uint32_t)(( ((lane>>4)&1)*8 + (lane&7) )*APITCH
                                       + (wid*16 + ((lane>>3)&1)*8)*2);
    const uint32_t vb_rel = (uint32_t)(( ((lane>>3)&1)*8 + (lane&7) )*APITCH
                                       + ((lane>>4)*8)*2);
    #pragma unroll
    for (int ks = 0; ks < 8; ks++) {
        const uint32_t krow = (uint32_t)(ks*16)*APITCH;
        uint32_t kah[4], kal[4], vbh[4][4], vbl[4][4];
        ldsm4t(kah, sb + SKH + krow + ka_rel);
        ldsm4t(kal, sb + SKL + krow + ka_rel);
        #pragma unroll
        for (int p = 0; p < 4; p++) {
            ldsm4t(vbh[p], sb + SVH + krow + vb_rel + (uint32_t)(p*16*2));
            ldsm4t(vbl[p], sb + SVL + krow + vb_rel + (uint32_t)(p*16*2));
        }
        #pragma unroll
        for (int nt = 0; nt < 8; nt++) {
            const uint32_t* bhp = &vbh[nt>>1][(nt&1)*2];
            const uint32_t* blp = &vbl[nt>>1][(nt&1)*2];
            mma16816(f[nt], kah, bhp);
            mma16816(f[nt], kal, bhp);
            mma16816(f[nt], kah, blp);
        }
    }

    float* kvout = g_kv + (size_t)blk*DK*DK;
    const int d0 = wid*16 + (lane>>2);
    #pragma unroll
    for (int nt = 0; nt < 8; nt++) {
        const int e = nt*8 + (lane&3)*2;
        *(float2*)(kvout + (size_t)d0*DK + e)     = make_float2(f[nt][0], f[nt][1]);
        *(float2*)(kvout + (size_t)(d0+8)*DK + e) = make_float2(f[nt][2], f[nt][3]);
    }

    if (tid < 64) {
        float s = 0.f;
        #pragma unroll 4
        for (int t = 0; t < 128; t++) {
            s += __bfloat162float(*(const __nv_bfloat16*)(smem + SKH + t*APITCH + tid*2));
            s += __bfloat162float(*(const __nv_bfloat16*)(smem + SKL + t*APITCH + tid*2));
        }
        g_ksum[(size_t)blk*DK + tid] = s;
    }
}

// ---------------- exclusive prefix scan -> bf16 hi/lo ext [d][72] ----------------
__global__ __launch_bounds__(256) void chunk_scan_kernel()
{
    const int bh = blockIdx.x;
    const int tid = threadIdx.x;
    for (int pos = tid; pos < DK*KVE; pos += 256) {
        const int d = pos / KVE, e = pos % KVE;
        float run = 0.f;
        #pragma unroll
        for (int c = 0; c < NCHUNK; c++) {
            const size_t blk = (size_t)(bh*NCHUNK + c);
            __nv_bfloat16 h, l;
            split_pair(run, h, l);
            g_kvh[blk*DK*KVE + pos] = h;
            g_kvl[blk*DK*KVE + pos] = l;
            float val = 0.f;
            if (e < DK)       val = g_kv[blk*DK*DK + (size_t)d*DK + e];
            else if (e == DK) val = g_ksum[blk*DK + d];
            run += val;
        }
    }
}

// ---------------- per-chunk attention (MMA, causal) ----------------
#define ATT_SMEM (6*ATILE + 2*KVTILE)   /* 129024 */
__global__ __launch_bounds__(256) void attn_mma_kernel()
{
    extern __shared__ char smem[];
    const uint32_t sb = smem_to_u32(smem);
    const uint32_t SQH = 0, SQL = ATILE, SKH = 2*ATILE, SKL = 3*ATILE;
    const uint32_t SVH = 4*ATILE, SVL = 5*ATILE;
    const uint32_t SGH = 6*ATILE, SGL = 6*ATILE + KVTILE;

    const int blk = blockIdx.x;
    const int bh = blk >> 4, c = blk & 15;
    const int tid = threadIdx.x;
    const int lane = tid & 31, wid = tid >> 5;
    const size_t gbase = (size_t)bh*TSEQ*DK + (size_t)c*CHUNK*DK;

    #pragma unroll
    for (int it = 0; it < 4; it++) {
        int idx = tid + it*256;
        int r = idx >> 3, cc = idx & 7;
        const size_t so = gbase + (size_t)r*DK + cc*8;
        const uint32_t doff = r*APITCH + cc*16;
        *(float4*)(smem + SQH + doff) = *(const float4*)(g_qh + so);
        *(float4*)(smem + SQL + doff) = *(const float4*)(g_ql + so);
        *(float4*)(smem + SKH + doff) = *(const float4*)(g_kh + so);
        *(float4*)(smem + SKL + doff) = *(const float4*)(g_kl + so);
        *(float4*)(smem + SVH + doff) = *(const float4*)(g_vh + so);
        *(float4*)(smem + SVL + doff) = *(const float4*)(g_vl + so);
    }
    {
        const size_t kvbase = (size_t)blk*DK*KVE;
        for (int idx = tid; idx < 576; idx += 256) {
            int r = idx / 9, cc = idx % 9;
            *(float4*)(smem + SGH + r*APITCH + cc*16) = *(const float4*)(g_kvh + kvbase + (size_t)r*KVE + cc*8);
            *(float4*)(smem + SGL + r*APITCH + cc*16) = *(const float4*)(g_kvl + kvbase + (size_t)r*KVE + cc*8);
        }
    }
    __syncthreads();

    const int rbase = wid * 16;
    const uint32_t qa_rel = (uint32_t)((rbase + (lane & 15))*APITCH + (lane >> 4)*16);
    uint32_t qh[4][4], ql[4][4];
    #pragma unroll
    for (int ks = 0; ks < 4; ks++) {
        ldsm4(qh[ks], sb + SQH + qa_rel + ks*32);
        ldsm4(ql[ks], sb + SQL + qa_rel + ks*32);
    }

    float o[9][4];
    #pragma unroll
    for (int n = 0; n < 9; n++)
        #pragma unroll
        for (int l = 0; l < 4; l++) o[n][l] = 0.f;

    const uint32_t gb_rel = (uint32_t)(( ((lane>>3)&1)*8 + (lane&7) )*APITCH + ((lane>>4)*8)*2);
    #pragma unroll
    for (int ks = 0; ks < 4; ks++) {
        const uint32_t krow = (uint32_t)(ks*16)*APITCH;
        uint32_t gbh[4][4], gbl[4][4], g2h[2], g2l[2];
        #pragma unroll
        for (int p = 0; p < 4; p++) {
            ldsm4t(gbh[p], sb + SGH + krow + gb_rel + (uint32_t)(p*16*2));
            ldsm4t(gbl[p], sb + SGL + krow + gb_rel + (uint32_t)(p*16*2));
        }
        const uint32_t g2_rel = (uint32_t)(( ((lane>>3)&1)*8 + (lane&7) )*APITCH + 64*2);
        ldsm2t(g2h, sb + SGH + krow + g2_rel);
        ldsm2t(g2l, sb + SGL + krow + g2_rel);
        #pragma unroll
        for (int nt = 0; nt < 8; nt++) {
            const uint32_t* bhp = &gbh[nt>>1][(nt&1)*2];
            const uint32_t* blp = &gbl[nt>>1][(nt&1)*2];
            mma16816(o[nt], qh[ks], bhp);
            mma16816(o[nt], ql[ks], bhp);
            mma16816(o[nt], qh[ks], blp);
        }
        mma16816(o[8], qh[ks], g2h);
        mma16816(o[8], ql[ks], g2h);
        mma16816(o[8], qh[ks], g2l);
    }

    float zacc0 = 0.f, zacc1 = 0.f;
    const int row0 = rbase + (lane >> 2), row1 = row0 + 8;
    const int ncc = wid/2 + 1;
    const uint32_t kb_col = (uint32_t)(((lane>>3)&1)*16);
    const uint32_t vb_rel = (uint32_t)(( ((lane>>3)&1)*8 + (lane&7) )*APITCH + ((lane>>4)*8)*2);

    for (int cc = 0; cc < ncc; cc++) {
        const int c0 = cc*32;
        float s[4][4];
        #pragma unroll
        for (int n = 0; n < 4; n++)
            #pragma unroll
            for (int l = 0; l < 4; l++) s[n][l] = 0.f;
        #pragma unroll
        for (int ks = 0; ks < 4; ks++) {
            uint32_t kbh[2][4], kbl[2][4];
            #pragma unroll
            for (int p = 0; p < 2; p++) {
                const uint32_t kb = (uint32_t)((c0 + 16*p + ((lane>>4)<<3) + (lane&7))*APITCH)
                                    + kb_col + (uint32_t)(ks*32);
                ldsm4(kbh[p], sb + SKH + kb);
                ldsm4(kbl[p], sb + SKL + kb);
            }
            #pragma unroll
            for (int nt = 0; nt < 4; nt++) {
                const uint32_t* bhp = &kbh[nt>>1][(nt&1)*2];
                const uint32_t* blp = &kbl[nt>>1][(nt&1)*2];
                mma16816(s[nt], qh[ks], bhp);
                mma16816(s[nt], ql[ks], bhp);
                mma16816(s[nt], qh[ks], blp);
            }
        }
        uint32_t ah[2][4], al[2][4];
        #pragma unroll
        for (int nt = 0; nt < 4; nt++) {
            const int colj = c0 + nt*8 + (lane&3)*2;
            float e0 = (colj   <= row0) ? s[nt][0] : 0.f;
            float e1 = (colj+1 <= row0) ? s[nt][1] : 0.f;
            float e2 = (colj   <= row1) ? s[nt][2] : 0.f;
            float e3 = (colj+1 <= row1) ? s[nt][3] : 0.f;
            zacc0 += e0 + e1;
            zacc1 += e2 + e3;
            float h0 = __bfloat162float(__float2bfloat16(e0));
            float h1 = __bfloat162float(__float2bfloat16(e1));
            float h2 = __bfloat162float(__float2bfloat16(e2));
            float h3 = __bfloat162float(__float2bfloat16(e3));
            const int kk = nt >> 1, half = nt & 1;
            ah[kk][half*2+0] = pack_bf16(h0, h1);
            ah[kk][half*2+1] = pack_bf16(h2, h3);
            al[kk][half*2+0] = pack_bf16(e0-h0, e1-h1);
            al[kk][half*2+1] = pack_bf16(e2-h2, e3-h3);
        }
        #pragma unroll
        for (int kk = 0; kk < 2; kk++) {
            const uint32_t krow = (uint32_t)((c0 + kk*16))*APITCH;
            uint32_t vbh[4][4], vbl[4][4];
            #pragma unroll
            for (int p = 0; p < 4; p++) {
                ldsm4t(vbh[p], sb + SVH + krow + vb_rel + (uint32_t)(p*16*2));
                ldsm4t(vbl[p], sb + SVL + krow + vb_rel + (uint32_t)(p*16*2));
            }
            #pragma unroll
            for (int nt = 0; nt < 8; nt++) {
                const uint32_t* bhp = &vbh[nt>>1][(nt&1)*2];
                const uint32_t* blp = &vbl[nt>>1][(nt&1)*2];
                mma16816(o[nt], ah[kk], bhp);
                mma16816(o[nt], al[kk], bhp);
                mma16816(o[nt], ah[kk], blp);
            }
        }
    }

    float z0 = zacc0 + ((lane & 3) == 0 ? o[8][0] : 0.f);
    float z1 = zacc1 + ((lane & 3) == 0 ? o[8][2] : 0.f);
    z0 += __shfl_xor_sync(0xffffffff, z0, 1);
    z0 += __shfl_xor_sync(0xffffffff, z0, 2);
    z1 += __shfl_xor_sync(0xffffffff, z1, 1);
    z1 += __shfl_xor_sync(0xffffffff, z1, 2);
    const float inv0 = 1.f / (z0 + 1e-6f);
    const float inv1 = 1.f / (z1 + 1e-6f);

    const int b = bh >> 4, h = bh & 15;
    const size_t mbase0 = ((size_t)(b*TSEQ + c*CHUNK + row0))*D_MODEL + h*DK;
    const size_t mbase1 = ((size_t)(b*TSEQ + c*CHUNK + row1))*D_MODEL + h*DK;
    #pragma unroll
    for (int nt = 0; nt < 8; nt++) {
        const int e = nt*8 + (lane&3)*2;
        float y0 = o[nt][0]*inv0, y1 = o[nt][1]*inv0;
        float y2 = o[nt][2]*inv1, y3 = o[nt][3]*inv1;
        __nv_bfloat16 h0,h1,h2,h3,l0,l1,l2,l3;
        split_pair(y0,h0,l0); split_pair(y1,h1,l1);
        split_pair(y2,h2,l2); split_pair(y3,h3,l3);
        __nv_bfloat162 p0{h0,h1}, q0{l0,l1}, p1{h2,h3}, q1{l2,l3};
        *(__nv_bfloat162*)(g_a_hi + mbase0 + e) = p0;
        *(__nv_bfloat162*)(g_a_lo + mbase0 + e) = q0;
        *(__nv_bfloat162*)(g_a_hi + mbase1 + e) = p1;
        *(__nv_bfloat162*)(g_a_lo + mbase1 + e) = q1;
    }
}

// ---------------- launch ----------------
extern "C" void kernel_launch(void* const* d_in, const int* in_sizes, int n_in,
                              void* d_out, int out_size)
{
    (void)in_sizes; (void)n_in; (void)out_size;
    const float* x  = (const float*)d_in[0];
    const float* Wq = (const float*)d_in[1];
    const float* bq = (const float*)d_in[2];
    const float* Wk = (const float*)d_in[3];
    const float* bk = (const float*)d_in[4];
    const float* Wv = (const float*)d_in[5];
    const float* bv = (const float*)d_in[6];
    const float* Wo = (const float*)d_in[7];
    const float* bo = (const float*)d_in[8];
    float* out = (float*)d_out;

    cudaFuncSetAttribute(gemm_mma<0>, cudaFuncAttributeMaxDynamicSharedMemorySize, GEMM_SMEM);
    cudaFuncSetAttribute(gemm_mma<1>, cudaFuncAttributeMaxDynamicSharedMemorySize, GEMM_SMEM);
    cudaFuncSetAttribute(gemm_mma<2>, cudaFuncAttributeMaxDynamicSharedMemorySize, GEMM_SMEM);
    cudaFuncSetAttribute(gemm_mma<3>, cudaFuncAttributeMaxDynamicSharedMemorySize, GEMM_SMEM);
    cudaFuncSetAttribute(chunk_kv_mma,   cudaFuncAttributeMaxDynamicSharedMemorySize, CKV_SMEM);
    cudaFuncSetAttribute(attn_mma_kernel,cudaFuncAttributeMaxDynamicSharedMemorySize, ATT_SMEM);

    split_x_kernel<<<(MROWS*D_MODEL/4 + 255)/256, 256>>>(x, MROWS*D_MODEL/4);
    split_w_kernel<<<(4*D_MODEL*D_MODEL/4 + 255)/256, 256>>>(Wq, Wk, Wv, Wo);

    dim3 ggrid(D_MODEL/128, MROWS/128);   // (8, 32)
    gemm_mma<0><<<ggrid, 256, GEMM_SMEM>>>(bq, nullptr);
    gemm_mma<1><<<ggrid, 256, GEMM_SMEM>>>(bk, nullptr);
    gemm_mma<2><<<ggrid, 256, GEMM_SMEM>>>(bv, nullptr);

    chunk_kv_mma<<<NBH*NCHUNK, 128, CKV_SMEM>>>();
    chunk_scan_kernel<<<NBH, 256>>>();
    attn_mma_kernel<<<NBH*NCHUNK, 256, ATT_SMEM>>>();

    gemm_mma<3><<<ggrid, 256, GEMM_SMEM>>>(bo, out);
}

// round 7
// speedup vs baseline: 2.7711x; 1.1352x over previous
#include <cuda_runtime.h>
#include <cuda_bf16.h>
#include <cstdint>

#define D_MODEL 1024
#define N_HEADS 16
#define DK 64
#define BATCH 2
#define TSEQ 2048
#define MROWS (BATCH*TSEQ)   /* 4096 */
#define CHUNK 128
#define NCHUNK (TSEQ/CHUNK)  /* 16 */
#define NBH (BATCH*N_HEADS)  /* 32 */
#define KVE 72               /* KV ext cols: 64 + ksum + pad */

// ---------------- scratch (static device arrays; no allocation) ----------------
__device__ float g_kv[NBH*NCHUNK*DK*DK];
__device__ float g_ksum[NBH*NCHUNK*DK];
__device__ __nv_bfloat16 g_x_hi[MROWS*D_MODEL];
__device__ __nv_bfloat16 g_x_lo[MROWS*D_MODEL];
__device__ __nv_bfloat16 g_w_hi[4*D_MODEL*D_MODEL];
__device__ __nv_bfloat16 g_w_lo[4*D_MODEL*D_MODEL];
__device__ __nv_bfloat16 g_a_hi[MROWS*D_MODEL];
__device__ __nv_bfloat16 g_a_lo[MROWS*D_MODEL];
__device__ __nv_bfloat16 g_qh[NBH*TSEQ*DK], g_ql[NBH*TSEQ*DK];
__device__ __nv_bfloat16 g_kh[NBH*TSEQ*DK], g_kl[NBH*TSEQ*DK];
__device__ __nv_bfloat16 g_vh[NBH*TSEQ*DK], g_vl[NBH*TSEQ*DK];
__device__ __nv_bfloat16 g_kvh[NBH*NCHUNK*DK*KVE];
__device__ __nv_bfloat16 g_kvl[NBH*NCHUNK*DK*KVE];

__device__ __forceinline__ float phi_fn(float x) {
    return x > 0.f ? x + 1.f : __expf(x);
}
__device__ __forceinline__ uint32_t smem_to_u32(const void* smem_ptr) {
    uint32_t addr;
    asm("{ .reg .u64 tmp; cvta.to.shared.u64 tmp, %1; cvt.u32.u64 %0, tmp; }"
        : "=r"(addr) : "l"(smem_ptr));
    return addr;
}

// ---------------- mma / ldmatrix / cp.async primitives ----------------
__device__ __forceinline__ void mma16816(float* d, const uint32_t* a, const uint32_t* b) {
    asm volatile(
        "mma.sync.aligned.m16n8k16.row.col.f32.bf16.bf16.f32 "
        "{%0,%1,%2,%3}, {%4,%5,%6,%7}, {%8,%9}, {%0,%1,%2,%3};"
        : "+f"(d[0]), "+f"(d[1]), "+f"(d[2]), "+f"(d[3])
        : "r"(a[0]), "r"(a[1]), "r"(a[2]), "r"(a[3]), "r"(b[0]), "r"(b[1]));
}
__device__ __forceinline__ void ldsm4(uint32_t* r, uint32_t addr) {
    asm volatile("ldmatrix.sync.aligned.m8n8.x4.shared.b16 {%0,%1,%2,%3}, [%4];"
        : "=r"(r[0]), "=r"(r[1]), "=r"(r[2]), "=r"(r[3]) : "r"(addr));
}
__device__ __forceinline__ void ldsm4t(uint32_t* r, uint32_t addr) {
    asm volatile("ldmatrix.sync.aligned.m8n8.x4.trans.shared.b16 {%0,%1,%2,%3}, [%4];"
        : "=r"(r[0]), "=r"(r[1]), "=r"(r[2]), "=r"(r[3]) : "r"(addr));
}
__device__ __forceinline__ void ldsm2t(uint32_t* r, uint32_t addr) {
    asm volatile("ldmatrix.sync.aligned.m8n8.x2.trans.shared.b16 {%0,%1}, [%2];"
        : "=r"(r[0]), "=r"(r[1]) : "r"(addr));
}
#define CP_ASYNC16(dst, src) \
    asm volatile("cp.async.cg.shared.global [%0], [%1], 16;" :: "r"(dst), "l"(src))
#define CP_COMMIT() asm volatile("cp.async.commit_group;" ::: "memory")
#define CP_WAIT2()  asm volatile("cp.async.wait_group 2;" ::: "memory")
#define CP_WAIT1()  asm volatile("cp.async.wait_group 1;" ::: "memory")
#define CP_WAIT0()  asm volatile("cp.async.wait_group 0;" ::: "memory")

__device__ __forceinline__ uint32_t pack_bf16(float lo, float hi) {
    __nv_bfloat162 p = __floats2bfloat162_rn(lo, hi);
    return *reinterpret_cast<uint32_t*>(&p);
}
__device__ __forceinline__ void split_pair(float y, __nv_bfloat16& h, __nv_bfloat16& l) {
    h = __float2bfloat16(y);
    l = __float2bfloat16(y - __bfloat162float(h));
}

// ---------------- fp32 -> bf16 hi/lo splits ----------------
__global__ __launch_bounds__(256) void split_x_kernel(const float* __restrict__ src, int n4)
{
    int i = blockIdx.x * 256 + threadIdx.x;
    if (i >= n4) return;
    float4 v = ((const float4*)src)[i];
    __nv_bfloat16 h0,h1,h2,h3,l0,l1,l2,l3;
    split_pair(v.x,h0,l0); split_pair(v.y,h1,l1);
    split_pair(v.z,h2,l2); split_pair(v.w,h3,l3);
    __nv_bfloat162 ph0{h0,h1}, ph1{h2,h3}, pl0{l0,l1}, pl1{l2,l3};
    ((__nv_bfloat162*)(g_x_hi + 4*(size_t)i))[0] = ph0;
    ((__nv_bfloat162*)(g_x_hi + 4*(size_t)i))[1] = ph1;
    ((__nv_bfloat162*)(g_x_lo + 4*(size_t)i))[0] = pl0;
    ((__nv_bfloat162*)(g_x_lo + 4*(size_t)i))[1] = pl1;
}
__global__ __launch_bounds__(256) void split_w_kernel(
    const float* __restrict__ w0, const float* __restrict__ w1,
    const float* __restrict__ w2, const float* __restrict__ w3)
{
    const int per = D_MODEL*D_MODEL/4;
    int i = blockIdx.x * 256 + threadIdx.x;
    int sel = i >> 18, loc = i & (per - 1);
    const float* src = (sel == 0) ? w0 : (sel == 1) ? w1 : (sel == 2) ? w2 : w3;
    float4 v = ((const float4*)src)[loc];
    size_t o = (size_t)sel * D_MODEL * D_MODEL + 4*(size_t)loc;
    __nv_bfloat16 h0,h1,h2,h3,l0,l1,l2,l3;
    split_pair(v.x,h0,l0); split_pair(v.y,h1,l1);
    split_pair(v.z,h2,l2); split_pair(v.w,h3,l3);
    __nv_bfloat162 ph0{h0,h1}, ph1{h2,h3}, pl0{l0,l1}, pl1{l2,l3};
    ((__nv_bfloat162*)(g_w_hi + o))[0] = ph0;
    ((__nv_bfloat162*)(g_w_hi + o))[1] = ph1;
    ((__nv_bfloat162*)(g_w_lo + o))[0] = pl0;
    ((__nv_bfloat162*)(g_w_lo + o))[1] = pl1;
}

// ---------------- split-bf16 GEMM: 3-stage, swizzled 64B pitch, 2 CTAs/SM ----------------
#define TILE_B (128*64)             /* 8192 */
#define STAGE_B (4*TILE_B)          /* 32768 */
#define GEMM_SMEM (3*STAGE_B)       /* 98304 -> 2 CTAs/SM */
#define NSTG 32

__device__ __forceinline__ uint32_t swz(int row, int cl) {
    return (uint32_t)(row*64 + (((cl ^ ((row>>1)&3)) & 3) << 4));
}

// ep: 0=Wq->phi->q, 1=Wk->phi->k, 2=Wv->v, 3=g_a@Wo^T->outp
__device__ __forceinline__ void gemm_body(
    int ep, const __nv_bfloat16* __restrict__ Xh, const __nv_bfloat16* __restrict__ Xl,
    const float* __restrict__ bias, float* __restrict__ outp, char* smem)
{
    const uint32_t sb = smem_to_u32(smem);
    const int tid = threadIdx.x;
    const int lane = tid & 31, wid = tid >> 5;
    const int wm = wid & 1, wn = wid >> 1;
    const int m0 = blockIdx.y * 128;
    const int n0 = blockIdx.x * 128;

    const __nv_bfloat16* Wh = g_w_hi + (size_t)ep * D_MODEL * D_MODEL;
    const __nv_bfloat16* Wl = g_w_lo + (size_t)ep * D_MODEL * D_MODEL;

    float acc[4][4][4];
    #pragma unroll
    for (int i = 0; i < 4; i++)
        #pragma unroll
        for (int j = 0; j < 4; j++)
            #pragma unroll
            for (int l = 0; l < 4; l++) acc[i][j][l] = 0.f;

    const int r0l = tid >> 2, c0l = tid & 3;
    const int r1l = r0l + 64;
    const uint32_t d0 = swz(r0l, c0l), d1 = swz(r1l, c0l);

    auto load_stage = [&](int buf, int k0) {
        uint32_t base = sb + buf * STAGE_B;
        #pragma unroll
        for (int t = 0; t < 4; t++) {
            const __nv_bfloat16* src = (t == 0) ? Xh : (t == 1) ? Xl : (t == 2) ? Wh : Wl;
            const int row0 = (t < 2) ? m0 : n0;
            CP_ASYNC16(base + t*TILE_B + d0,
                       src + (size_t)(row0 + r0l)*D_MODEL + k0 + c0l*8);
            CP_ASYNC16(base + t*TILE_B + d1,
                       src + (size_t)(row0 + r1l)*D_MODEL + k0 + c0l*8);
        }
        CP_COMMIT();
    };

    load_stage(0, 0);
    load_stage(1, 32);

    for (int kc = 0; kc < NSTG; kc++) {
        // issue prefetch FIRST so >=3 groups are in flight before the wait
        if (kc + 2 < NSTG) load_stage((kc + 2) % 3, (kc + 2) * 32);
        if (kc + 2 < NSTG)       { CP_WAIT2(); }
        else if (kc == NSTG-2)   { CP_WAIT1(); }
        else                     { CP_WAIT0(); }
        __syncthreads();

        const uint32_t base = sb + (kc % 3) * STAGE_B;
        #pragma unroll
        for (int ks = 0; ks < 2; ks++) {
            uint32_t ah[4][4], al[4][4], bh[2][4], bl[2][4];
            #pragma unroll
            for (int mt = 0; mt < 4; mt++) {
                const int rA = wm*64 + mt*16 + (lane & 15);
                const uint32_t offA = swz(rA, (lane >> 4) + 2*ks);
                ldsm4(ah[mt], base + 0*TILE_B + offA);
                ldsm4(al[mt], base + 1*TILE_B + offA);
            }
            #pragma unroll
            for (int op = 0; op < 2; op++) {
                const int rB = wn*32 + op*16 + ((lane >> 4) << 3) + (lane & 7);
                const uint32_t offB = swz(rB, ((lane >> 3) & 1) + 2*ks);
                ldsm4(bh[op], base + 2*TILE_B + offB);
                ldsm4(bl[op], base + 3*TILE_B + offB);
            }
            #pragma unroll
            for (int mt = 0; mt < 4; mt++)
                #pragma unroll
                for (int nt = 0; nt < 4; nt++) {
                    const uint32_t* bhp = &bh[nt >> 1][(nt & 1) * 2];
                    const uint32_t* blp = &bl[nt >> 1][(nt & 1) * 2];
                    mma16816(acc[mt][nt], ah[mt], bhp);
                    mma16816(acc[mt][nt], al[mt], bhp);
                    mma16816(acc[mt][nt], ah[mt], blp);
                }
        }
        __syncthreads();
    }

    // ---- epilogue ----
    const int m_base = m0 + wm*64;
    #pragma unroll
    for (int mt = 0; mt < 4; mt++) {
        #pragma unroll
        for (int nt = 0; nt < 4; nt++) {
            const int n = n0 + wn*32 + nt*8 + (lane & 3)*2;
            const float b0v = bias[n], b1v = bias[n+1];
            #pragma unroll
            for (int half = 0; half < 2; half++) {
                const int m = m_base + mt*16 + (lane >> 2) + half*8;
                float y0 = acc[mt][nt][half*2+0] + b0v;
                float y1 = acc[mt][nt][half*2+1] + b1v;
                if (ep <= 1) { y0 = phi_fn(y0); y1 = phi_fn(y1); }
                if (ep <= 2) {
                    const int h = n >> 6, d = n & 63;
                    const int b = m >> 11, t = m & (TSEQ-1);
                    const size_t off = ((size_t)((b*N_HEADS + h)*TSEQ + t))*DK + d;
                    __nv_bfloat16 h0,h1,l0,l1;
                    split_pair(y0,h0,l0); split_pair(y1,h1,l1);
                    __nv_bfloat162 ph{h0,h1}, pl{l0,l1};
                    __nv_bfloat16* dh = (ep == 0) ? g_qh : (ep == 1) ? g_kh : g_vh;
                    __nv_bfloat16* dl = (ep == 0) ? g_ql : (ep == 1) ? g_kl : g_vl;
                    *(__nv_bfloat162*)(dh + off) = ph;
                    *(__nv_bfloat162*)(dl + off) = pl;
                } else {
                    *(float2*)(outp + (size_t)m*D_MODEL + n) = make_float2(y0, y1);
                }
            }
        }
    }
}

__global__ __launch_bounds__(256, 2) void gemm_qkv(
    const float* __restrict__ bq, const float* __restrict__ bk,
    const float* __restrict__ bv)
{
    extern __shared__ char smem[];
    const int ep = blockIdx.z;
    const float* bias = (ep == 0) ? bq : (ep == 1) ? bk : bv;
    gemm_body(ep, g_x_hi, g_x_lo, bias, nullptr, smem);
}
__global__ __launch_bounds__(256, 2) void gemm_wo(
    const float* __restrict__ bo, float* __restrict__ outp)
{
    extern __shared__ char smem[];
    gemm_body(3, g_a_hi, g_a_lo, bo, outp, smem);
}

// ================= attention on tensor cores =================
#define APITCH 144
#define ATILE (128*APITCH)
#define KVTILE (DK*APITCH)

#define CKV_SMEM (4*ATILE)
__global__ __launch_bounds__(128) void chunk_kv_mma()
{
    extern __shared__ char smem[];
    const uint32_t sb = smem_to_u32(smem);
    const uint32_t SKH = 0, SKL = ATILE, SVH = 2*ATILE, SVL = 3*ATILE;
    const int blk = blockIdx.x;
    const int bh = blk >> 4, c = blk & 15;
    const int tid = threadIdx.x;
    const int lane = tid & 31, wid = tid >> 5;
    const size_t gbase = (size_t)bh*TSEQ*DK + (size_t)c*CHUNK*DK;

    #pragma unroll
    for (int it = 0; it < 8; it++) {
        int idx = tid + it*128;
        int r = idx >> 3, cc = idx & 7;
        const size_t so = gbase + (size_t)r*DK + cc*8;
        *(float4*)(smem + SKH + r*APITCH + cc*16) = *(const float4*)(g_kh + so);
        *(float4*)(smem + SKL + r*APITCH + cc*16) = *(const float4*)(g_kl + so);
        *(float4*)(smem + SVH + r*APITCH + cc*16) = *(const float4*)(g_vh + so);
        *(float4*)(smem + SVL + r*APITCH + cc*16) = *(const float4*)(g_vl + so);
    }
    __syncthreads();

    float f[8][4];
    #pragma unroll
    for (int n = 0; n < 8; n++)
        #pragma unroll
        for (int l = 0; l < 4; l++) f[n][l] = 0.f;

    const uint32_t ka_rel = (uint32_t)(( ((lane>>4)&1)*8 + (lane&7) )*APITCH
                                       + (wid*16 + ((lane>>3)&1)*8)*2);
    const uint32_t vb_rel = (uint32_t)(( ((lane>>3)&1)*8 + (lane&7) )*APITCH
                                       + ((lane>>4)*8)*2);
    #pragma unroll
    for (int ks = 0; ks < 8; ks++) {
        const uint32_t krow = (uint32_t)(ks*16)*APITCH;
        uint32_t kah[4], kal[4], vbh[4][4], vbl[4][4];
        ldsm4t(kah, sb + SKH + krow + ka_rel);
        ldsm4t(kal, sb + SKL + krow + ka_rel);
        #pragma unroll
        for (int p = 0; p < 4; p++) {
            ldsm4t(vbh[p], sb + SVH + krow + vb_rel + (uint32_t)(p*16*2));
            ldsm4t(vbl[p], sb + SVL + krow + vb_rel + (uint32_t)(p*16*2));
        }
        #pragma unroll
        for (int nt = 0; nt < 8; nt++) {
            const uint32_t* bhp = &vbh[nt>>1][(nt&1)*2];
            const uint32_t* blp = &vbl[nt>>1][(nt&1)*2];
            mma16816(f[nt], kah, bhp);
            mma16816(f[nt], kal, bhp);
            mma16816(f[nt], kah, blp);
        }
    }

    float* kvout = g_kv + (size_t)blk*DK*DK;
    const int d0 = wid*16 + (lane>>2);
    #pragma unroll
    for (int nt = 0; nt < 8; nt++) {
        const int e = nt*8 + (lane&3)*2;
        *(float2*)(kvout + (size_t)d0*DK + e)     = make_float2(f[nt][0], f[nt][1]);
        *(float2*)(kvout + (size_t)(d0+8)*DK + e) = make_float2(f[nt][2], f[nt][3]);
    }

    if (tid < 64) {
        float s = 0.f;
        #pragma unroll 4
        for (int t = 0; t < 128; t++) {
            s += __bfloat162float(*(const __nv_bfloat16*)(smem + SKH + t*APITCH + tid*2));
            s += __bfloat162float(*(const __nv_bfloat16*)(smem + SKL + t*APITCH + tid*2));
        }
        g_ksum[(size_t)blk*DK + tid] = s;
    }
}

__global__ __launch_bounds__(256) void chunk_scan_kernel()
{
    const int bh = blockIdx.x;
    const int tid = threadIdx.x;
    for (int pos = tid; pos < DK*KVE; pos += 256) {
        const int d = pos / KVE, e = pos % KVE;
        float run = 0.f;
        #pragma unroll
        for (int c = 0; c < NCHUNK; c++) {
            const size_t blk = (size_t)(bh*NCHUNK + c);
            __nv_bfloat16 h, l;
            split_pair(run, h, l);
            g_kvh[blk*DK*KVE + pos] = h;
            g_kvl[blk*DK*KVE + pos] = l;
            float val = 0.f;
            if (e < DK)       val = g_kv[blk*DK*DK + (size_t)d*DK + e];
            else if (e == DK) val = g_ksum[blk*DK + d];
            run += val;
        }
    }
}

#define ATT_SMEM (6*ATILE + 2*KVTILE)
__global__ __launch_bounds__(256) void attn_mma_kernel()
{
    extern __shared__ char smem[];
    const uint32_t sb = smem_to_u32(smem);
    const uint32_t SQH = 0, SQL = ATILE, SKH = 2*ATILE, SKL = 3*ATILE;
    const uint32_t SVH = 4*ATILE, SVL = 5*ATILE;
    const uint32_t SGH = 6*ATILE, SGL = 6*ATILE + KVTILE;

    const int blk = blockIdx.x;
    const int bh = blk >> 4, c = blk & 15;
    const int tid = threadIdx.x;
    const int lane = tid & 31, wid = tid >> 5;
    const size_t gbase = (size_t)bh*TSEQ*DK + (size_t)c*CHUNK*DK;

    #pragma unroll
    for (int it = 0; it < 4; it++) {
        int idx = tid + it*256;
        int r = idx >> 3, cc = idx & 7;
        const size_t so = gbase + (size_t)r*DK + cc*8;
        const uint32_t doff = r*APITCH + cc*16;
        *(float4*)(smem + SQH + doff) = *(const float4*)(g_qh + so);
        *(float4*)(smem + SQL + doff) = *(const float4*)(g_ql + so);
        *(float4*)(smem + SKH + doff) = *(const float4*)(g_kh + so);
        *(float4*)(smem + SKL + doff) = *(const float4*)(g_kl + so);
        *(float4*)(smem + SVH + doff) = *(const float4*)(g_vh + so);
        *(float4*)(smem + SVL + doff) = *(const float4*)(g_vl + so);
    }
    {
        const size_t kvbase = (size_t)blk*DK*KVE;
        for (int idx = tid; idx < 576; idx += 256) {
            int r = idx / 9, cc = idx % 9;
            *(float4*)(smem + SGH + r*APITCH + cc*16) = *(const float4*)(g_kvh + kvbase + (size_t)r*KVE + cc*8);
            *(float4*)(smem + SGL + r*APITCH + cc*16) = *(const float4*)(g_kvl + kvbase + (size_t)r*KVE + cc*8);
        }
    }
    __syncthreads();

    const int rbase = wid * 16;
    const uint32_t qa_rel = (uint32_t)((rbase + (lane & 15))*APITCH + (lane >> 4)*16);
    uint32_t qh[4][4], ql[4][4];
    #pragma unroll
    for (int ks = 0; ks < 4; ks++) {
        ldsm4(qh[ks], sb + SQH + qa_rel + ks*32);
        ldsm4(ql[ks], sb + SQL + qa_rel + ks*32);
    }

    float o[9][4];
    #pragma unroll
    for (int n = 0; n < 9; n++)
        #pragma unroll
        for (int l = 0; l < 4; l++) o[n][l] = 0.f;

    const uint32_t gb_rel = (uint32_t)(( ((lane>>3)&1)*8 + (lane&7) )*APITCH + ((lane>>4)*8)*2);
    #pragma unroll
    for (int ks = 0; ks < 4; ks++) {
        const uint32_t krow = (uint32_t)(ks*16)*APITCH;
        uint32_t gbh[4][4], gbl[4][4], g2h[2], g2l[2];
        #pragma unroll
        for (int p = 0; p < 4; p++) {
            ldsm4t(gbh[p], sb + SGH + krow + gb_rel + (uint32_t)(p*16*2));
            ldsm4t(gbl[p], sb + SGL + krow + gb_rel + (uint32_t)(p*16*2));
        }
        const uint32_t g2_rel = (uint32_t)(( ((lane>>3)&1)*8 + (lane&7) )*APITCH + 64*2);
        ldsm2t(g2h, sb + SGH + krow + g2_rel);
        ldsm2t(g2l, sb + SGL + krow + g2_rel);
        #pragma unroll
        for (int nt = 0; nt < 8; nt++) {
            const uint32_t* bhp = &gbh[nt>>1][(nt&1)*2];
            const uint32_t* blp = &gbl[nt>>1][(nt&1)*2];
            mma16816(o[nt], qh[ks], bhp);
            mma16816(o[nt], ql[ks], bhp);
            mma16816(o[nt], qh[ks], blp);
        }
        mma16816(o[8], qh[ks], g2h);
        mma16816(o[8], ql[ks], g2h);
        mma16816(o[8], qh[ks], g2l);
    }

    float zacc0 = 0.f, zacc1 = 0.f;
    const int row0 = rbase + (lane >> 2), row1 = row0 + 8;
    const int ncc = wid/2 + 1;
    const uint32_t kb_col = (uint32_t)(((lane>>3)&1)*16);
    const uint32_t vb_rel = (uint32_t)(( ((lane>>3)&1)*8 + (lane&7) )*APITCH + ((lane>>4)*8)*2);

    for (int cc = 0; cc < ncc; cc++) {
        const int c0 = cc*32;
        float s[4][4];
        #pragma unroll
        for (int n = 0; n < 4; n++)
            #pragma unroll
            for (int l = 0; l < 4; l++) s[n][l] = 0.f;
        #pragma unroll
        for (int ks = 0; ks < 4; ks++) {
            uint32_t kbh[2][4], kbl[2][4];
            #pragma unroll
            for (int p = 0; p < 2; p++) {
                const uint32_t kb = (uint32_t)((c0 + 16*p + ((lane>>4)<<3) + (lane&7))*APITCH)
                                    + kb_col + (uint32_t)(ks*32);
                ldsm4(kbh[p], sb + SKH + kb);
                ldsm4(kbl[p], sb + SKL + kb);
            }
            #pragma unroll
            for (int nt = 0; nt < 4; nt++) {
                const uint32_t* bhp = &kbh[nt>>1][(nt&1)*2];
                const uint32_t* blp = &kbl[nt>>1][(nt&1)*2];
                mma16816(s[nt], qh[ks], bhp);
                mma16816(s[nt], ql[ks], bhp);
                mma16816(s[nt], qh[ks], blp);
            }
        }
        uint32_t ah[2][4], al[2][4];
        #pragma unroll
        for (int nt = 0; nt < 4; nt++) {
            const int colj = c0 + nt*8 + (lane&3)*2;
            float e0 = (colj   <= row0) ? s[nt][0] : 0.f;
            float e1 = (colj+1 <= row0) ? s[nt][1] : 0.f;
            float e2 = (colj   <= row1) ? s[nt][2] : 0.f;
            float e3 = (colj+1 <= row1) ? s[nt][3] : 0.f;
            zacc0 += e0 + e1;
            zacc1 += e2 + e3;
            float h0 = __bfloat162float(__float2bfloat16(e0));
            float h1 = __bfloat162float(__float2bfloat16(e1));
            float h2 = __bfloat162float(__float2bfloat16(e2));
            float h3 = __bfloat162float(__float2bfloat16(e3));
            const int kk = nt >> 1, half = nt & 1;
            ah[kk][half*2+0] = pack_bf16(h0, h1);
            ah[kk][half*2+1] = pack_bf16(h2, h3);
            al[kk][half*2+0] = pack_bf16(e0-h0, e1-h1);
            al[kk][half*2+1] = pack_bf16(e2-h2, e3-h3);
        }
        #pragma unroll
        for (int kk = 0; kk < 2; kk++) {
            const uint32_t krow = (uint32_t)((c0 + kk*16))*APITCH;
            uint32_t vbh[4][4], vbl[4][4];
            #pragma unroll
            for (int p = 0; p < 4; p++) {
                ldsm4t(vbh[p], sb + SVH + krow + vb_rel + (uint32_t)(p*16*2));
                ldsm4t(vbl[p], sb + SVL + krow + vb_rel + (uint32_t)(p*16*2));
            }
            #pragma unroll
            for (int nt = 0; nt < 8; nt++) {
                const uint32_t* bhp = &vbh[nt>>1][(nt&1)*2];
                const uint32_t* blp = &vbl[nt>>1][(nt&1)*2];
                mma16816(o[nt], ah[kk], bhp);
                mma16816(o[nt], al[kk], bhp);
                mma16816(o[nt], ah[kk], blp);
            }
        }
    }

    float z0 = zacc0 + ((lane & 3) == 0 ? o[8][0] : 0.f);
    float z1 = zacc1 + ((lane & 3) == 0 ? o[8][2] : 0.f);
    z0 += __shfl_xor_sync(0xffffffff, z0, 1);
    z0 += __shfl_xor_sync(0xffffffff, z0, 2);
    z1 += __shfl_xor_sync(0xffffffff, z1, 1);
    z1 += __shfl_xor_sync(0xffffffff, z1, 2);
    const float inv0 = 1.f / (z0 + 1e-6f);
    const float inv1 = 1.f / (z1 + 1e-6f);

    const int b = bh >> 4, h = bh & 15;
    const size_t mbase0 = ((size_t)(b*TSEQ + c*CHUNK + row0))*D_MODEL + h*DK;
    const size_t mbase1 = ((size_t)(b*TSEQ + c*CHUNK + row1))*D_MODEL + h*DK;
    #pragma unroll
    for (int nt = 0; nt < 8; nt++) {
        const int e = nt*8 + (lane&3)*2;
        float y0 = o[nt][0]*inv0, y1 = o[nt][1]*inv0;
        float y2 = o[nt][2]*inv1, y3 = o[nt][3]*inv1;
        __nv_bfloat16 h0,h1,h2,h3,l0,l1,l2,l3;
        split_pair(y0,h0,l0); split_pair(y1,h1,l1);
        split_pair(y2,h2,l2); split_pair(y3,h3,l3);
        __nv_bfloat162 p0{h0,h1}, q0{l0,l1}, p1{h2,h3}, q1{l2,l3};
        *(__nv_bfloat162*)(g_a_hi + mbase0 + e) = p0;
        *(__nv_bfloat162*)(g_a_lo + mbase0 + e) = q0;
        *(__nv_bfloat162*)(g_a_hi + mbase1 + e) = p1;
        *(__nv_bfloat162*)(g_a_lo + mbase1 + e) = q1;
    }
}

// ---------------- launch ----------------
extern "C" void kernel_launch(void* const* d_in, const int* in_sizes, int n_in,
                              void* d_out, int out_size)
{
    (void)in_sizes; (void)n_in; (void)out_size;
    const float* x  = (const float*)d_in[0];
    const float* Wq = (const float*)d_in[1];
    const float* bq = (const float*)d_in[2];
    const float* Wk = (const float*)d_in[3];
    const float* bk = (const float*)d_in[4];
    const float* Wv = (const float*)d_in[5];
    const float* bv = (const float*)d_in[6];
    const float* Wo = (const float*)d_in[7];
    const float* bo = (const float*)d_in[8];
    float* out = (float*)d_out;

    cudaFuncSetAttribute(gemm_qkv, cudaFuncAttributeMaxDynamicSharedMemorySize, GEMM_SMEM);
    cudaFuncSetAttribute(gemm_wo,  cudaFuncAttributeMaxDynamicSharedMemorySize, GEMM_SMEM);
    cudaFuncSetAttribute(chunk_kv_mma,    cudaFuncAttributeMaxDynamicSharedMemorySize, CKV_SMEM);
    cudaFuncSetAttribute(attn_mma_kernel, cudaFuncAttributeMaxDynamicSharedMemorySize, ATT_SMEM);

    split_x_kernel<<<(MROWS*D_MODEL/4 + 255)/256, 256>>>(x, MROWS*D_MODEL/4);
    split_w_kernel<<<(4*D_MODEL*D_MODEL/4 + 255)/256, 256>>>(Wq, Wk, Wv, Wo);

    dim3 gq(D_MODEL/128, MROWS/128, 3);   // (8, 32, 3)
    gemm_qkv<<<gq, 256, GEMM_SMEM>>>(bq, bk, bv);

    chunk_kv_mma<<<NBH*NCHUNK, 128, CKV_SMEM>>>();
    chunk_scan_kernel<<<NBH, 256>>>();
    attn_mma_kernel<<<NBH*NCHUNK, 256, ATT_SMEM>>>();

    dim3 go(D_MODEL/128, MROWS/128);      // (8, 32)
    gemm_wo<<<go, 256, GEMM_SMEM>>>(bo, out);
}

// round 8
// speedup vs baseline: 3.6095x; 1.3025x over previous
#include <cuda_runtime.h>
#include <cuda_bf16.h>
#include <cuda_fp16.h>
#include <cstdint>

#define D_MODEL 1024
#define N_HEADS 16
#define DK 64
#define BATCH 2
#define TSEQ 2048
#define MROWS (BATCH*TSEQ)   /* 4096 */
#define CHUNK 128
#define NCHUNK (TSEQ/CHUNK)  /* 16 */
#define NBH (BATCH*N_HEADS)  /* 32 */
#define KVE 72               /* KV ext cols: 64 + ksum + pad */

// ---------------- scratch (static device arrays; no allocation) ----------------
__device__ float g_kv[NBH*NCHUNK*DK*DK];
__device__ float g_ksum[NBH*NCHUNK*DK];
// fp16 GEMM operands (W pre-scaled by 32, split hi/lo; x and attn-out single fp16)
__device__ __half g_xh[MROWS*D_MODEL];
__device__ __half g_wh[4*D_MODEL*D_MODEL];
__device__ __half g_wl[4*D_MODEL*D_MODEL];
__device__ __half g_ah[MROWS*D_MODEL];
// bf16 hi/lo attention operands
__device__ __nv_bfloat16 g_qh[NBH*TSEQ*DK], g_ql[NBH*TSEQ*DK];
__device__ __nv_bfloat16 g_kh[NBH*TSEQ*DK], g_kl[NBH*TSEQ*DK];
__device__ __nv_bfloat16 g_vh[NBH*TSEQ*DK], g_vl[NBH*TSEQ*DK];
__device__ __nv_bfloat16 g_kvh[NBH*NCHUNK*DK*KVE];
__device__ __nv_bfloat16 g_kvl[NBH*NCHUNK*DK*KVE];

__device__ __forceinline__ float phi_fn(float x) {
    return x > 0.f ? x + 1.f : __expf(x);
}
__device__ __forceinline__ uint32_t smem_to_u32(const void* smem_ptr) {
    uint32_t addr;
    asm("{ .reg .u64 tmp; cvta.to.shared.u64 tmp, %1; cvt.u32.u64 %0, tmp; }"
        : "=r"(addr) : "l"(smem_ptr));
    return addr;
}

// ---------------- mma / ldmatrix / cp.async primitives ----------------
__device__ __forceinline__ void mma16816(float* d, const uint32_t* a, const uint32_t* b) {
    asm volatile(
        "mma.sync.aligned.m16n8k16.row.col.f32.bf16.bf16.f32 "
        "{%0,%1,%2,%3}, {%4,%5,%6,%7}, {%8,%9}, {%0,%1,%2,%3};"
        : "+f"(d[0]), "+f"(d[1]), "+f"(d[2]), "+f"(d[3])
        : "r"(a[0]), "r"(a[1]), "r"(a[2]), "r"(a[3]), "r"(b[0]), "r"(b[1]));
}
__device__ __forceinline__ void mma16816h(float* d, const uint32_t* a, const uint32_t* b) {
    asm volatile(
        "mma.sync.aligned.m16n8k16.row.col.f32.f16.f16.f32 "
        "{%0,%1,%2,%3}, {%4,%5,%6,%7}, {%8,%9}, {%0,%1,%2,%3};"
        : "+f"(d[0]), "+f"(d[1]), "+f"(d[2]), "+f"(d[3])
        : "r"(a[0]), "r"(a[1]), "r"(a[2]), "r"(a[3]), "r"(b[0]), "r"(b[1]));
}
__device__ __forceinline__ void ldsm4(uint32_t* r, uint32_t addr) {
    asm volatile("ldmatrix.sync.aligned.m8n8.x4.shared.b16 {%0,%1,%2,%3}, [%4];"
        : "=r"(r[0]), "=r"(r[1]), "=r"(r[2]), "=r"(r[3]) : "r"(addr));
}
__device__ __forceinline__ void ldsm4t(uint32_t* r, uint32_t addr) {
    asm volatile("ldmatrix.sync.aligned.m8n8.x4.trans.shared.b16 {%0,%1,%2,%3}, [%4];"
        : "=r"(r[0]), "=r"(r[1]), "=r"(r[2]), "=r"(r[3]) : "r"(addr));
}
__device__ __forceinline__ void ldsm2t(uint32_t* r, uint32_t addr) {
    asm volatile("ldmatrix.sync.aligned.m8n8.x2.trans.shared.b16 {%0,%1}, [%2];"
        : "=r"(r[0]), "=r"(r[1]) : "r"(addr));
}
#define CP_ASYNC16(dst, src) \
    asm volatile("cp.async.cg.shared.global [%0], [%1], 16;" :: "r"(dst), "l"(src))
#define CP_COMMIT() asm volatile("cp.async.commit_group;" ::: "memory")
#define CP_WAIT2()  asm volatile("cp.async.wait_group 2;" ::: "memory")
#define CP_WAIT1()  asm volatile("cp.async.wait_group 1;" ::: "memory")
#define CP_WAIT0()  asm volatile("cp.async.wait_group 0;" ::: "memory")

__device__ __forceinline__ uint32_t pack_bf16(float lo, float hi) {
    __nv_bfloat162 p = __floats2bfloat162_rn(lo, hi);
    return *reinterpret_cast<uint32_t*>(&p);
}
__device__ __forceinline__ void split_pair(float y, __nv_bfloat16& h, __nv_bfloat16& l) {
    h = __float2bfloat16(y);
    l = __float2bfloat16(y - __bfloat162float(h));
}
__device__ __forceinline__ void split_pair_h(float y, __half& h, __half& l) {
    h = __float2half(y);
    l = __float2half(y - __half2float(h));
}

// ---------------- input conversions ----------------
__global__ __launch_bounds__(256) void split_x_kernel(const float* __restrict__ src, int n4)
{
    int i = blockIdx.x * 256 + threadIdx.x;
    if (i >= n4) return;
    float4 v = ((const float4*)src)[i];
    __half2 h01 = __floats2half2_rn(v.x, v.y);
    __half2 h23 = __floats2half2_rn(v.z, v.w);
    ((__half2*)(g_xh + 4*(size_t)i))[0] = h01;
    ((__half2*)(g_xh + 4*(size_t)i))[1] = h23;
}
__global__ __launch_bounds__(256) void split_w_kernel(
    const float* __restrict__ w0, const float* __restrict__ w1,
    const float* __restrict__ w2, const float* __restrict__ w3)
{
    const int per = D_MODEL*D_MODEL/4;
    int i = blockIdx.x * 256 + threadIdx.x;
    int sel = i >> 18, loc = i & (per - 1);
    const float* src = (sel == 0) ? w0 : (sel == 1) ? w1 : (sel == 2) ? w2 : w3;
    float4 v = ((const float4*)src)[loc];
    size_t o = (size_t)sel * D_MODEL * D_MODEL + 4*(size_t)loc;
    __half h0,h1,h2,h3,l0,l1,l2,l3;
    split_pair_h(v.x*32.f,h0,l0); split_pair_h(v.y*32.f,h1,l1);
    split_pair_h(v.z*32.f,h2,l2); split_pair_h(v.w*32.f,h3,l3);
    __half2 ph0{h0,h1}, ph1{h2,h3}, pl0{l0,l1}, pl1{l2,l3};
    ((__half2*)(g_wh + o))[0] = ph0;
    ((__half2*)(g_wh + o))[1] = ph1;
    ((__half2*)(g_wl + o))[0] = pl0;
    ((__half2*)(g_wl + o))[1] = pl1;
}

// ---------------- fp16 2-term GEMM: 4-stage, swizzled 64B pitch, 2 CTAs/SM ----------------
#define TILE_B (128*64)             /* 8192 */
#define STAGE_B (3*TILE_B)          /* 24576: XH WH WL */
#define GEMM_SMEM (4*STAGE_B)       /* 98304 -> 2 CTAs/SM */
#define NSTG 32

__device__ __forceinline__ uint32_t swz(int row, int cl) {
    return (uint32_t)(row*64 + (((cl ^ ((row>>1)&3)) & 3) << 4));
}

// ep: 0=Wq->phi->q, 1=Wk->phi->k, 2=Wv->v, 3=g_ah@Wo^T->outp
__device__ __forceinline__ void gemm_body(
    int ep, const __half* __restrict__ Xh,
    const float* __restrict__ bias, float* __restrict__ outp, char* smem)
{
    const uint32_t sb = smem_to_u32(smem);
    const int tid = threadIdx.x;
    const int lane = tid & 31, wid = tid >> 5;
    const int wm = wid & 1, wn = wid >> 1;
    const int m0 = blockIdx.y * 128;
    const int n0 = blockIdx.x * 128;

    const __half* Wh = g_wh + (size_t)ep * D_MODEL * D_MODEL;
    const __half* Wl = g_wl + (size_t)ep * D_MODEL * D_MODEL;

    float acc[4][4][4];
    #pragma unroll
    for (int i = 0; i < 4; i++)
        #pragma unroll
        for (int j = 0; j < 4; j++)
            #pragma unroll
            for (int l = 0; l < 4; l++) acc[i][j][l] = 0.f;

    const int r0l = tid >> 2, c0l = tid & 3;
    const int r1l = r0l + 64;
    const uint32_t d0 = swz(r0l, c0l), d1 = swz(r1l, c0l);

    auto load_stage = [&](int buf, int k0) {
        uint32_t base = sb + buf * STAGE_B;
        CP_ASYNC16(base + 0*TILE_B + d0, Xh + (size_t)(m0 + r0l)*D_MODEL + k0 + c0l*8);
        CP_ASYNC16(base + 0*TILE_B + d1, Xh + (size_t)(m0 + r1l)*D_MODEL + k0 + c0l*8);
        CP_ASYNC16(base + 1*TILE_B + d0, Wh + (size_t)(n0 + r0l)*D_MODEL + k0 + c0l*8);
        CP_ASYNC16(base + 1*TILE_B + d1, Wh + (size_t)(n0 + r1l)*D_MODEL + k0 + c0l*8);
        CP_ASYNC16(base + 2*TILE_B + d0, Wl + (size_t)(n0 + r0l)*D_MODEL + k0 + c0l*8);
        CP_ASYNC16(base + 2*TILE_B + d1, Wl + (size_t)(n0 + r1l)*D_MODEL + k0 + c0l*8);
        CP_COMMIT();
    };

    load_stage(0, 0);
    load_stage(1, 32);
    load_stage(2, 64);

    for (int kc = 0; kc < NSTG; kc++) {
        if (kc <= NSTG-3)      { CP_WAIT2(); }
        else if (kc == NSTG-2) { CP_WAIT1(); }
        else                   { CP_WAIT0(); }
        __syncthreads();                      // single barrier per stage
        if (kc + 3 < NSTG) load_stage((kc + 3) & 3, (kc + 3) * 32);

        const uint32_t base = sb + (kc & 3) * STAGE_B;
        #pragma unroll
        for (int ks = 0; ks < 2; ks++) {
            uint32_t ah[4][4], bh[2][4], bl[2][4];
            #pragma unroll
            for (int mt = 0; mt < 4; mt++) {
                const int rA = wm*64 + mt*16 + (lane & 15);
                const uint32_t offA = swz(rA, (lane >> 4) + 2*ks);
                ldsm4(ah[mt], base + 0*TILE_B + offA);
            }
            #pragma unroll
            for (int op = 0; op < 2; op++) {
                const int rB = wn*32 + op*16 + ((lane >> 4) << 3) + (lane & 7);
                const uint32_t offB = swz(rB, ((lane >> 3) & 1) + 2*ks);
                ldsm4(bh[op], base + 1*TILE_B + offB);
                ldsm4(bl[op], base + 2*TILE_B + offB);
            }
            #pragma unroll
            for (int mt = 0; mt < 4; mt++)
                #pragma unroll
                for (int nt = 0; nt < 4; nt++) {
                    const uint32_t* bhp = &bh[nt >> 1][(nt & 1) * 2];
                    const uint32_t* blp = &bl[nt >> 1][(nt & 1) * 2];
                    mma16816h(acc[mt][nt], ah[mt], bhp);
                    mma16816h(acc[mt][nt], ah[mt], blp);
                }
        }
    }
    __syncthreads();

    // ---- epilogue (acc is 32x scaled) ----
    const float INV32 = 1.f/32.f;
    const int m_base = m0 + wm*64;
    #pragma unroll
    for (int mt = 0; mt < 4; mt++) {
        #pragma unroll
        for (int nt = 0; nt < 4; nt++) {
            const int n = n0 + wn*32 + nt*8 + (lane & 3)*2;
            const float b0v = bias[n], b1v = bias[n+1];
            #pragma unroll
            for (int half = 0; half < 2; half++) {
                const int m = m_base + mt*16 + (lane >> 2) + half*8;
                float y0 = acc[mt][nt][half*2+0]*INV32 + b0v;
                float y1 = acc[mt][nt][half*2+1]*INV32 + b1v;
                if (ep <= 1) { y0 = phi_fn(y0); y1 = phi_fn(y1); }
                if (ep <= 2) {
                    const int h = n >> 6, d = n & 63;
                    const int b = m >> 11, t = m & (TSEQ-1);
                    const size_t off = ((size_t)((b*N_HEADS + h)*TSEQ + t))*DK + d;
                    __nv_bfloat16 h0,h1,l0,l1;
                    split_pair(y0,h0,l0); split_pair(y1,h1,l1);
                    __nv_bfloat162 ph{h0,h1}, pl{l0,l1};
                    __nv_bfloat16* dh = (ep == 0) ? g_qh : (ep == 1) ? g_kh : g_vh;
                    __nv_bfloat16* dl = (ep == 0) ? g_ql : (ep == 1) ? g_kl : g_vl;
                    *(__nv_bfloat162*)(dh + off) = ph;
                    *(__nv_bfloat162*)(dl + off) = pl;
                } else {
                    *(float2*)(outp + (size_t)m*D_MODEL + n) = make_float2(y0, y1);
                }
            }
        }
    }
}

__global__ __launch_bounds__(256, 2) void gemm_qkv(
    const float* __restrict__ bq, const float* __restrict__ bk,
    const float* __restrict__ bv)
{
    extern __shared__ char smem[];
    const int ep = blockIdx.z;
    const float* bias = (ep == 0) ? bq : (ep == 1) ? bk : bv;
    gemm_body(ep, g_xh, bias, nullptr, smem);
}
__global__ __launch_bounds__(256, 2) void gemm_wo(
    const float* __restrict__ bo, float* __restrict__ outp)
{
    extern __shared__ char smem[];
    gemm_body(3, g_ah, bo, outp, smem);
}

// ================= attention on tensor cores =================
#define APITCH 144
#define ATILE (128*APITCH)
#define KVTILE (DK*APITCH)

#define CKV_SMEM (4*ATILE)
__global__ __launch_bounds__(128) void chunk_kv_mma()
{
    extern __shared__ char smem[];
    const uint32_t sb = smem_to_u32(smem);
    const uint32_t SKH = 0, SKL = ATILE, SVH = 2*ATILE, SVL = 3*ATILE;
    const int blk = blockIdx.x;
    const int bh = blk >> 4, c = blk & 15;
    const int tid = threadIdx.x;
    const int lane = tid & 31, wid = tid >> 5;
    const size_t gbase = (size_t)bh*TSEQ*DK + (size_t)c*CHUNK*DK;

    #pragma unroll
    for (int it = 0; it < 8; it++) {
        int idx = tid + it*128;
        int r = idx >> 3, cc = idx & 7;
        const size_t so = gbase + (size_t)r*DK + cc*8;
        *(float4*)(smem + SKH + r*APITCH + cc*16) = *(const float4*)(g_kh + so);
        *(float4*)(smem + SKL + r*APITCH + cc*16) = *(const float4*)(g_kl + so);
        *(float4*)(smem + SVH + r*APITCH + cc*16) = *(const float4*)(g_vh + so);
        *(float4*)(smem + SVL + r*APITCH + cc*16) = *(const float4*)(g_vl + so);
    }
    // ones-extension columns 64..71 of V tiles (col 64 = 1.0 in hi, rest 0)
    {
        int r = tid;   // 0..127
        *(float4*)(smem + SVH + r*APITCH + 128) =
            make_float4(__uint_as_float(0x00003F80u), 0.f, 0.f, 0.f);
        *(float4*)(smem + SVL + r*APITCH + 128) = make_float4(0.f, 0.f, 0.f, 0.f);
    }
    __syncthreads();

    float f[8][4];
    #pragma unroll
    for (int n = 0; n < 8; n++)
        #pragma unroll
        for (int l = 0; l < 4; l++) f[n][l] = 0.f;
    float f8[4] = {0.f, 0.f, 0.f, 0.f};

    const uint32_t ka_rel = (uint32_t)(( ((lane>>4)&1)*8 + (lane&7) )*APITCH
                                       + (wid*16 + ((lane>>3)&1)*8)*2);
    const uint32_t vb_rel = (uint32_t)(( ((lane>>3)&1)*8 + (lane&7) )*APITCH
                                       + ((lane>>4)*8)*2);
    const uint32_t v2_rel = (uint32_t)(( ((lane>>3)&1)*8 + (lane&7) )*APITCH + 64*2);
    #pragma unroll
    for (int ks = 0; ks < 8; ks++) {
        const uint32_t krow = (uint32_t)(ks*16)*APITCH;
        uint32_t kah[4], kal[4], vbh[4][4], vbl[4][4], v2h[2];
        ldsm4t(kah, sb + SKH + krow + ka_rel);
        ldsm4t(kal, sb + SKL + krow + ka_rel);
        #pragma unroll
        for (int p = 0; p < 4; p++) {
            ldsm4t(vbh[p], sb + SVH + krow + vb_rel + (uint32_t)(p*16*2));
            ldsm4t(vbl[p], sb + SVL + krow + vb_rel + (uint32_t)(p*16*2));
        }
        ldsm2t(v2h, sb + SVH + krow + v2_rel);
        #pragma unroll
        for (int nt = 0; nt < 8; nt++) {
            const uint32_t* bhp = &vbh[nt>>1][(nt&1)*2];
            const uint32_t* blp = &vbl[nt>>1][(nt&1)*2];
            mma16816(f[nt], kah, bhp);
            mma16816(f[nt], kal, bhp);
            mma16816(f[nt], kah, blp);
        }
        mma16816(f8, kah, v2h);
        mma16816(f8, kal, v2h);
    }

    float* kvout = g_kv + (size_t)blk*DK*DK;
    const int d0 = wid*16 + (lane>>2);
    #pragma unroll
    for (int nt = 0; nt < 8; nt++) {
        const int e = nt*8 + (lane&3)*2;
        *(float2*)(kvout + (size_t)d0*DK + e)     = make_float2(f[nt][0], f[nt][1]);
        *(float2*)(kvout + (size_t)(d0+8)*DK + e) = make_float2(f[nt][2], f[nt][3]);
    }
    if ((lane & 3) == 0) {
        g_ksum[(size_t)blk*DK + d0]     = f8[0];
        g_ksum[(size_t)blk*DK + d0 + 8] = f8[2];
    }
}

__global__ __launch_bounds__(256) void chunk_scan_kernel()
{
    const int bh = blockIdx.x;
    const int tid = threadIdx.x;
    for (int pos = tid; pos < DK*KVE; pos += 256) {
        const int d = pos / KVE, e = pos % KVE;
        float run = 0.f;
        #pragma unroll
        for (int c = 0; c < NCHUNK; c++) {
            const size_t blk = (size_t)(bh*NCHUNK + c);
            __nv_bfloat16 h, l;
            split_pair(run, h, l);
            g_kvh[blk*DK*KVE + pos] = h;
            g_kvl[blk*DK*KVE + pos] = l;
            float val = 0.f;
            if (e < DK)       val = g_kv[blk*DK*DK + (size_t)d*DK + e];
            else if (e == DK) val = g_ksum[blk*DK + d];
            run += val;
        }
    }
}

#define ATT_SMEM (6*ATILE + 2*KVTILE)
__global__ __launch_bounds__(256) void attn_mma_kernel()
{
    extern __shared__ char smem[];
    const uint32_t sb = smem_to_u32(smem);
    const uint32_t SQH = 0, SQL = ATILE, SKH = 2*ATILE, SKL = 3*ATILE;
    const uint32_t SVH = 4*ATILE, SVL = 5*ATILE;
    const uint32_t SGH = 6*ATILE, SGL = 6*ATILE + KVTILE;

    const int blk = blockIdx.x;
    const int bh = blk >> 4, c = blk & 15;
    const int tid = threadIdx.x;
    const int lane = tid & 31, wid = tid >> 5;
    const size_t gbase = (size_t)bh*TSEQ*DK + (size_t)c*CHUNK*DK;

    #pragma unroll
    for (int it = 0; it < 4; it++) {
        int idx = tid + it*256;
        int r = idx >> 3, cc = idx & 7;
        const size_t so = gbase + (size_t)r*DK + cc*8;
        const uint32_t doff = r*APITCH + cc*16;
        *(float4*)(smem + SQH + doff) = *(const float4*)(g_qh + so);
        *(float4*)(smem + SQL + doff) = *(const float4*)(g_ql + so);
        *(float4*)(smem + SKH + doff) = *(const float4*)(g_kh + so);
        *(float4*)(smem + SKL + doff) = *(const float4*)(g_kl + so);
        *(float4*)(smem + SVH + doff) = *(const float4*)(g_vh + so);
        *(float4*)(smem + SVL + doff) = *(const float4*)(g_vl + so);
    }
    {
        const size_t kvbase = (size_t)blk*DK*KVE;
        for (int idx = tid; idx < 576; idx += 256) {
            int r = idx / 9, cc = idx % 9;
            *(float4*)(smem + SGH + r*APITCH + cc*16) = *(const float4*)(g_kvh + kvbase + (size_t)r*KVE + cc*8);
            *(float4*)(smem + SGL + r*APITCH + cc*16) = *(const float4*)(g_kvl + kvbase + (size_t)r*KVE + cc*8);
        }
    }
    __syncthreads();

    const int rbase = wid * 16;
    const uint32_t qa_rel = (uint32_t)((rbase + (lane & 15))*APITCH + (lane >> 4)*16);
    uint32_t qh[4][4], ql[4][4];
    #pragma unroll
    for (int ks = 0; ks < 4; ks++) {
        ldsm4(qh[ks], sb + SQH + qa_rel + ks*32);
        ldsm4(ql[ks], sb + SQL + qa_rel + ks*32);
    }

    float o[9][4];
    #pragma unroll
    for (int n = 0; n < 9; n++)
        #pragma unroll
        for (int l = 0; l < 4; l++) o[n][l] = 0.f;

    const uint32_t gb_rel = (uint32_t)(( ((lane>>3)&1)*8 + (lane&7) )*APITCH + ((lane>>4)*8)*2);
    #pragma unroll
    for (int ks = 0; ks < 4; ks++) {
        const uint32_t krow = (uint32_t)(ks*16)*APITCH;
        uint32_t gbh[4][4], gbl[4][4], g2h[2], g2l[2];
        #pragma unroll
        for (int p = 0; p < 4; p++) {
            ldsm4t(gbh[p], sb + SGH + krow + gb_rel + (uint32_t)(p*16*2));
            ldsm4t(gbl[p], sb + SGL + krow + gb_rel + (uint32_t)(p*16*2));
        }
        const uint32_t g2_rel = (uint32_t)(( ((lane>>3)&1)*8 + (lane&7) )*APITCH + 64*2);
        ldsm2t(g2h, sb + SGH + krow + g2_rel);
        ldsm2t(g2l, sb + SGL + krow + g2_rel);
        #pragma unroll
        for (int nt = 0; nt < 8; nt++) {
            const uint32_t* bhp = &gbh[nt>>1][(nt&1)*2];
            const uint32_t* blp = &gbl[nt>>1][(nt&1)*2];
            mma16816(o[nt], qh[ks], bhp);
            mma16816(o[nt], ql[ks], bhp);
            mma16816(o[nt], qh[ks], blp);
        }
        mma16816(o[8], qh[ks], g2h);
        mma16816(o[8], ql[ks], g2h);
        mma16816(o[8], qh[ks], g2l);
    }

    float zacc0 = 0.f, zacc1 = 0.f;
    const int row0 = rbase + (lane >> 2), row1 = row0 + 8;
    const int ncc = wid/2 + 1;
    const uint32_t kb_col = (uint32_t)(((lane>>3)&1)*16);
    const uint32_t vb_rel = (uint32_t)(( ((lane>>3)&1)*8 + (lane&7) )*APITCH + ((lane>>4)*8)*2);

    for (int cc = 0; cc < ncc; cc++) {
        const int c0 = cc*32;
        float s[4][4];
        #pragma unroll
        for (int n = 0; n < 4; n++)
            #pragma unroll
            for (int l = 0; l < 4; l++) s[n][l] = 0.f;
        #pragma unroll
        for (int ks = 0; ks < 4; ks++) {
            uint32_t kbh[2][4], kbl[2][4];
            #pragma unroll
            for (int p = 0; p < 2; p++) {
                const uint32_t kb = (uint32_t)((c0 + 16*p + ((lane>>4)<<3) + (lane&7))*APITCH)
                                    + kb_col + (uint32_t)(ks*32);
                ldsm4(kbh[p], sb + SKH + kb);
                ldsm4(kbl[p], sb + SKL + kb);
            }
            #pragma unroll
            for (int nt = 0; nt < 4; nt++) {
                const uint32_t* bhp = &kbh[nt>>1][(nt&1)*2];
                const uint32_t* blp = &kbl[nt>>1][(nt&1)*2];
                mma16816(s[nt], qh[ks], bhp);
                mma16816(s[nt], ql[ks], bhp);
                mma16816(s[nt], qh[ks], blp);
            }
        }
        uint32_t ah[2][4], al[2][4];
        #pragma unroll
        for (int nt = 0; nt < 4; nt++) {
            const int colj = c0 + nt*8 + (lane&3)*2;
            float e0 = (colj   <= row0) ? s[nt][0] : 0.f;
            float e1 = (colj+1 <= row0) ? s[nt][1] : 0.f;
            float e2 = (colj   <= row1) ? s[nt][2] : 0.f;
            float e3 = (colj+1 <= row1) ? s[nt][3] : 0.f;
            zacc0 += e0 + e1;
            zacc1 += e2 + e3;
            float h0 = __bfloat162float(__float2bfloat16(e0));
            float h1 = __bfloat162float(__float2bfloat16(e1));
            float h2 = __bfloat162float(__float2bfloat16(e2));
            float h3 = __bfloat162float(__float2bfloat16(e3));
            const int kk = nt >> 1, half = nt & 1;
            ah[kk][half*2+0] = pack_bf16(h0, h1);
            ah[kk][half*2+1] = pack_bf16(h2, h3);
            al[kk][half*2+0] = pack_bf16(e0-h0, e1-h1);
            al[kk][half*2+1] = pack_bf16(e2-h2, e3-h3);
        }
        #pragma unroll
        for (int kk = 0; kk < 2; kk++) {
            const uint32_t krow = (uint32_t)((c0 + kk*16))*APITCH;
            uint32_t vbh[4][4], vbl[4][4];
            #pragma unroll
            for (int p = 0; p < 4; p++) {
                ldsm4t(vbh[p], sb + SVH + krow + vb_rel + (uint32_t)(p*16*2));
                ldsm4t(vbl[p], sb + SVL + krow + vb_rel + (uint32_t)(p*16*2));
            }
            #pragma unroll
            for (int nt = 0; nt < 8; nt++) {
                const uint32_t* bhp = &vbh[nt>>1][(nt&1)*2];
                const uint32_t* blp = &vbl[nt>>1][(nt&1)*2];
                mma16816(o[nt], ah[kk], bhp);
                mma16816(o[nt], al[kk], bhp);
                mma16816(o[nt], ah[kk], blp);
            }
        }
    }

    float z0 = zacc0 + ((lane & 3) == 0 ? o[8][0] : 0.f);
    float z1 = zacc1 + ((lane & 3) == 0 ? o[8][2] : 0.f);
    z0 += __shfl_xor_sync(0xffffffff, z0, 1);
    z0 += __shfl_xor_sync(0xffffffff, z0, 2);
    z1 += __shfl_xor_sync(0xffffffff, z1, 1);
    z1 += __shfl_xor_sync(0xffffffff, z1, 2);
    const float inv0 = 1.f / (z0 + 1e-6f);
    const float inv1 = 1.f / (z1 + 1e-6f);

    const int b = bh >> 4, h = bh & 15;
    const size_t mbase0 = ((size_t)(b*TSEQ + c*CHUNK + row0))*D_MODEL + h*DK;
    const size_t mbase1 = ((size_t)(b*TSEQ + c*CHUNK + row1))*D_MODEL + h*DK;
    #pragma unroll
    for (int nt = 0; nt < 8; nt++) {
        const int e = nt*8 + (lane&3)*2;
        float y0 = o[nt][0]*inv0, y1 = o[nt][1]*inv0;
        float y2 = o[nt][2]*inv1, y3 = o[nt][3]*inv1;
        *(__half2*)(g_ah + mbase0 + e) = __floats2half2_rn(y0, y1);
        *(__half2*)(g_ah + mbase1 + e) = __floats2half2_rn(y2, y3);
    }
}

// ---------------- launch ----------------
extern "C" void kernel_launch(void* const* d_in, const int* in_sizes, int n_in,
                              void* d_out, int out_size)
{
    (void)in_sizes; (void)n_in; (void)out_size;
    const float* x  = (const float*)d_in[0];
    const float* Wq = (const float*)d_in[1];
    const float* bq = (const float*)d_in[2];
    const float* Wk = (const float*)d_in[3];
    const float* bk = (const float*)d_in[4];
    const float* Wv = (const float*)d_in[5];
    const float* bv = (const float*)d_in[6];
    const float* Wo = (const float*)d_in[7];
    const float* bo = (const float*)d_in[8];
    float* out = (float*)d_out;

    cudaFuncSetAttribute(gemm_qkv, cudaFuncAttributeMaxDynamicSharedMemorySize, GEMM_SMEM);
    cudaFuncSetAttribute(gemm_wo,  cudaFuncAttributeMaxDynamicSharedMemorySize, GEMM_SMEM);
    cudaFuncSetAttribute(chunk_kv_mma,    cudaFuncAttributeMaxDynamicSharedMemorySize, CKV_SMEM);
    cudaFuncSetAttribute(attn_mma_kernel, cudaFuncAttributeMaxDynamicSharedMemorySize, ATT_SMEM);

    split_x_kernel<<<(MROWS*D_MODEL/4 + 255)/256, 256>>>(x, MROWS*D_MODEL/4);
    split_w_kernel<<<(4*D_MODEL*D_MODEL/4 + 255)/256, 256>>>(Wq, Wk, Wv, Wo);

    dim3 gq(D_MODEL/128, MROWS/128, 3);   // (8, 32, 3)
    gemm_qkv<<<gq, 256, GEMM_SMEM>>>(bq, bk, bv);

    chunk_kv_mma<<<NBH*NCHUNK, 128, CKV_SMEM>>>();
    chunk_scan_kernel<<<NBH, 256>>>();
    attn_mma_kernel<<<NBH*NCHUNK, 256, ATT_SMEM>>>();

    dim3 go(D_MODEL/128, MROWS/128);      // (8, 32)
    gemm_wo<<<go, 256, GEMM_SMEM>>>(bo, out);
}

// round 9
// speedup vs baseline: 4.7055x; 1.3036x over previous
#include <cuda_runtime.h>
#include <cuda_bf16.h>
#include <cuda_fp16.h>
#include <cstdint>

#define D_MODEL 1024
#define N_HEADS 16
#define DK 64
#define BATCH 2
#define TSEQ 2048
#define MROWS (BATCH*TSEQ)   /* 4096 */
#define CHUNK 128
#define NCHUNK (TSEQ/CHUNK)  /* 16 */
#define NBH (BATCH*N_HEADS)  /* 32 */
#define KVE 72               /* KV ext cols: 64 + ksum + pad */

// ---------------- scratch (static device arrays; no allocation) ----------------
__device__ float g_kv[NBH*NCHUNK*DK*DK];
__device__ float g_ksum[NBH*NCHUNK*DK];
// fp16 GEMM operands (W pre-scaled by 32, single fp16; x and attn-out single fp16)
__device__ __half g_xh[MROWS*D_MODEL];
__device__ __half g_wh[4*D_MODEL*D_MODEL];
__device__ __half g_ah[MROWS*D_MODEL];
// bf16 hi/lo attention operands
__device__ __nv_bfloat16 g_qh[NBH*TSEQ*DK], g_ql[NBH*TSEQ*DK];
__device__ __nv_bfloat16 g_kh[NBH*TSEQ*DK], g_kl[NBH*TSEQ*DK];
__device__ __nv_bfloat16 g_vh[NBH*TSEQ*DK], g_vl[NBH*TSEQ*DK];
__device__ __nv_bfloat16 g_kvh[NBH*NCHUNK*DK*KVE];
__device__ __nv_bfloat16 g_kvl[NBH*NCHUNK*DK*KVE];

__device__ __forceinline__ float phi_fn(float x) {
    return x > 0.f ? x + 1.f : __expf(x);
}
__device__ __forceinline__ uint32_t smem_to_u32(const void* smem_ptr) {
    uint32_t addr;
    asm("{ .reg .u64 tmp; cvta.to.shared.u64 tmp, %1; cvt.u32.u64 %0, tmp; }"
        : "=r"(addr) : "l"(smem_ptr));
    return addr;
}

// ---------------- mma / ldmatrix / cp.async primitives ----------------
__device__ __forceinline__ void mma16816(float* d, const uint32_t* a, const uint32_t* b) {
    asm volatile(
        "mma.sync.aligned.m16n8k16.row.col.f32.bf16.bf16.f32 "
        "{%0,%1,%2,%3}, {%4,%5,%6,%7}, {%8,%9}, {%0,%1,%2,%3};"
        : "+f"(d[0]), "+f"(d[1]), "+f"(d[2]), "+f"(d[3])
        : "r"(a[0]), "r"(a[1]), "r"(a[2]), "r"(a[3]), "r"(b[0]), "r"(b[1]));
}
__device__ __forceinline__ void mma16816h(float* d, const uint32_t* a, const uint32_t* b) {
    asm volatile(
        "mma.sync.aligned.m16n8k16.row.col.f32.f16.f16.f32 "
        "{%0,%1,%2,%3}, {%4,%5,%6,%7}, {%8,%9}, {%0,%1,%2,%3};"
        : "+f"(d[0]), "+f"(d[1]), "+f"(d[2]), "+f"(d[3])
        : "r"(a[0]), "r"(a[1]), "r"(a[2]), "r"(a[3]), "r"(b[0]), "r"(b[1]));
}
__device__ __forceinline__ void ldsm4(uint32_t* r, uint32_t addr) {
    asm volatile("ldmatrix.sync.aligned.m8n8.x4.shared.b16 {%0,%1,%2,%3}, [%4];"
        : "=r"(r[0]), "=r"(r[1]), "=r"(r[2]), "=r"(r[3]) : "r"(addr));
}
__device__ __forceinline__ void ldsm4t(uint32_t* r, uint32_t addr) {
    asm volatile("ldmatrix.sync.aligned.m8n8.x4.trans.shared.b16 {%0,%1,%2,%3}, [%4];"
        : "=r"(r[0]), "=r"(r[1]), "=r"(r[2]), "=r"(r[3]) : "r"(addr));
}
__device__ __forceinline__ void ldsm2t(uint32_t* r, uint32_t addr) {
    asm volatile("ldmatrix.sync.aligned.m8n8.x2.trans.shared.b16 {%0,%1}, [%2];"
        : "=r"(r[0]), "=r"(r[1]) : "r"(addr));
}
#define CP_ASYNC16(dst, src) \
    asm volatile("cp.async.cg.shared.global [%0], [%1], 16;" :: "r"(dst), "l"(src))
#define CP_COMMIT() asm volatile("cp.async.commit_group;" ::: "memory")
#define CP_WAIT2()  asm volatile("cp.async.wait_group 2;" ::: "memory")
#define CP_WAIT1()  asm volatile("cp.async.wait_group 1;" ::: "memory")
#define CP_WAIT0()  asm volatile("cp.async.wait_group 0;" ::: "memory")

__device__ __forceinline__ uint32_t pack_bf16(float lo, float hi) {
    __nv_bfloat162 p = __floats2bfloat162_rn(lo, hi);
    return *reinterpret_cast<uint32_t*>(&p);
}
__device__ __forceinline__ void split_pair(float y, __nv_bfloat16& h, __nv_bfloat16& l) {
    h = __float2bfloat16(y);
    l = __float2bfloat16(y - __bfloat162float(h));
}

// ---------------- input conversions ----------------
__global__ __launch_bounds__(256) void split_x_kernel(const float* __restrict__ src, int n4)
{
    int i = blockIdx.x * 256 + threadIdx.x;
    if (i >= n4) return;
    float4 v = ((const float4*)src)[i];
    ((__half2*)(g_xh + 4*(size_t)i))[0] = __floats2half2_rn(v.x, v.y);
    ((__half2*)(g_xh + 4*(size_t)i))[1] = __floats2half2_rn(v.z, v.w);
}
__global__ __launch_bounds__(256) void split_w_kernel(
    const float* __restrict__ w0, const float* __restrict__ w1,
    const float* __restrict__ w2, const float* __restrict__ w3)
{
    const int per = D_MODEL*D_MODEL/4;
    int i = blockIdx.x * 256 + threadIdx.x;
    int sel = i >> 18, loc = i & (per - 1);
    const float* src = (sel == 0) ? w0 : (sel == 1) ? w1 : (sel == 2) ? w2 : w3;
    float4 v = ((const float4*)src)[loc];
    size_t o = (size_t)sel * D_MODEL * D_MODEL + 4*(size_t)loc;
    ((__half2*)(g_wh + o))[0] = __floats2half2_rn(v.x*32.f, v.y*32.f);
    ((__half2*)(g_wh + o))[1] = __floats2half2_rn(v.z*32.f, v.w*32.f);
}

// ---------------- fp16 1-term GEMM: 4-stage, swizzled 64B pitch, 2 CTAs/SM ----------------
#define TILE_B (128*64)             /* 8192 */
#define STAGE_B (2*TILE_B)          /* 16384: XH WH */
#define GEMM_SMEM (4*STAGE_B)       /* 65536 -> 2 CTAs/SM */
#define NSTG 32

__device__ __forceinline__ uint32_t swz(int row, int cl) {
    return (uint32_t)(row*64 + (((cl ^ ((row>>1)&3)) & 3) << 4));
}

// ep: 0=Wq->phi->q, 1=Wk->phi->k, 2=Wv->v, 3=g_ah@Wo^T->outp
__device__ __forceinline__ void gemm_body(
    int ep, const __half* __restrict__ Xh,
    const float* __restrict__ bias, float* __restrict__ outp, char* smem)
{
    const uint32_t sb = smem_to_u32(smem);
    const int tid = threadIdx.x;
    const int lane = tid & 31, wid = tid >> 5;
    const int wm = wid & 1, wn = wid >> 1;
    const int m0 = blockIdx.y * 128;
    const int n0 = blockIdx.x * 128;

    const __half* Wh = g_wh + (size_t)ep * D_MODEL * D_MODEL;

    float acc[4][4][4];
    #pragma unroll
    for (int i = 0; i < 4; i++)
        #pragma unroll
        for (int j = 0; j < 4; j++)
            #pragma unroll
            for (int l = 0; l < 4; l++) acc[i][j][l] = 0.f;

    const int r0l = tid >> 2, c0l = tid & 3;
    const int r1l = r0l + 64;
    const uint32_t d0 = swz(r0l, c0l), d1 = swz(r1l, c0l);

    auto load_stage = [&](int buf, int k0) {
        uint32_t base = sb + buf * STAGE_B;
        CP_ASYNC16(base + 0*TILE_B + d0, Xh + (size_t)(m0 + r0l)*D_MODEL + k0 + c0l*8);
        CP_ASYNC16(base + 0*TILE_B + d1, Xh + (size_t)(m0 + r1l)*D_MODEL + k0 + c0l*8);
        CP_ASYNC16(base + 1*TILE_B + d0, Wh + (size_t)(n0 + r0l)*D_MODEL + k0 + c0l*8);
        CP_ASYNC16(base + 1*TILE_B + d1, Wh + (size_t)(n0 + r1l)*D_MODEL + k0 + c0l*8);
        CP_COMMIT();
    };

    load_stage(0, 0);
    load_stage(1, 32);
    load_stage(2, 64);

    for (int kc = 0; kc < NSTG; kc++) {
        if (kc <= NSTG-3)      { CP_WAIT2(); }
        else if (kc == NSTG-2) { CP_WAIT1(); }
        else                   { CP_WAIT0(); }
        __syncthreads();
        if (kc + 3 < NSTG) load_stage((kc + 3) & 3, (kc + 3) * 32);

        const uint32_t base = sb + (kc & 3) * STAGE_B;
        #pragma unroll
        for (int ks = 0; ks < 2; ks++) {
            uint32_t ah[4][4], bh[2][4];
            #pragma unroll
            for (int mt = 0; mt < 4; mt++) {
                const int rA = wm*64 + mt*16 + (lane & 15);
                const uint32_t offA = swz(rA, (lane >> 4) + 2*ks);
                ldsm4(ah[mt], base + 0*TILE_B + offA);
            }
            #pragma unroll
            for (int op = 0; op < 2; op++) {
                const int rB = wn*32 + op*16 + ((lane >> 4) << 3) + (lane & 7);
                const uint32_t offB = swz(rB, ((lane >> 3) & 1) + 2*ks);
                ldsm4(bh[op], base + 1*TILE_B + offB);
            }
            #pragma unroll
            for (int mt = 0; mt < 4; mt++)
                #pragma unroll
                for (int nt = 0; nt < 4; nt++) {
                    const uint32_t* bhp = &bh[nt >> 1][(nt & 1) * 2];
                    mma16816h(acc[mt][nt], ah[mt], bhp);
                }
        }
    }
    __syncthreads();

    // ---- epilogue (acc is 32x scaled) ----
    const float INV32 = 1.f/32.f;
    const int m_base = m0 + wm*64;
    #pragma unroll
    for (int mt = 0; mt < 4; mt++) {
        #pragma unroll
        for (int nt = 0; nt < 4; nt++) {
            const int n = n0 + wn*32 + nt*8 + (lane & 3)*2;
            const float b0v = bias[n], b1v = bias[n+1];
            #pragma unroll
            for (int half = 0; half < 2; half++) {
                const int m = m_base + mt*16 + (lane >> 2) + half*8;
                float y0 = acc[mt][nt][half*2+0]*INV32 + b0v;
                float y1 = acc[mt][nt][half*2+1]*INV32 + b1v;
                if (ep <= 1) { y0 = phi_fn(y0); y1 = phi_fn(y1); }
                if (ep <= 2) {
                    const int h = n >> 6, d = n & 63;
                    const int b = m >> 11, t = m & (TSEQ-1);
                    const size_t off = ((size_t)((b*N_HEADS + h)*TSEQ + t))*DK + d;
                    __nv_bfloat16 h0,h1,l0,l1;
                    split_pair(y0,h0,l0); split_pair(y1,h1,l1);
                    __nv_bfloat162 ph{h0,h1}, pl{l0,l1};
                    __nv_bfloat16* dh = (ep == 0) ? g_qh : (ep == 1) ? g_kh : g_vh;
                    __nv_bfloat16* dl = (ep == 0) ? g_ql : (ep == 1) ? g_kl : g_vl;
                    *(__nv_bfloat162*)(dh + off) = ph;
                    *(__nv_bfloat162*)(dl + off) = pl;
                } else {
                    *(float2*)(outp + (size_t)m*D_MODEL + n) = make_float2(y0, y1);
                }
            }
        }
    }
}

__global__ __launch_bounds__(256, 2) void gemm_qkv(
    const float* __restrict__ bq, const float* __restrict__ bk,
    const float* __restrict__ bv)
{
    extern __shared__ char smem[];
    const int ep = blockIdx.z;
    const float* bias = (ep == 0) ? bq : (ep == 1) ? bk : bv;
    gemm_body(ep, g_xh, bias, nullptr, smem);
}
__global__ __launch_bounds__(256, 2) void gemm_wo(
    const float* __restrict__ bo, float* __restrict__ outp)
{
    extern __shared__ char smem[];
    gemm_body(3, g_ah, bo, outp, smem);
}

// ================= attention on tensor cores =================
#define APITCH 144
#define ATILE (128*APITCH)
#define KVTILE (DK*APITCH)

#define CKV_SMEM (4*ATILE)
__global__ __launch_bounds__(128) void chunk_kv_mma()
{
    extern __shared__ char smem[];
    const uint32_t sb = smem_to_u32(smem);
    const uint32_t SKH = 0, SKL = ATILE, SVH = 2*ATILE, SVL = 3*ATILE;
    const int blk = blockIdx.x;
    const int bh = blk >> 4, c = blk & 15;
    const int tid = threadIdx.x;
    const int lane = tid & 31, wid = tid >> 5;
    const size_t gbase = (size_t)bh*TSEQ*DK + (size_t)c*CHUNK*DK;

    #pragma unroll
    for (int it = 0; it < 8; it++) {
        int idx = tid + it*128;
        int r = idx >> 3, cc = idx & 7;
        const size_t so = gbase + (size_t)r*DK + cc*8;
        *(float4*)(smem + SKH + r*APITCH + cc*16) = *(const float4*)(g_kh + so);
        *(float4*)(smem + SKL + r*APITCH + cc*16) = *(const float4*)(g_kl + so);
        *(float4*)(smem + SVH + r*APITCH + cc*16) = *(const float4*)(g_vh + so);
        *(float4*)(smem + SVL + r*APITCH + cc*16) = *(const float4*)(g_vl + so);
    }
    {
        int r = tid;
        *(float4*)(smem + SVH + r*APITCH + 128) =
            make_float4(__uint_as_float(0x00003F80u), 0.f, 0.f, 0.f);
        *(float4*)(smem + SVL + r*APITCH + 128) = make_float4(0.f, 0.f, 0.f, 0.f);
    }
    __syncthreads();

    float f[8][4];
    #pragma unroll
    for (int n = 0; n < 8; n++)
        #pragma unroll
        for (int l = 0; l < 4; l++) f[n][l] = 0.f;
    float f8[4] = {0.f, 0.f, 0.f, 0.f};

    const uint32_t ka_rel = (uint32_t)(( ((lane>>4)&1)*8 + (lane&7) )*APITCH
                                       + (wid*16 + ((lane>>3)&1)*8)*2);
    const uint32_t vb_rel = (uint32_t)(( ((lane>>3)&1)*8 + (lane&7) )*APITCH
                                       + ((lane>>4)*8)*2);
    const uint32_t v2_rel = (uint32_t)(( ((lane>>3)&1)*8 + (lane&7) )*APITCH + 64*2);
    #pragma unroll
    for (int ks = 0; ks < 8; ks++) {
        const uint32_t krow = (uint32_t)(ks*16)*APITCH;
        uint32_t kah[4], kal[4], vbh[4][4], vbl[4][4], v2h[2];
        ldsm4t(kah, sb + SKH + krow + ka_rel);
        ldsm4t(kal, sb + SKL + krow + ka_rel);
        #pragma unroll
        for (int p = 0; p < 4; p++) {
            ldsm4t(vbh[p], sb + SVH + krow + vb_rel + (uint32_t)(p*16*2));
            ldsm4t(vbl[p], sb + SVL + krow + vb_rel + (uint32_t)(p*16*2));
        }
        ldsm2t(v2h, sb + SVH + krow + v2_rel);
        #pragma unroll
        for (int nt = 0; nt < 8; nt++) {
            const uint32_t* bhp = &vbh[nt>>1][(nt&1)*2];
            const uint32_t* blp = &vbl[nt>>1][(nt&1)*2];
            mma16816(f[nt], kah, bhp);
            mma16816(f[nt], kal, bhp);
            mma16816(f[nt], kah, blp);
        }
        mma16816(f8, kah, v2h);
        mma16816(f8, kal, v2h);
    }

    float* kvout = g_kv + (size_t)blk*DK*DK;
    const int d0 = wid*16 + (lane>>2);
    #pragma unroll
    for (int nt = 0; nt < 8; nt++) {
        const int e = nt*8 + (lane&3)*2;
        *(float2*)(kvout + (size_t)d0*DK + e)     = make_float2(f[nt][0], f[nt][1]);
        *(float2*)(kvout + (size_t)(d0+8)*DK + e) = make_float2(f[nt][2], f[nt][3]);
    }
    if ((lane & 3) == 0) {
        g_ksum[(size_t)blk*DK + d0]     = f8[0];
        g_ksum[(size_t)blk*DK + d0 + 8] = f8[2];
    }
}

__global__ __launch_bounds__(256) void chunk_scan_kernel()
{
    const int bh = blockIdx.x;
    const int tid = threadIdx.x;
    for (int pos = tid; pos < DK*KVE; pos += 256) {
        const int d = pos / KVE, e = pos % KVE;
        float run = 0.f;
        #pragma unroll
        for (int c = 0; c < NCHUNK; c++) {
            const size_t blk = (size_t)(bh*NCHUNK + c);
            __nv_bfloat16 h, l;
            split_pair(run, h, l);
            g_kvh[blk*DK*KVE + pos] = h;
            g_kvl[blk*DK*KVE + pos] = l;
            float val = 0.f;
            if (e < DK)       val = g_kv[blk*DK*DK + (size_t)d*DK + e];
            else if (e == DK) val = g_ksum[blk*DK + d];
            run += val;
        }
    }
}

#define ATT_SMEM (6*ATILE + 2*KVTILE)
__global__ __launch_bounds__(256) void attn_mma_kernel()
{
    extern __shared__ char smem[];
    const uint32_t sb = smem_to_u32(smem);
    const uint32_t SQH = 0, SQL = ATILE, SKH = 2*ATILE, SKL = 3*ATILE;
    const uint32_t SVH = 4*ATILE, SVL = 5*ATILE;
    const uint32_t SGH = 6*ATILE, SGL = 6*ATILE + KVTILE;

    const int blk = blockIdx.x;
    const int bh = blk >> 4, c = blk & 15;
    const int tid = threadIdx.x;
    const int lane = tid & 31, wid = tid >> 5;
    const size_t gbase = (size_t)bh*TSEQ*DK + (size_t)c*CHUNK*DK;

    #pragma unroll
    for (int it = 0; it < 4; it++) {
        int idx = tid + it*256;
        int r = idx >> 3, cc = idx & 7;
        const size_t so = gbase + (size_t)r*DK + cc*8;
        const uint32_t doff = r*APITCH + cc*16;
        *(float4*)(smem + SQH + doff) = *(const float4*)(g_qh + so);
        *(float4*)(smem + SQL + doff) = *(const float4*)(g_ql + so);
        *(float4*)(smem + SKH + doff) = *(const float4*)(g_kh + so);
        *(float4*)(smem + SKL + doff) = *(const float4*)(g_kl + so);
        *(float4*)(smem + SVH + doff) = *(const float4*)(g_vh + so);
        *(float4*)(smem + SVL + doff) = *(const float4*)(g_vl + so);
    }
    {
        const size_t kvbase = (size_t)blk*DK*KVE;
        for (int idx = tid; idx < 576; idx += 256) {
            int r = idx / 9, cc = idx % 9;
            *(float4*)(smem + SGH + r*APITCH + cc*16) = *(const float4*)(g_kvh + kvbase + (size_t)r*KVE + cc*8);
            *(float4*)(smem + SGL + r*APITCH + cc*16) = *(const float4*)(g_kvl + kvbase + (size_t)r*KVE + cc*8);
        }
    }
    __syncthreads();

    const int rbase = wid * 16;
    const uint32_t qa_rel = (uint32_t)((rbase + (lane & 15))*APITCH + (lane >> 4)*16);
    uint32_t qh[4][4], ql[4][4];
    #pragma unroll
    for (int ks = 0; ks < 4; ks++) {
        ldsm4(qh[ks], sb + SQH + qa_rel + ks*32);
        ldsm4(ql[ks], sb + SQL + qa_rel + ks*32);
    }

    float o[9][4];
    #pragma unroll
    for (int n = 0; n < 9; n++)
        #pragma unroll
        for (int l = 0; l < 4; l++) o[n][l] = 0.f;

    const uint32_t gb_rel = (uint32_t)(( ((lane>>3)&1)*8 + (lane&7) )*APITCH + ((lane>>4)*8)*2);
    #pragma unroll
    for (int ks = 0; ks < 4; ks++) {
        const uint32_t krow = (uint32_t)(ks*16)*APITCH;
        uint32_t gbh[4][4], gbl[4][4], g2h[2], g2l[2];
        #pragma unroll
        for (int p = 0; p < 4; p++) {
            ldsm4t(gbh[p], sb + SGH + krow + gb_rel + (uint32_t)(p*16*2));
            ldsm4t(gbl[p], sb + SGL + krow + gb_rel + (uint32_t)(p*16*2));
        }
        const uint32_t g2_rel = (uint32_t)(( ((lane>>3)&1)*8 + (lane&7) )*APITCH + 64*2);
        ldsm2t(g2h, sb + SGH + krow + g2_rel);
        ldsm2t(g2l, sb + SGL + krow + g2_rel);
        #pragma unroll
        for (int nt = 0; nt < 8; nt++) {
            const uint32_t* bhp = &gbh[nt>>1][(nt&1)*2];
            const uint32_t* blp = &gbl[nt>>1][(nt&1)*2];
            mma16816(o[nt], qh[ks], bhp);
            mma16816(o[nt], ql[ks], bhp);
            mma16816(o[nt], qh[ks], blp);
        }
        mma16816(o[8], qh[ks], g2h);
        mma16816(o[8], ql[ks], g2h);
        mma16816(o[8], qh[ks], g2l);
    }

    float zacc0 = 0.f, zacc1 = 0.f;
    const int row0 = rbase + (lane >> 2), row1 = row0 + 8;
    const int ncc = wid/2 + 1;
    const uint32_t kb_col = (uint32_t)(((lane>>3)&1)*16);
    const uint32_t vb_rel = (uint32_t)(( ((lane>>3)&1)*8 + (lane&7) )*APITCH + ((lane>>4)*8)*2);

    for (int cc = 0; cc < ncc; cc++) {
        const int c0 = cc*32;
        float s[4][4];
        #pragma unroll
        for (int n = 0; n < 4; n++)
            #pragma unroll
            for (int l = 0; l < 4; l++) s[n][l] = 0.f;
        #pragma unroll
        for (int ks = 0; ks < 4; ks++) {
            uint32_t kbh[2][4], kbl[2][4];
            #pragma unroll
            for (int p = 0; p < 2; p++) {
                const uint32_t kb = (uint32_t)((c0 + 16*p + ((lane>>4)<<3) + (lane&7))*APITCH)
                                    + kb_col + (uint32_t)(ks*32);
                ldsm4(kbh[p], sb + SKH + kb);
                ldsm4(kbl[p], sb + SKL + kb);
            }
            #pragma unroll
            for (int nt = 0; nt < 4; nt++) {
                const uint32_t* bhp = &kbh[nt>>1][(nt&1)*2];
                const uint32_t* blp = &kbl[nt>>1][(nt&1)*2];
                mma16816(s[nt], qh[ks], bhp);
                mma16816(s[nt], ql[ks], bhp);
                mma16816(s[nt], qh[ks], blp);
            }
        }
        uint32_t ah[2][4], al[2][4];
        #pragma unroll
        for (int nt = 0; nt < 4; nt++) {
            const int colj = c0 + nt*8 + (lane&3)*2;
            float e0 = (colj   <= row0) ? s[nt][0] : 0.f;
            float e1 = (colj+1 <= row0) ? s[nt][1] : 0.f;
            float e2 = (colj   <= row1) ? s[nt][2] : 0.f;
            float e3 = (colj+1 <= row1) ? s[nt][3] : 0.f;
            zacc0 += e0 + e1;
            zacc1 += e2 + e3;
            float h0 = __bfloat162float(__float2bfloat16(e0));
            float h1 = __bfloat162float(__float2bfloat16(e1));
            float h2 = __bfloat162float(__float2bfloat16(e2));
            float h3 = __bfloat162float(__float2bfloat16(e3));
            const int kk = nt >> 1, half = nt & 1;
            ah[kk][half*2+0] = pack_bf16(h0, h1);
            ah[kk][half*2+1] = pack_bf16(h2, h3);
            al[kk][half*2+0] = pack_bf16(e0-h0, e1-h1);
            al[kk][half*2+1] = pack_bf16(e2-h2, e3-h3);
        }
        #pragma unroll
        for (int kk = 0; kk < 2; kk++) {
            const uint32_t krow = (uint32_t)((c0 + kk*16))*APITCH;
            uint32_t vbh[4][4], vbl[4][4];
            #pragma unroll
            for (int p = 0; p < 4; p++) {
                ldsm4t(vbh[p], sb + SVH + krow + vb_rel + (uint32_t)(p*16*2));
                ldsm4t(vbl[p], sb + SVL + krow + vb_rel + (uint32_t)(p*16*2));
            }
            #pragma unroll
            for (int nt = 0; nt < 8; nt++) {
                const uint32_t* bhp = &vbh[nt>>1][(nt&1)*2];
                const uint32_t* blp = &vbl[nt>>1][(nt&1)*2];
                mma16816(o[nt], ah[kk], bhp);
                mma16816(o[nt], al[kk], bhp);
                mma16816(o[nt], ah[kk], blp);
            }
        }
    }

    float z0 = zacc0 + ((lane & 3) == 0 ? o[8][0] : 0.f);
    float z1 = zacc1 + ((lane & 3) == 0 ? o[8][2] : 0.f);
    z0 += __shfl_xor_sync(0xffffffff, z0, 1);
    z0 += __shfl_xor_sync(0xffffffff, z0, 2);
    z1 += __shfl_xor_sync(0xffffffff, z1, 1);
    z1 += __shfl_xor_sync(0xffffffff, z1, 2);
    const float inv0 = 1.f / (z0 + 1e-6f);
    const float inv1 = 1.f / (z1 + 1e-6f);

    const int b = bh >> 4, h = bh & 15;
    const size_t mbase0 = ((size_t)(b*TSEQ + c*CHUNK + row0))*D_MODEL + h*DK;
    const size_t mbase1 = ((size_t)(b*TSEQ + c*CHUNK + row1))*D_MODEL + h*DK;
    #pragma unroll
    for (int nt = 0; nt < 8; nt++) {
        const int e = nt*8 + (lane&3)*2;
        float y0 = o[nt][0]*inv0, y1 = o[nt][1]*inv0;
        float y2 = o[nt][2]*inv1, y3 = o[nt][3]*inv1;
        *(__half2*)(g_ah + mbase0 + e) = __floats2half2_rn(y0, y1);
        *(__half2*)(g_ah + mbase1 + e) = __floats2half2_rn(y2, y3);
    }
}

// ---------------- launch ----------------
extern "C" void kernel_launch(void* const* d_in, const int* in_sizes, int n_in,
                              void* d_out, int out_size)
{
    (void)in_sizes; (void)n_in; (void)out_size;
    const float* x  = (const float*)d_in[0];
    const float* Wq = (const float*)d_in[1];
    const float* bq = (const float*)d_in[2];
    const float* Wk = (const float*)d_in[3];
    const float* bk = (const float*)d_in[4];
    const float* Wv = (const float*)d_in[5];
    const float* bv = (const float*)d_in[6];
    const float* Wo = (const float*)d_in[7];
    const float* bo = (const float*)d_in[8];
    float* out = (float*)d_out;

    cudaFuncSetAttribute(gemm_qkv, cudaFuncAttributeMaxDynamicSharedMemorySize, GEMM_SMEM);
    cudaFuncSetAttribute(gemm_wo,  cudaFuncAttributeMaxDynamicSharedMemorySize, GEMM_SMEM);
    cudaFuncSetAttribute(chunk_kv_mma,    cudaFuncAttributeMaxDynamicSharedMemorySize, CKV_SMEM);
    cudaFuncSetAttribute(attn_mma_kernel, cudaFuncAttributeMaxDynamicSharedMemorySize, ATT_SMEM);

    split_x_kernel<<<(MROWS*D_MODEL/4 + 255)/256, 256>>>(x, MROWS*D_MODEL/4);
    split_w_kernel<<<(4*D_MODEL*D_MODEL/4 + 255)/256, 256>>>(Wq, Wk, Wv, Wo);

    dim3 gq(D_MODEL/128, MROWS/128, 3);   // (8, 32, 3)
    gemm_qkv<<<gq, 256, GEMM_SMEM>>>(bq, bk, bv);

    chunk_kv_mma<<<NBH*NCHUNK, 128, CKV_SMEM>>>();
    chunk_scan_kernel<<<NBH, 256>>>();
    attn_mma_kernel<<<NBH*NCHUNK, 256, ATT_SMEM>>>();

    dim3 go(D_MODEL/128, MROWS/128);      // (8, 32)
    gemm_wo<<<go, 256, GEMM_SMEM>>>(bo, out);
}

// round 10
// speedup vs baseline: 5.0542x; 1.0741x over previous
#include <cuda_runtime.h>
#include <cuda_bf16.h>
#include <cuda_fp16.h>
#include <cstdint>

#define D_MODEL 1024
#define N_HEADS 16
#define DK 64
#define BATCH 2
#define TSEQ 2048
#define MROWS (BATCH*TSEQ)   /* 4096 */
#define CHUNK 128
#define NCHUNK (TSEQ/CHUNK)  /* 16 */
#define NBH (BATCH*N_HEADS)  /* 32 */
#define KVE 72               /* KV ext cols: 64 + ksum + pad */

// ---------------- scratch (static device arrays; no allocation) ----------------
__device__ float g_kv[NBH*NCHUNK*DK*DK];
__device__ float g_ksum[NBH*NCHUNK*DK];
// fp16 GEMM operands (W pre-scaled by 32)
__device__ __half g_xh[MROWS*D_MODEL];
__device__ __half g_wh[4*D_MODEL*D_MODEL];
__device__ __half g_ah[MROWS*D_MODEL];
// fp16 attention operands
__device__ __half g_qf[NBH*TSEQ*DK];
__device__ __half g_kf[NBH*TSEQ*DK];
__device__ __half g_vh[NBH*TSEQ*DK], g_vl[NBH*TSEQ*DK];
__device__ __half g_kvh[NBH*NCHUNK*DK*KVE];
__device__ __half g_kvl[NBH*NCHUNK*DK*KVE];

__device__ __forceinline__ float phi_fn(float x) {
    return x > 0.f ? x + 1.f : __expf(x);
}
__device__ __forceinline__ uint32_t smem_to_u32(const void* smem_ptr) {
    uint32_t addr;
    asm("{ .reg .u64 tmp; cvta.to.shared.u64 tmp, %1; cvt.u32.u64 %0, tmp; }"
        : "=r"(addr) : "l"(smem_ptr));
    return addr;
}

// ---------------- mma / ldmatrix / cp.async primitives ----------------
__device__ __forceinline__ void mma16816h(float* d, const uint32_t* a, const uint32_t* b) {
    asm volatile(
        "mma.sync.aligned.m16n8k16.row.col.f32.f16.f16.f32 "
        "{%0,%1,%2,%3}, {%4,%5,%6,%7}, {%8,%9}, {%0,%1,%2,%3};"
        : "+f"(d[0]), "+f"(d[1]), "+f"(d[2]), "+f"(d[3])
        : "r"(a[0]), "r"(a[1]), "r"(a[2]), "r"(a[3]), "r"(b[0]), "r"(b[1]));
}
__device__ __forceinline__ void ldsm4(uint32_t* r, uint32_t addr) {
    asm volatile("ldmatrix.sync.aligned.m8n8.x4.shared.b16 {%0,%1,%2,%3}, [%4];"
        : "=r"(r[0]), "=r"(r[1]), "=r"(r[2]), "=r"(r[3]) : "r"(addr));
}
__device__ __forceinline__ void ldsm4t(uint32_t* r, uint32_t addr) {
    asm volatile("ldmatrix.sync.aligned.m8n8.x4.trans.shared.b16 {%0,%1,%2,%3}, [%4];"
        : "=r"(r[0]), "=r"(r[1]), "=r"(r[2]), "=r"(r[3]) : "r"(addr));
}
__device__ __forceinline__ void ldsm2t(uint32_t* r, uint32_t addr) {
    asm volatile("ldmatrix.sync.aligned.m8n8.x2.trans.shared.b16 {%0,%1}, [%2];"
        : "=r"(r[0]), "=r"(r[1]) : "r"(addr));
}
#define CP_ASYNC16(dst, src) \
    asm volatile("cp.async.cg.shared.global [%0], [%1], 16;" :: "r"(dst), "l"(src))
#define CP_COMMIT() asm volatile("cp.async.commit_group;" ::: "memory")
#define CP_WAIT2()  asm volatile("cp.async.wait_group 2;" ::: "memory")
#define CP_WAIT1()  asm volatile("cp.async.wait_group 1;" ::: "memory")
#define CP_WAIT0()  asm volatile("cp.async.wait_group 0;" ::: "memory")

__device__ __forceinline__ uint32_t pack_h(float a, float b) {
    __half2 p = __floats2half2_rn(a, b);
    return *reinterpret_cast<uint32_t*>(&p);
}
__device__ __forceinline__ void split_pair_h(float y, __half& h, __half& l) {
    h = __float2half(y);
    l = __float2half(y - __half2float(h));
}

// ---------------- input conversions ----------------
__global__ __launch_bounds__(256) void split_x_kernel(const float* __restrict__ src, int n4)
{
    int i = blockIdx.x * 256 + threadIdx.x;
    if (i >= n4) return;
    float4 v = ((const float4*)src)[i];
    ((__half2*)(g_xh + 4*(size_t)i))[0] = __floats2half2_rn(v.x, v.y);
    ((__half2*)(g_xh + 4*(size_t)i))[1] = __floats2half2_rn(v.z, v.w);
}
__global__ __launch_bounds__(256) void split_w_kernel(
    const float* __restrict__ w0, const float* __restrict__ w1,
    const float* __restrict__ w2, const float* __restrict__ w3)
{
    const int per = D_MODEL*D_MODEL/4;
    int i = blockIdx.x * 256 + threadIdx.x;
    int sel = i >> 18, loc = i & (per - 1);
    const float* src = (sel == 0) ? w0 : (sel == 1) ? w1 : (sel == 2) ? w2 : w3;
    float4 v = ((const float4*)src)[loc];
    size_t o = (size_t)sel * D_MODEL * D_MODEL + 4*(size_t)loc;
    ((__half2*)(g_wh + o))[0] = __floats2half2_rn(v.x*32.f, v.y*32.f);
    ((__half2*)(g_wh + o))[1] = __floats2half2_rn(v.z*32.f, v.w*32.f);
}

// ---------------- fp16 1-term GEMM: 4-stage, swizzled 64B pitch, 2 CTAs/SM ----------------
#define TILE_B (128*64)             /* 8192 */
#define STAGE_B (2*TILE_B)          /* 16384: XH WH */
#define GEMM_SMEM (4*STAGE_B)       /* 65536 -> 2 CTAs/SM */
#define NSTG 32

__device__ __forceinline__ uint32_t swz(int row, int cl) {
    return (uint32_t)(row*64 + (((cl ^ ((row>>1)&3)) & 3) << 4));
}

// ep: 0=Wq->phi->q, 1=Wk->phi->k, 2=Wv->v, 3=g_ah@Wo^T->outp
__device__ __forceinline__ void gemm_body(
    int ep, const __half* __restrict__ Xh,
    const float* __restrict__ bias, float* __restrict__ outp, char* smem)
{
    const uint32_t sb = smem_to_u32(smem);
    const int tid = threadIdx.x;
    const int lane = tid & 31, wid = tid >> 5;
    const int wm = wid & 1, wn = wid >> 1;
    const int m0 = blockIdx.y * 128;
    const int n0 = blockIdx.x * 128;

    const __half* Wh = g_wh + (size_t)ep * D_MODEL * D_MODEL;

    float acc[4][4][4];
    #pragma unroll
    for (int i = 0; i < 4; i++)
        #pragma unroll
        for (int j = 0; j < 4; j++)
            #pragma unroll
            for (int l = 0; l < 4; l++) acc[i][j][l] = 0.f;

    const int r0l = tid >> 2, c0l = tid & 3;
    const int r1l = r0l + 64;
    const uint32_t d0 = swz(r0l, c0l), d1 = swz(r1l, c0l);

    auto load_stage = [&](int buf, int k0) {
        uint32_t base = sb + buf * STAGE_B;
        CP_ASYNC16(base + 0*TILE_B + d0, Xh + (size_t)(m0 + r0l)*D_MODEL + k0 + c0l*8);
        CP_ASYNC16(base + 0*TILE_B + d1, Xh + (size_t)(m0 + r1l)*D_MODEL + k0 + c0l*8);
        CP_ASYNC16(base + 1*TILE_B + d0, Wh + (size_t)(n0 + r0l)*D_MODEL + k0 + c0l*8);
        CP_ASYNC16(base + 1*TILE_B + d1, Wh + (size_t)(n0 + r1l)*D_MODEL + k0 + c0l*8);
        CP_COMMIT();
    };

    load_stage(0, 0);
    load_stage(1, 32);
    load_stage(2, 64);

    for (int kc = 0; kc < NSTG; kc++) {
        if (kc <= NSTG-3)      { CP_WAIT2(); }
        else if (kc == NSTG-2) { CP_WAIT1(); }
        else                   { CP_WAIT0(); }
        __syncthreads();
        if (kc + 3 < NSTG) load_stage((kc + 3) & 3, (kc + 3) * 32);

        const uint32_t base = sb + (kc & 3) * STAGE_B;
        #pragma unroll
        for (int ks = 0; ks < 2; ks++) {
            uint32_t ah[4][4], bh[2][4];
            #pragma unroll
            for (int mt = 0; mt < 4; mt++) {
                const int rA = wm*64 + mt*16 + (lane & 15);
                const uint32_t offA = swz(rA, (lane >> 4) + 2*ks);
                ldsm4(ah[mt], base + 0*TILE_B + offA);
            }
            #pragma unroll
            for (int op = 0; op < 2; op++) {
                const int rB = wn*32 + op*16 + ((lane >> 4) << 3) + (lane & 7);
                const uint32_t offB = swz(rB, ((lane >> 3) & 1) + 2*ks);
                ldsm4(bh[op], base + 1*TILE_B + offB);
            }
            #pragma unroll
            for (int mt = 0; mt < 4; mt++)
                #pragma unroll
                for (int nt = 0; nt < 4; nt++) {
                    const uint32_t* bhp = &bh[nt >> 1][(nt & 1) * 2];
                    mma16816h(acc[mt][nt], ah[mt], bhp);
                }
        }
    }
    __syncthreads();

    // ---- epilogue (acc is 32x scaled) ----
    const float INV32 = 1.f/32.f;
    const int m_base = m0 + wm*64;
    #pragma unroll
    for (int mt = 0; mt < 4; mt++) {
        #pragma unroll
        for (int nt = 0; nt < 4; nt++) {
            const int n = n0 + wn*32 + nt*8 + (lane & 3)*2;
            const float b0v = bias[n], b1v = bias[n+1];
            #pragma unroll
            for (int half = 0; half < 2; half++) {
                const int m = m_base + mt*16 + (lane >> 2) + half*8;
                float y0 = acc[mt][nt][half*2+0]*INV32 + b0v;
                float y1 = acc[mt][nt][half*2+1]*INV32 + b1v;
                if (ep <= 1) { y0 = phi_fn(y0); y1 = phi_fn(y1); }
                if (ep <= 2) {
                    const int h = n >> 6, d = n & 63;
                    const int b = m >> 11, t = m & (TSEQ-1);
                    const size_t off = ((size_t)((b*N_HEADS + h)*TSEQ + t))*DK + d;
                    if (ep == 0) {
                        *(__half2*)(g_qf + off) = __floats2half2_rn(y0, y1);
                    } else if (ep == 1) {
                        *(__half2*)(g_kf + off) = __floats2half2_rn(y0, y1);
                    } else {
                        __half h0,h1,l0,l1;
                        split_pair_h(y0,h0,l0); split_pair_h(y1,h1,l1);
                        __half2 ph{h0,h1}, pl{l0,l1};
                        *(__half2*)(g_vh + off) = ph;
                        *(__half2*)(g_vl + off) = pl;
                    }
                } else {
                    *(float2*)(outp + (size_t)m*D_MODEL + n) = make_float2(y0, y1);
                }
            }
        }
    }
}

__global__ __launch_bounds__(256, 2) void gemm_qkv(
    const float* __restrict__ bq, const float* __restrict__ bk,
    const float* __restrict__ bv)
{
    extern __shared__ char smem[];
    const int ep = blockIdx.z;
    const float* bias = (ep == 0) ? bq : (ep == 1) ? bk : bv;
    gemm_body(ep, g_xh, bias, nullptr, smem);
}
__global__ __launch_bounds__(256, 2) void gemm_wo(
    const float* __restrict__ bo, float* __restrict__ outp)
{
    extern __shared__ char smem[];
    gemm_body(3, g_ah, bo, outp, smem);
}

// ================= attention on tensor cores (fp16) =================
#define APITCH 144
#define ATILE (128*APITCH)
#define KVTILE (DK*APITCH)

// ---------------- per-chunk K^T V and k-sum ----------------
#define CKV_SMEM (3*ATILE)          /* K, Vh, Vl = 55296 */
__global__ __launch_bounds__(128) void chunk_kv_mma()
{
    extern __shared__ char smem[];
    const uint32_t sb = smem_to_u32(smem);
    const uint32_t SK = 0, SVH = ATILE, SVL = 2*ATILE;
    const int blk = blockIdx.x;
    const int bh = blk >> 4, c = blk & 15;
    const int tid = threadIdx.x;
    const int lane = tid & 31, wid = tid >> 5;
    const size_t gbase = (size_t)bh*TSEQ*DK + (size_t)c*CHUNK*DK;

    #pragma unroll
    for (int it = 0; it < 8; it++) {
        int idx = tid + it*128;
        int r = idx >> 3, cc = idx & 7;
        const size_t so = gbase + (size_t)r*DK + cc*8;
        *(float4*)(smem + SK  + r*APITCH + cc*16) = *(const float4*)(g_kf + so);
        *(float4*)(smem + SVH + r*APITCH + cc*16) = *(const float4*)(g_vh + so);
        *(float4*)(smem + SVL + r*APITCH + cc*16) = *(const float4*)(g_vl + so);
    }
    // ones-extension columns 64..71 of V tiles (col 64 = fp16 1.0 in hi, rest 0)
    {
        int r = tid;
        *(float4*)(smem + SVH + r*APITCH + 128) =
            make_float4(__uint_as_float(0x00003C00u), 0.f, 0.f, 0.f);
        *(float4*)(smem + SVL + r*APITCH + 128) = make_float4(0.f, 0.f, 0.f, 0.f);
    }
    __syncthreads();

    float f[8][4];
    #pragma unroll
    for (int n = 0; n < 8; n++)
        #pragma unroll
        for (int l = 0; l < 4; l++) f[n][l] = 0.f;
    float f8[4] = {0.f, 0.f, 0.f, 0.f};

    const uint32_t ka_rel = (uint32_t)(( ((lane>>4)&1)*8 + (lane&7) )*APITCH
                                       + (wid*16 + ((lane>>3)&1)*8)*2);
    const uint32_t vb_rel = (uint32_t)(( ((lane>>3)&1)*8 + (lane&7) )*APITCH
                                       + ((lane>>4)*8)*2);
    const uint32_t v2_rel = (uint32_t)(( ((lane>>3)&1)*8 + (lane&7) )*APITCH + 64*2);
    #pragma unroll
    for (int ks = 0; ks < 8; ks++) {
        const uint32_t krow = (uint32_t)(ks*16)*APITCH;
        uint32_t kah[4], vbh[4][4], vbl[4][4], v2h[2];
        ldsm4t(kah, sb + SK + krow + ka_rel);
        #pragma unroll
        for (int p = 0; p < 4; p++) {
            ldsm4t(vbh[p], sb + SVH + krow + vb_rel + (uint32_t)(p*16*2));
            ldsm4t(vbl[p], sb + SVL + krow + vb_rel + (uint32_t)(p*16*2));
        }
        ldsm2t(v2h, sb + SVH + krow + v2_rel);
        #pragma unroll
        for (int nt = 0; nt < 8; nt++) {
            const uint32_t* bhp = &vbh[nt>>1][(nt&1)*2];
            const uint32_t* blp = &vbl[nt>>1][(nt&1)*2];
            mma16816h(f[nt], kah, bhp);
            mma16816h(f[nt], kah, blp);
        }
        mma16816h(f8, kah, v2h);
    }

    float* kvout = g_kv + (size_t)blk*DK*DK;
    const int d0 = wid*16 + (lane>>2);
    #pragma unroll
    for (int nt = 0; nt < 8; nt++) {
        const int e = nt*8 + (lane&3)*2;
        *(float2*)(kvout + (size_t)d0*DK + e)     = make_float2(f[nt][0], f[nt][1]);
        *(float2*)(kvout + (size_t)(d0+8)*DK + e) = make_float2(f[nt][2], f[nt][3]);
    }
    if ((lane & 3) == 0) {
        g_ksum[(size_t)blk*DK + d0]     = f8[0];
        g_ksum[(size_t)blk*DK + d0 + 8] = f8[2];
    }
}

// ---------------- exclusive prefix scan -> fp16 hi/lo ext [d][72] ----------------
__global__ __launch_bounds__(256) void chunk_scan_kernel()
{
    const int bh = blockIdx.x;
    const int tid = threadIdx.x;
    for (int pos = tid; pos < DK*KVE; pos += 256) {
        const int d = pos / KVE, e = pos % KVE;
        float run = 0.f;
        #pragma unroll
        for (int c = 0; c < NCHUNK; c++) {
            const size_t blk = (size_t)(bh*NCHUNK + c);
            __half h, l;
            split_pair_h(run, h, l);
            g_kvh[blk*DK*KVE + pos] = h;
            g_kvl[blk*DK*KVE + pos] = l;
            float val = 0.f;
            if (e < DK)       val = g_kv[blk*DK*DK + (size_t)d*DK + e];
            else if (e == DK) val = g_ksum[blk*DK + d];
            run += val;
        }
    }
}

// ---------------- per-chunk attention (fp16, causal) ----------------
#define ATT_SMEM (4*ATILE + 2*KVTILE)   /* 92160 */
__global__ __launch_bounds__(256) void attn_mma_kernel()
{
    extern __shared__ char smem[];
    const uint32_t sb = smem_to_u32(smem);
    const uint32_t SQ = 0, SK = ATILE, SVH = 2*ATILE, SVL = 3*ATILE;
    const uint32_t SGH = 4*ATILE, SGL = 4*ATILE + KVTILE;

    const int blk = blockIdx.x;
    const int bh = blk >> 4, c = blk & 15;
    const int tid = threadIdx.x;
    const int lane = tid & 31, wid = tid >> 5;
    const size_t gbase = (size_t)bh*TSEQ*DK + (size_t)c*CHUNK*DK;

    #pragma unroll
    for (int it = 0; it < 4; it++) {
        int idx = tid + it*256;
        int r = idx >> 3, cc = idx & 7;
        const size_t so = gbase + (size_t)r*DK + cc*8;
        const uint32_t doff = r*APITCH + cc*16;
        *(float4*)(smem + SQ  + doff) = *(const float4*)(g_qf + so);
        *(float4*)(smem + SK  + doff) = *(const float4*)(g_kf + so);
        *(float4*)(smem + SVH + doff) = *(const float4*)(g_vh + so);
        *(float4*)(smem + SVL + doff) = *(const float4*)(g_vl + so);
    }
    {
        const size_t kvbase = (size_t)blk*DK*KVE;
        for (int idx = tid; idx < 576; idx += 256) {
            int r = idx / 9, cc = idx % 9;
            *(float4*)(smem + SGH + r*APITCH + cc*16) = *(const float4*)(g_kvh + kvbase + (size_t)r*KVE + cc*8);
            *(float4*)(smem + SGL + r*APITCH + cc*16) = *(const float4*)(g_kvl + kvbase + (size_t)r*KVE + cc*8);
        }
    }
    __syncthreads();

    const int rbase = wid * 16;
    const uint32_t qa_rel = (uint32_t)((rbase + (lane & 15))*APITCH + (lane >> 4)*16);
    uint32_t qa[4][4];
    #pragma unroll
    for (int ks = 0; ks < 4; ks++)
        ldsm4(qa[ks], sb + SQ + qa_rel + ks*32);

    float o[9][4];
    #pragma unroll
    for (int n = 0; n < 9; n++)
        #pragma unroll
        for (int l = 0; l < 4; l++) o[n][l] = 0.f;

    // ---- inter-chunk: o += q @ KV_prev (fp16 hi/lo, 2 terms) ----
    const uint32_t gb_rel = (uint32_t)(( ((lane>>3)&1)*8 + (lane&7) )*APITCH + ((lane>>4)*8)*2);
    #pragma unroll
    for (int ks = 0; ks < 4; ks++) {
        const uint32_t krow = (uint32_t)(ks*16)*APITCH;
        uint32_t gbh[4][4], gbl[4][4], g2h[2], g2l[2];
        #pragma unroll
        for (int p = 0; p < 4; p++) {
            ldsm4t(gbh[p], sb + SGH + krow + gb_rel + (uint32_t)(p*16*2));
            ldsm4t(gbl[p], sb + SGL + krow + gb_rel + (uint32_t)(p*16*2));
        }
        const uint32_t g2_rel = (uint32_t)(( ((lane>>3)&1)*8 + (lane&7) )*APITCH + 64*2);
        ldsm2t(g2h, sb + SGH + krow + g2_rel);
        ldsm2t(g2l, sb + SGL + krow + g2_rel);
        #pragma unroll
        for (int nt = 0; nt < 8; nt++) {
            const uint32_t* bhp = &gbh[nt>>1][(nt&1)*2];
            const uint32_t* blp = &gbl[nt>>1][(nt&1)*2];
            mma16816h(o[nt], qa[ks], bhp);
            mma16816h(o[nt], qa[ks], blp);
        }
        mma16816h(o[8], qa[ks], g2h);
        mma16816h(o[8], qa[ks], g2l);
    }

    // ---- intra-chunk causal ----
    float zacc0 = 0.f, zacc1 = 0.f;
    const int row0 = rbase + (lane >> 2), row1 = row0 + 8;
    const int ncc = wid/2 + 1;
    const uint32_t kb_col = (uint32_t)(((lane>>3)&1)*16);
    const uint32_t vb_rel = (uint32_t)(( ((lane>>3)&1)*8 + (lane&7) )*APITCH + ((lane>>4)*8)*2);

    for (int cc = 0; cc < ncc; cc++) {
        const int c0 = cc*32;
        float s[4][4];
        #pragma unroll
        for (int n = 0; n < 4; n++)
            #pragma unroll
            for (int l = 0; l < 4; l++) s[n][l] = 0.f;
        #pragma unroll
        for (int ks = 0; ks < 4; ks++) {
            uint32_t kb[2][4];
            #pragma unroll
            for (int p = 0; p < 2; p++) {
                const uint32_t kbo = (uint32_t)((c0 + 16*p + ((lane>>4)<<3) + (lane&7))*APITCH)
                                     + kb_col + (uint32_t)(ks*32);
                ldsm4(kb[p], sb + SK + kbo);
            }
            #pragma unroll
            for (int nt = 0; nt < 4; nt++) {
                const uint32_t* bp = &kb[nt>>1][(nt&1)*2];
                mma16816h(s[nt], qa[ks], bp);
            }
        }
        // mask, z, convert S -> fp16 A-frags
        uint32_t af[2][4];
        #pragma unroll
        for (int nt = 0; nt < 4; nt++) {
            const int colj = c0 + nt*8 + (lane&3)*2;
            float e0 = (colj   <= row0) ? s[nt][0] : 0.f;
            float e1 = (colj+1 <= row0) ? s[nt][1] : 0.f;
            float e2 = (colj   <= row1) ? s[nt][2] : 0.f;
            float e3 = (colj+1 <= row1) ? s[nt][3] : 0.f;
            zacc0 += e0 + e1;
            zacc1 += e2 + e3;
            const int kk = nt >> 1, half = nt & 1;
            af[kk][half*2+0] = pack_h(e0, e1);
            af[kk][half*2+1] = pack_h(e2, e3);
        }
        // o += S @ V (fp16 hi/lo, 2 terms)
        #pragma unroll
        for (int kk = 0; kk < 2; kk++) {
            const uint32_t krow = (uint32_t)((c0 + kk*16))*APITCH;
            uint32_t vbh[4][4], vbl[4][4];
            #pragma unroll
            for (int p = 0; p < 4; p++) {
                ldsm4t(vbh[p], sb + SVH + krow + vb_rel + (uint32_t)(p*16*2));
                ldsm4t(vbl[p], sb + SVL + krow + vb_rel + (uint32_t)(p*16*2));
            }
            #pragma unroll
            for (int nt = 0; nt < 8; nt++) {
                const uint32_t* bhp = &vbh[nt>>1][(nt&1)*2];
                const uint32_t* blp = &vbl[nt>>1][(nt&1)*2];
                mma16816h(o[nt], af[kk], bhp);
                mma16816h(o[nt], af[kk], blp);
            }
        }
    }

    float z0 = zacc0 + ((lane & 3) == 0 ? o[8][0] : 0.f);
    float z1 = zacc1 + ((lane & 3) == 0 ? o[8][2] : 0.f);
    z0 += __shfl_xor_sync(0xffffffff, z0, 1);
    z0 += __shfl_xor_sync(0xffffffff, z0, 2);
    z1 += __shfl_xor_sync(0xffffffff, z1, 1);
    z1 += __shfl_xor_sync(0xffffffff, z1, 2);
    const float inv0 = 1.f / (z0 + 1e-6f);
    const float inv1 = 1.f / (z1 + 1e-6f);

    const int b = bh >> 4, h = bh & 15;
    const size_t mbase0 = ((size_t)(b*TSEQ + c*CHUNK + row0))*D_MODEL + h*DK;
    const size_t mbase1 = ((size_t)(b*TSEQ + c*CHUNK + row1))*D_MODEL + h*DK;
    #pragma unroll
    for (int nt = 0; nt < 8; nt++) {
        const int e = nt*8 + (lane&3)*2;
        float y0 = o[nt][0]*inv0, y1 = o[nt][1]*inv0;
        float y2 = o[nt][2]*inv1, y3 = o[nt][3]*inv1;
        *(__half2*)(g_ah + mbase0 + e) = __floats2half2_rn(y0, y1);
        *(__half2*)(g_ah + mbase1 + e) = __floats2half2_rn(y2, y3);
    }
}

// ---------------- launch ----------------
extern "C" void kernel_launch(void* const* d_in, const int* in_sizes, int n_in,
                              void* d_out, int out_size)
{
    (void)in_sizes; (void)n_in; (void)out_size;
    const float* x  = (const float*)d_in[0];
    const float* Wq = (const float*)d_in[1];
    const float* bq = (const float*)d_in[2];
    const float* Wk = (const float*)d_in[3];
    const float* bk = (const float*)d_in[4];
    const float* Wv = (const float*)d_in[5];
    const float* bv = (const float*)d_in[6];
    const float* Wo = (const float*)d_in[7];
    const float* bo = (const float*)d_in[8];
    float* out = (float*)d_out;

    cudaFuncSetAttribute(gemm_qkv, cudaFuncAttributeMaxDynamicSharedMemorySize, GEMM_SMEM);
    cudaFuncSetAttribute(gemm_wo,  cudaFuncAttributeMaxDynamicSharedMemorySize, GEMM_SMEM);
    cudaFuncSetAttribute(chunk_kv_mma,    cudaFuncAttributeMaxDynamicSharedMemorySize, CKV_SMEM);
    cudaFuncSetAttribute(attn_mma_kernel, cudaFuncAttributeMaxDynamicSharedMemorySize, ATT_SMEM);

    split_x_kernel<<<(MROWS*D_MODEL/4 + 255)/256, 256>>>(x, MROWS*D_MODEL/4);
    split_w_kernel<<<(4*D_MODEL*D_MODEL/4 + 255)/256, 256>>>(Wq, Wk, Wv, Wo);

    dim3 gq(D_MODEL/128, MROWS/128, 3);   // (8, 32, 3)
    gemm_qkv<<<gq, 256, GEMM_SMEM>>>(bq, bk, bv);

    chunk_kv_mma<<<NBH*NCHUNK, 128, CKV_SMEM>>>();
    chunk_scan_kernel<<<NBH, 256>>>();
    attn_mma_kernel<<<NBH*NCHUNK, 256, ATT_SMEM>>>();

    dim3 go(D_MODEL/128, MROWS/128);      // (8, 32)
    gemm_wo<<<go, 256, GEMM_SMEM>>>(bo, out);
}

// round 12
// speedup vs baseline: 7.1331x; 1.4113x over previous
#include <cuda_runtime.h>
#include <cuda_bf16.h>
#include <cuda_fp16.h>
#include <cstdint>

#define D_MODEL 1024
#define N_HEADS 16
#define DK 64
#define BATCH 2
#define TSEQ 2048
#define MROWS (BATCH*TSEQ)   /* 4096 */
#define CHUNK 128
#define NCHUNK (TSEQ/CHUNK)  /* 16 */
#define NBH (BATCH*N_HEADS)  /* 32 */
#define KVE 72               /* KV ext cols: 64 + ksum + pad */

// ---------------- scratch (static device arrays; no allocation) ----------------
__device__ float g_kv[NBH*NCHUNK*DK*DK];
__device__ float g_ksum[NBH*NCHUNK*DK];
// fp16 GEMM operands (W pre-scaled by 32)
__device__ __half g_xh[MROWS*D_MODEL];
__device__ __half g_wh[4*D_MODEL*D_MODEL];
__device__ __half g_ah[MROWS*D_MODEL];
// fp16 attention operands
__device__ __half g_qf[NBH*TSEQ*DK];
__device__ __half g_kf[NBH*TSEQ*DK];
__device__ __half g_vh[NBH*TSEQ*DK], g_vl[NBH*TSEQ*DK];
__device__ __half g_kvh[NBH*NCHUNK*DK*KVE];
__device__ __half g_kvl[NBH*NCHUNK*DK*KVE];

__device__ __forceinline__ float phi_fn(float x) {
    return x > 0.f ? x + 1.f : __expf(x);
}
__device__ __forceinline__ uint32_t smem_to_u32(const void* smem_ptr) {
    uint32_t addr;
    asm("{ .reg .u64 tmp; cvta.to.shared.u64 tmp, %1; cvt.u32.u64 %0, tmp; }"
        : "=r"(addr) : "l"(smem_ptr));
    return addr;
}

// ---------------- mma / ldmatrix / cp.async primitives ----------------
__device__ __forceinline__ void mma16816h(float* d, const uint32_t* a, const uint32_t* b) {
    asm volatile(
        "mma.sync.aligned.m16n8k16.row.col.f32.f16.f16.f32 "
        "{%0,%1,%2,%3}, {%4,%5,%6,%7}, {%8,%9}, {%0,%1,%2,%3};"
        : "+f"(d[0]), "+f"(d[1]), "+f"(d[2]), "+f"(d[3])
        : "r"(a[0]), "r"(a[1]), "r"(a[2]), "r"(a[3]), "r"(b[0]), "r"(b[1]));
}
__device__ __forceinline__ void ldsm4(uint32_t* r, uint32_t addr) {
    asm volatile("ldmatrix.sync.aligned.m8n8.x4.shared.b16 {%0,%1,%2,%3}, [%4];"
        : "=r"(r[0]), "=r"(r[1]), "=r"(r[2]), "=r"(r[3]) : "r"(addr));
}
__device__ __forceinline__ void ldsm4t(uint32_t* r, uint32_t addr) {
    asm volatile("ldmatrix.sync.aligned.m8n8.x4.trans.shared.b16 {%0,%1,%2,%3}, [%4];"
        : "=r"(r[0]), "=r"(r[1]), "=r"(r[2]), "=r"(r[3]) : "r"(addr));
}
__device__ __forceinline__ void ldsm2t(uint32_t* r, uint32_t addr) {
    asm volatile("ldmatrix.sync.aligned.m8n8.x2.trans.shared.b16 {%0,%1}, [%2];"
        : "=r"(r[0]), "=r"(r[1]) : "r"(addr));
}
#define CP_ASYNC16(dst, src) \
    asm volatile("cp.async.cg.shared.global [%0], [%1], 16;" :: "r"(dst), "l"(src))
#define CP_COMMIT() asm volatile("cp.async.commit_group;" ::: "memory")
#define CP_WAIT1()  asm volatile("cp.async.wait_group 1;" ::: "memory")
#define CP_WAIT0()  asm volatile("cp.async.wait_group 0;" ::: "memory")

__device__ __forceinline__ uint32_t pack_h(float a, float b) {
    __half2 p = __floats2half2_rn(a, b);
    return *reinterpret_cast<uint32_t*>(&p);
}
__device__ __forceinline__ void split_pair_h(float y, __half& h, __half& l) {
    h = __float2half(y);
    l = __float2half(y - __half2float(h));
}
#define SWZ128(off) ((uint32_t)(off) ^ ((((uint32_t)(off)) >> 3) & 0x70))

// ---------------- merged input conversion ----------------
// blocks [0, 4096): x (1048576 float4); blocks [4096, 8192): W (4x262144 float4)
__global__ __launch_bounds__(256) void split_all_kernel(
    const float* __restrict__ x,
    const float* __restrict__ w0, const float* __restrict__ w1,
    const float* __restrict__ w2, const float* __restrict__ w3)
{
    const int per = D_MODEL*D_MODEL/4;          // 262144
    int i = blockIdx.x * 256 + threadIdx.x;
    if (i < MROWS*D_MODEL/4) {
        float4 v = ((const float4*)x)[i];
        ((__half2*)(g_xh + 4*(size_t)i))[0] = __floats2half2_rn(v.x, v.y);
        ((__half2*)(g_xh + 4*(size_t)i))[1] = __floats2half2_rn(v.z, v.w);
    } else {
        int j = i - MROWS*D_MODEL/4;
        int sel = j >> 18, loc = j & (per - 1);
        const float* src = (sel == 0) ? w0 : (sel == 1) ? w1 : (sel == 2) ? w2 : w3;
        float4 v = ((const float4*)src)[loc];
        size_t o = (size_t)sel * D_MODEL * D_MODEL + 4*(size_t)loc;
        ((__half2*)(g_wh + o))[0] = __floats2half2_rn(v.x*32.f, v.y*32.f);
        ((__half2*)(g_wh + o))[1] = __floats2half2_rn(v.z*32.f, v.w*32.f);
    }
}

// ---------------- fp16 GEMM: BK=64, 3-stage, SW128, 2 CTAs/SM ----------------
#define TILE_B (128*128)            /* 16384: 128 rows x 128B (64 fp16) */
#define STAGE_B (2*TILE_B)          /* 32768: XH WH */
#define GEMM_SMEM (3*STAGE_B)       /* 98304 -> 2 CTAs/SM */
#define NSTG 16                     /* 1024 / 64 */

// ep: 0=Wq->phi->q, 1=Wk->phi->k, 2=Wv->v, 3=g_ah@Wo^T->outp
__device__ __forceinline__ void gemm_body(
    int ep, const __half* __restrict__ Xh,
    const float* __restrict__ bias, float* __restrict__ outp, char* smem)
{
    const uint32_t sb = smem_to_u32(smem);
    const int tid = threadIdx.x;
    const int lane = tid & 31, wid = tid >> 5;
    const int wm = wid & 1, wn = wid >> 1;
    const int m0 = blockIdx.y * 128;
    const int n0 = blockIdx.x * 128;

    const __half* Wh = g_wh + (size_t)ep * D_MODEL * D_MODEL;

    float acc[4][4][4];
    #pragma unroll
    for (int i = 0; i < 4; i++)
        #pragma unroll
        for (int j = 0; j < 4; j++)
            #pragma unroll
            for (int l = 0; l < 4; l++) acc[i][j][l] = 0.f;

    // loader: thread t -> rows t>>2 and t>>2+64, units (t&3)*2 and +1
    const int lr = tid >> 2, lu = (tid & 3) * 2;
    const uint32_t d00 = SWZ128(lr*128 + lu*16),        d01 = SWZ128(lr*128 + (lu+1)*16);
    const uint32_t d10 = SWZ128((lr+64)*128 + lu*16),   d11 = SWZ128((lr+64)*128 + (lu+1)*16);

    auto load_stage = [&](int buf, int k0) {
        uint32_t base = sb + buf * STAGE_B;
        CP_ASYNC16(base + d00, Xh + (size_t)(m0 + lr)*D_MODEL + k0 + lu*8);
        CP_ASYNC16(base + d01, Xh + (size_t)(m0 + lr)*D_MODEL + k0 + lu*8 + 8);
        CP_ASYNC16(base + d10, Xh + (size_t)(m0 + lr + 64)*D_MODEL + k0 + lu*8);
        CP_ASYNC16(base + d11, Xh + (size_t)(m0 + lr + 64)*D_MODEL + k0 + lu*8 + 8);
        base += TILE_B;
        CP_ASYNC16(base + d00, Wh + (size_t)(n0 + lr)*D_MODEL + k0 + lu*8);
        CP_ASYNC16(base + d01, Wh + (size_t)(n0 + lr)*D_MODEL + k0 + lu*8 + 8);
        CP_ASYNC16(base + d10, Wh + (size_t)(n0 + lr + 64)*D_MODEL + k0 + lu*8);
        CP_ASYNC16(base + d11, Wh + (size_t)(n0 + lr + 64)*D_MODEL + k0 + lu*8 + 8);
        CP_COMMIT();
    };

    load_stage(0, 0);
    load_stage(1, 64);

    for (int kc = 0; kc < NSTG; kc++) {
        if (kc < NSTG-1) { CP_WAIT1(); } else { CP_WAIT0(); }
        __syncthreads();
        if (kc + 2 < NSTG) load_stage((kc + 2) % 3, (kc + 2) * 64);

        const uint32_t base = sb + (kc % 3) * STAGE_B;
        #pragma unroll
        for (int ks = 0; ks < 4; ks++) {
            uint32_t ah[4][4], bh[2][4];
            #pragma unroll
            for (int mt = 0; mt < 4; mt++) {
                const int rA = wm*64 + mt*16 + (lane & 15);
                const uint32_t offA = SWZ128(rA*128 + ((lane >> 4) + 2*ks)*16);
                ldsm4(ah[mt], base + offA);
            }
            #pragma unroll
            for (int op = 0; op < 2; op++) {
                const int rB = wn*32 + op*16 + ((lane >> 4) << 3) + (lane & 7);
                const uint32_t offB = SWZ128(rB*128 + (((lane >> 3) & 1) + 2*ks)*16);
                ldsm4(bh[op], base + TILE_B + offB);
            }
            #pragma unroll
            for (int mt = 0; mt < 4; mt++)
                #pragma unroll
                for (int nt = 0; nt < 4; nt++) {
                    const uint32_t* bhp = &bh[nt >> 1][(nt & 1) * 2];
                    mma16816h(acc[mt][nt], ah[mt], bhp);
                }
        }
    }
    __syncthreads();

    // ---- epilogue (acc is 32x scaled) ----
    const float INV32 = 1.f/32.f;
    const int m_base = m0 + wm*64;
    #pragma unroll
    for (int mt = 0; mt < 4; mt++) {
        #pragma unroll
        for (int nt = 0; nt < 4; nt++) {
            const int n = n0 + wn*32 + nt*8 + (lane & 3)*2;
            const float b0v = bias[n], b1v = bias[n+1];
            #pragma unroll
            for (int half = 0; half < 2; half++) {
                const int m = m_base + mt*16 + (lane >> 2) + half*8;
                float y0 = acc[mt][nt][half*2+0]*INV32 + b0v;
                float y1 = acc[mt][nt][half*2+1]*INV32 + b1v;
                if (ep <= 1) { y0 = phi_fn(y0); y1 = phi_fn(y1); }
                if (ep <= 2) {
                    const int h = n >> 6, d = n & 63;
                    const int b = m >> 11, t = m & (TSEQ-1);
                    const size_t off = ((size_t)((b*N_HEADS + h)*TSEQ + t))*DK + d;
                    if (ep == 0) {
                        *(__half2*)(g_qf + off) = __floats2half2_rn(y0, y1);
                    } else if (ep == 1) {
                        *(__half2*)(g_kf + off) = __floats2half2_rn(y0, y1);
                    } else {
                        __half h0,h1,l0,l1;
                        split_pair_h(y0,h0,l0); split_pair_h(y1,h1,l1);
                        __half2 ph{h0,h1}, pl{l0,l1};
                        *(__half2*)(g_vh + off) = ph;
                        *(__half2*)(g_vl + off) = pl;
                    }
                } else {
                    *(float2*)(outp + (size_t)m*D_MODEL + n) = make_float2(y0, y1);
                }
            }
        }
    }
}

__global__ __launch_bounds__(256, 2) void gemm_qkv(
    const float* __restrict__ bq, const float* __restrict__ bk,
    const float* __restrict__ bv)
{
    extern __shared__ char smem[];
    const int ep = blockIdx.z;
    const float* bias = (ep == 0) ? bq : (ep == 1) ? bk : bv;
    gemm_body(ep, g_xh, bias, nullptr, smem);
}
__global__ __launch_bounds__(256, 2) void gemm_wo(
    const float* __restrict__ bo, float* __restrict__ outp)
{
    extern __shared__ char smem[];
    gemm_body(3, g_ah, bo, outp, smem);
}

// ================= attention on tensor cores (fp16) =================
#define APITCH 144
#define ATILE (128*APITCH)
#define KVTILE (DK*APITCH)

// ---------------- per-chunk K^T V and k-sum ----------------
#define CKV_SMEM (3*ATILE)          /* K, Vh, Vl = 55296 */
__global__ __launch_bounds__(128) void chunk_kv_mma()
{
    extern __shared__ char smem[];
    const uint32_t sb = smem_to_u32(smem);
    const uint32_t SK = 0, SVH = ATILE, SVL = 2*ATILE;
    const int blk = blockIdx.x;
    const int bh = blk >> 4, c = blk & 15;
    const int tid = threadIdx.x;
    const int lane = tid & 31, wid = tid >> 5;
    const size_t gbase = (size_t)bh*TSEQ*DK + (size_t)c*CHUNK*DK;

    #pragma unroll
    for (int it = 0; it < 8; it++) {
        int idx = tid + it*128;
        int r = idx >> 3, cc = idx & 7;
        const size_t so = gbase + (size_t)r*DK + cc*8;
        *(float4*)(smem + SK  + r*APITCH + cc*16) = *(const float4*)(g_kf + so);
        *(float4*)(smem + SVH + r*APITCH + cc*16) = *(const float4*)(g_vh + so);
        *(float4*)(smem + SVL + r*APITCH + cc*16) = *(const float4*)(g_vl + so);
    }
    {
        int r = tid;
        *(float4*)(smem + SVH + r*APITCH + 128) =
            make_float4(__uint_as_float(0x00003C00u), 0.f, 0.f, 0.f);
        *(float4*)(smem + SVL + r*APITCH + 128) = make_float4(0.f, 0.f, 0.f, 0.f);
    }
    __syncthreads();

    float f[8][4];
    #pragma unroll
    for (int n = 0; n < 8; n++)
        #pragma unroll
        for (int l = 0; l < 4; l++) f[n][l] = 0.f;
    float f8[4] = {0.f, 0.f, 0.f, 0.f};

    const uint32_t ka_rel = (uint32_t)(( ((lane>>4)&1)*8 + (lane&7) )*APITCH
                                       + (wid*16 + ((lane>>3)&1)*8)*2);
    const uint32_t vb_rel = (uint32_t)(( ((lane>>3)&1)*8 + (lane&7) )*APITCH
                                       + ((lane>>4)*8)*2);
    const uint32_t v2_rel = (uint32_t)(( ((lane>>3)&1)*8 + (lane&7) )*APITCH + 64*2);
    #pragma unroll
    for (int ks = 0; ks < 8; ks++) {
        const uint32_t krow = (uint32_t)(ks*16)*APITCH;
        uint32_t kah[4], vbh[4][4], vbl[4][4], v2h[2];
        ldsm4t(kah, sb + SK + krow + ka_rel);
        #pragma unroll
        for (int p = 0; p < 4; p++) {
            ldsm4t(vbh[p], sb + SVH + krow + vb_rel + (uint32_t)(p*16*2));
            ldsm4t(vbl[p], sb + SVL + krow + vb_rel + (uint32_t)(p*16*2));
        }
        ldsm2t(v2h, sb + SVH + krow + v2_rel);
        #pragma unroll
        for (int nt = 0; nt < 8; nt++) {
            const uint32_t* bhp = &vbh[nt>>1][(nt&1)*2];
            const uint32_t* blp = &vbl[nt>>1][(nt&1)*2];
            mma16816h(f[nt], kah, bhp);
            mma16816h(f[nt], kah, blp);
        }
        mma16816h(f8, kah, v2h);
    }

    float* kvout = g_kv + (size_t)blk*DK*DK;
    const int d0 = wid*16 + (lane>>2);
    #pragma unroll
    for (int nt = 0; nt < 8; nt++) {
        const int e = nt*8 + (lane&3)*2;
        *(float2*)(kvout + (size_t)d0*DK + e)     = make_float2(f[nt][0], f[nt][1]);
        *(float2*)(kvout + (size_t)(d0+8)*DK + e) = make_float2(f[nt][2], f[nt][3]);
    }
    if ((lane & 3) == 0) {
        g_ksum[(size_t)blk*DK + d0]     = f8[0];
        g_ksum[(size_t)blk*DK + d0 + 8] = f8[2];
    }
}

// ---------------- exclusive prefix scan (parallel, one pos per thread) ----------------
__global__ __launch_bounds__(256) void chunk_scan_kernel()
{
    const int bh = blockIdx.x;
    const int pos = blockIdx.y * 256 + threadIdx.x;
    if (pos >= DK*KVE) return;
    const int d = pos / KVE, e = pos % KVE;
    float run = 0.f;
    #pragma unroll
    for (int c = 0; c < NCHUNK; c++) {
        const size_t blk = (size_t)(bh*NCHUNK + c);
        __half h, l;
        split_pair_h(run, h, l);
        g_kvh[blk*DK*KVE + pos] = h;
        g_kvl[blk*DK*KVE + pos] = l;
        float val = 0.f;
        if (e < DK)       val = g_kv[blk*DK*DK + (size_t)d*DK + e];
        else if (e == DK) val = g_ksum[blk*DK + d];
        run += val;
    }
}

// ---------------- per-chunk attention (fp16, causal) ----------------
#define ATT_SMEM (4*ATILE + 2*KVTILE)   /* 92160 */
__global__ __launch_bounds__(256) void attn_mma_kernel()
{
    extern __shared__ char smem[];
    const uint32_t sb = smem_to_u32(smem);
    const uint32_t SQ = 0, SK = ATILE, SVH = 2*ATILE, SVL = 3*ATILE;
    const uint32_t SGH = 4*ATILE, SGL = 4*ATILE + KVTILE;

    const int blk = blockIdx.x;
    const int bh = blk >> 4, c = blk & 15;
    const int tid = threadIdx.x;
    const int lane = tid & 31, wid = tid >> 5;
    const size_t gbase = (size_t)bh*TSEQ*DK + (size_t)c*CHUNK*DK;

    #pragma unroll
    for (int it = 0; it < 4; it++) {
        int idx = tid + it*256;
        int r = idx >> 3, cc = idx & 7;
        const size_t so = gbase + (size_t)r*DK + cc*8;
        const uint32_t doff = r*APITCH + cc*16;
        *(float4*)(smem + SQ  + doff) = *(const float4*)(g_qf + so);
        *(float4*)(smem + SK  + doff) = *(const float4*)(g_kf + so);
        *(float4*)(smem + SVH + doff) = *(const float4*)(g_vh + so);
        *(float4*)(smem + SVL + doff) = *(const float4*)(g_vl + so);
    }
    {
        const size_t kvbase = (size_t)blk*DK*KVE;
        for (int idx = tid; idx < 576; idx += 256) {
            int r = idx / 9, cc = idx % 9;
            *(float4*)(smem + SGH + r*APITCH + cc*16) = *(const float4*)(g_kvh + kvbase + (size_t)r*KVE + cc*8);
            *(float4*)(smem + SGL + r*APITCH + cc*16) = *(const float4*)(g_kvl + kvbase + (size_t)r*KVE + cc*8);
        }
    }
    __syncthreads();

    const int rbase = wid * 16;
    const uint32_t qa_rel = (uint32_t)((rbase + (lane & 15))*APITCH + (lane >> 4)*16);
    uint32_t qa[4][4];
    #pragma unroll
    for (int ks = 0; ks < 4; ks++)
        ldsm4(qa[ks], sb + SQ + qa_rel + ks*32);

    float o[9][4];
    #pragma unroll
    for (int n = 0; n < 9; n++)
        #pragma unroll
        for (int l = 0; l < 4; l++) o[n][l] = 0.f;

    // ---- inter-chunk: o += q @ KV_prev (fp16 hi/lo, 2 terms) ----
    const uint32_t gb_rel = (uint32_t)(( ((lane>>3)&1)*8 + (lane&7) )*APITCH + ((lane>>4)*8)*2);
    #pragma unroll
    for (int ks = 0; ks < 4; ks++) {
        const uint32_t krow = (uint32_t)(ks*16)*APITCH;
        uint32_t gbh[4][4], gbl[4][4], g2h[2], g2l[2];
        #pragma unroll
        for (int p = 0; p < 4; p++) {
            ldsm4t(gbh[p], sb + SGH + krow + gb_rel + (uint32_t)(p*16*2));
            ldsm4t(gbl[p], sb + SGL + krow + gb_rel + (uint32_t)(p*16*2));
        }
        const uint32_t g2_rel = (uint32_t)(( ((lane>>3)&1)*8 + (lane&7) )*APITCH + 64*2);
        ldsm2t(g2h, sb + SGH + krow + g2_rel);
        ldsm2t(g2l, sb + SGL + krow + g2_rel);
        #pragma unroll
        for (int nt = 0; nt < 8; nt++) {
            const uint32_t* bhp = &gbh[nt>>1][(nt&1)*2];
            const uint32_t* blp = &gbl[nt>>1][(nt&1)*2];
            mma16816h(o[nt], qa[ks], bhp);
            mma16816h(o[nt], qa[ks], blp);
        }
        mma16816h(o[8], qa[ks], g2h);
        mma16816h(o[8], qa[ks], g2l);
    }

    // ---- intra-chunk causal ----
    float zacc0 = 0.f, zacc1 = 0.f;
    const int row0 = rbase + (lane >> 2), row1 = row0 + 8;
    const int ncc = wid/2 + 1;
    const uint32_t kb_col = (uint32_t)(((lane>>3)&1)*16);
    const uint32_t vb_rel = (uint32_t)(( ((lane>>3)&1)*8 + (lane&7) )*APITCH + ((lane>>4)*8)*2);

    for (int cc = 0; cc < ncc; cc++) {
        const int c0 = cc*32;
        float s[4][4];
        #pragma unroll
        for (int n = 0; n < 4; n++)
            #pragma unroll
            for (int l = 0; l < 4; l++) s[n][l] = 0.f;
        #pragma unroll
        for (int ks = 0; ks < 4; ks++) {
            uint32_t kb[2][4];
            #pragma unroll
            for (int p = 0; p < 2; p++) {
                const uint32_t kbo = (uint32_t)((c0 + 16*p + ((lane>>4)<<3) + (lane&7))*APITCH)
                                     + kb_col + (uint32_t)(ks*32);
                ldsm4(kb[p], sb + SK + kbo);
            }
            #pragma unroll
            for (int nt = 0; nt < 4; nt++) {
                const uint32_t* bp = &kb[nt>>1][(nt&1)*2];
                mma16816h(s[nt], qa[ks], bp);
            }
        }
        uint32_t af[2][4];
        #pragma unroll
        for (int nt = 0; nt < 4; nt++) {
            const int colj = c0 + nt*8 + (lane&3)*2;
            float e0 = (colj   <= row0) ? s[nt][0] : 0.f;
            float e1 = (colj+1 <= row0) ? s[nt][1] : 0.f;
            float e2 = (colj   <= row1) ? s[nt][2] : 0.f;
            float e3 = (colj+1 <= row1) ? s[nt][3] : 0.f;
            zacc0 += e0 + e1;
            zacc1 += e2 + e3;
            const int kk = nt >> 1, half = nt & 1;
            af[kk][half*2+0] = pack_h(e0, e1);
            af[kk][half*2+1] = pack_h(e2, e3);
        }
        #pragma unroll
        for (int kk = 0; kk < 2; kk++) {
            const uint32_t krow = (uint32_t)((c0 + kk*16))*APITCH;
            uint32_t vbh[4][4], vbl[4][4];
            #pragma unroll
            for (int p = 0; p < 4; p++) {
                ldsm4t(vbh[p], sb + SVH + krow + vb_rel + (uint32_t)(p*16*2));
                ldsm4t(vbl[p], sb + SVL + krow + vb_rel + (uint32_t)(p*16*2));
            }
            #pragma unroll
            for (int nt = 0; nt < 8; nt++) {
                const uint32_t* bhp = &vbh[nt>>1][(nt&1)*2];
                const uint32_t* blp = &vbl[nt>>1][(nt&1)*2];
                mma16816h(o[nt], af[kk], bhp);
                mma16816h(o[nt], af[kk], blp);
            }
        }
    }

    float z0 = zacc0 + ((lane & 3) == 0 ? o[8][0] : 0.f);
    float z1 = zacc1 + ((lane & 3) == 0 ? o[8][2] : 0.f);
    z0 += __shfl_xor_sync(0xffffffff, z0, 1);
    z0 += __shfl_xor_sync(0xffffffff, z0, 2);
    z1 += __shfl_xor_sync(0xffffffff, z1, 1);
    z1 += __shfl_xor_sync(0xffffffff, z1, 2);
    const float inv0 = 1.f / (z0 + 1e-6f);
    const float inv1 = 1.f / (z1 + 1e-6f);

    const int b = bh >> 4, h = bh & 15;
    const size_t mbase0 = ((size_t)(b*TSEQ + c*CHUNK + row0))*D_MODEL + h*DK;
    const size_t mbase1 = ((size_t)(b*TSEQ + c*CHUNK + row1))*D_MODEL + h*DK;
    #pragma unroll
    for (int nt = 0; nt < 8; nt++) {
        const int e = nt*8 + (lane&3)*2;
        float y0 = o[nt][0]*inv0, y1 = o[nt][1]*inv0;
        float y2 = o[nt][2]*inv1, y3 = o[nt][3]*inv1;
        *(__half2*)(g_ah + mbase0 + e) = __floats2half2_rn(y0, y1);
        *(__half2*)(g_ah + mbase1 + e) = __floats2half2_rn(y2, y3);
    }
}

// ---------------- launch ----------------
extern "C" void kernel_launch(void* const* d_in, const int* in_sizes, int n_in,
                              void* d_out, int out_size)
{
    (void)in_sizes; (void)n_in; (void)out_size;
    const float* x  = (const float*)d_in[0];
    const float* Wq = (const float*)d_in[1];
    const float* bq = (const float*)d_in[2];
    const float* Wk = (const float*)d_in[3];
    const float* bk = (const float*)d_in[4];
    const float* Wv = (const float*)d_in[5];
    const float* bv = (const float*)d_in[6];
    const float* Wo = (const float*)d_in[7];
    const float* bo = (const float*)d_in[8];
    float* out = (float*)d_out;

    cudaFuncSetAttribute(gemm_qkv, cudaFuncAttributeMaxDynamicSharedMemorySize, GEMM_SMEM);
    cudaFuncSetAttribute(gemm_wo,  cudaFuncAttributeMaxDynamicSharedMemorySize, GEMM_SMEM);
    cudaFuncSetAttribute(chunk_kv_mma,    cudaFuncAttributeMaxDynamicSharedMemorySize, CKV_SMEM);
    cudaFuncSetAttribute(attn_mma_kernel, cudaFuncAttributeMaxDynamicSharedMemorySize, ATT_SMEM);

    // x: 1048576 float4 -> 4096 blocks; W: 4*262144 float4 -> 4096 blocks
    split_all_kernel<<<8192, 256>>>(x, Wq, Wk, Wv, Wo);

    dim3 gq(D_MODEL/128, MROWS/128, 3);   // (8, 32, 3)
    gemm_qkv<<<gq, 256, GEMM_SMEM>>>(bq, bk, bv);

    chunk_kv_mma<<<NBH*NCHUNK, 128, CKV_SMEM>>>();
    dim3 gs(NBH, (DK*KVE + 255)/256);     // (32, 18)
    chunk_scan_kernel<<<gs, 256>>>();
    attn_mma_kernel<<<NBH*NCHUNK, 256, ATT_SMEM>>>();

    dim3 go(D_MODEL/128, MROWS/128);      // (8, 32)
    gemm_wo<<<go, 256, GEMM_SMEM>>>(bo, out);
}

// round 13
// speedup vs baseline: 7.2304x; 1.0136x over previous
#include <cuda_runtime.h>
#include <cuda_bf16.h>
#include <cuda_fp16.h>
#include <cstdint>

#define D_MODEL 1024
#define N_HEADS 16
#define DK 64
#define BATCH 2
#define TSEQ 2048
#define MROWS (BATCH*TSEQ)   /* 4096 */
#define CHUNK 128
#define NCHUNK (TSEQ/CHUNK)  /* 16 */
#define NBH (BATCH*N_HEADS)  /* 32 */
#define KVE 72               /* KV ext cols: 64 + ksum + pad */

// ---------------- scratch (static device arrays; no allocation) ----------------
__device__ float g_kv[NBH*NCHUNK*DK*DK];
__device__ float g_ksum[NBH*NCHUNK*DK];
// fp16 GEMM operands (W pre-scaled by 32)
__device__ __half g_xh[MROWS*D_MODEL];
__device__ __half g_wh[4*D_MODEL*D_MODEL];
__device__ __half g_ah[MROWS*D_MODEL];
// fp16 attention operands
__device__ __half g_qf[NBH*TSEQ*DK];
__device__ __half g_kf[NBH*TSEQ*DK];
__device__ __half g_vh[NBH*TSEQ*DK], g_vl[NBH*TSEQ*DK];
__device__ __half g_kvh[NBH*NCHUNK*DK*KVE];
__device__ __half g_kvl[NBH*NCHUNK*DK*KVE];

__device__ __forceinline__ float phi_fn(float x) {
    return x > 0.f ? x + 1.f : __expf(x);
}
__device__ __forceinline__ uint32_t smem_to_u32(const void* smem_ptr) {
    uint32_t addr;
    asm("{ .reg .u64 tmp; cvta.to.shared.u64 tmp, %1; cvt.u32.u64 %0, tmp; }"
        : "=r"(addr) : "l"(smem_ptr));
    return addr;
}

// ---------------- mma / ldmatrix / cp.async primitives ----------------
__device__ __forceinline__ void mma16816h(float* d, const uint32_t* a, const uint32_t* b) {
    asm volatile(
        "mma.sync.aligned.m16n8k16.row.col.f32.f16.f16.f32 "
        "{%0,%1,%2,%3}, {%4,%5,%6,%7}, {%8,%9}, {%0,%1,%2,%3};"
        : "+f"(d[0]), "+f"(d[1]), "+f"(d[2]), "+f"(d[3])
        : "r"(a[0]), "r"(a[1]), "r"(a[2]), "r"(a[3]), "r"(b[0]), "r"(b[1]));
}
__device__ __forceinline__ void ldsm4(uint32_t* r, uint32_t addr) {
    asm volatile("ldmatrix.sync.aligned.m8n8.x4.shared.b16 {%0,%1,%2,%3}, [%4];"
        : "=r"(r[0]), "=r"(r[1]), "=r"(r[2]), "=r"(r[3]) : "r"(addr));
}
__device__ __forceinline__ void ldsm4t(uint32_t* r, uint32_t addr) {
    asm volatile("ldmatrix.sync.aligned.m8n8.x4.trans.shared.b16 {%0,%1,%2,%3}, [%4];"
        : "=r"(r[0]), "=r"(r[1]), "=r"(r[2]), "=r"(r[3]) : "r"(addr));
}
__device__ __forceinline__ void ldsm2t(uint32_t* r, uint32_t addr) {
    asm volatile("ldmatrix.sync.aligned.m8n8.x2.trans.shared.b16 {%0,%1}, [%2];"
        : "=r"(r[0]), "=r"(r[1]) : "r"(addr));
}
#define CP_ASYNC16(dst, src) \
    asm volatile("cp.async.cg.shared.global [%0], [%1], 16;" :: "r"(dst), "l"(src))
#define CP_COMMIT() asm volatile("cp.async.commit_group;" ::: "memory")
#define CP_WAIT1()  asm volatile("cp.async.wait_group 1;" ::: "memory")
#define CP_WAIT0()  asm volatile("cp.async.wait_group 0;" ::: "memory")

__device__ __forceinline__ uint32_t pack_h(float a, float b) {
    __half2 p = __floats2half2_rn(a, b);
    return *reinterpret_cast<uint32_t*>(&p);
}
__device__ __forceinline__ void split_pair_h(float y, __half& h, __half& l) {
    h = __float2half(y);
    l = __float2half(y - __half2float(h));
}
#define SWZ128(off) ((uint32_t)(off) ^ ((((uint32_t)(off)) >> 3) & 0x70))

// ---------------- merged input conversion ----------------
// blocks [0, 4096): x (1048576 float4); blocks [4096, 8192): W (4x262144 float4)
__global__ __launch_bounds__(256) void split_all_kernel(
    const float* __restrict__ x,
    const float* __restrict__ w0, const float* __restrict__ w1,
    const float* __restrict__ w2, const float* __restrict__ w3)
{
    const int per = D_MODEL*D_MODEL/4;          // 262144
    int i = blockIdx.x * 256 + threadIdx.x;
    if (i < MROWS*D_MODEL/4) {
        float4 v = ((const float4*)x)[i];
        ((__half2*)(g_xh + 4*(size_t)i))[0] = __floats2half2_rn(v.x, v.y);
        ((__half2*)(g_xh + 4*(size_t)i))[1] = __floats2half2_rn(v.z, v.w);
    } else {
        int j = i - MROWS*D_MODEL/4;
        int sel = j >> 18, loc = j & (per - 1);
        const float* src = (sel == 0) ? w0 : (sel == 1) ? w1 : (sel == 2) ? w2 : w3;
        float4 v = ((const float4*)src)[loc];
        size_t o = (size_t)sel * D_MODEL * D_MODEL + 4*(size_t)loc;
        ((__half2*)(g_wh + o))[0] = __floats2half2_rn(v.x*32.f, v.y*32.f);
        ((__half2*)(g_wh + o))[1] = __floats2half2_rn(v.z*32.f, v.w*32.f);
    }
}

// ---------------- fp16 GEMM: BK=64, 3-stage, SW128, 2 CTAs/SM ----------------
#define TILE_B (128*128)            /* 16384: 128 rows x 128B (64 fp16) */
#define STAGE_B (2*TILE_B)          /* 32768: XH WH */
#define GEMM_SMEM (3*STAGE_B)       /* 98304 -> 2 CTAs/SM */
#define NSTG 16                     /* 1024 / 64 */

// ep: 0=Wq->phi->q, 1=Wk->phi->k, 2=Wv->v, 3=g_ah@Wo^T->outp
__device__ __forceinline__ void gemm_body(
    int ep, const __half* __restrict__ Xh,
    const float* __restrict__ bias, float* __restrict__ outp, char* smem)
{
    const uint32_t sb = smem_to_u32(smem);
    const int tid = threadIdx.x;
    const int lane = tid & 31, wid = tid >> 5;
    const int wm = wid & 1, wn = wid >> 1;
    const int m0 = blockIdx.y * 128;
    const int n0 = blockIdx.x * 128;

    const __half* Wh = g_wh + (size_t)ep * D_MODEL * D_MODEL;

    float acc[4][4][4];
    #pragma unroll
    for (int i = 0; i < 4; i++)
        #pragma unroll
        for (int j = 0; j < 4; j++)
            #pragma unroll
            for (int l = 0; l < 4; l++) acc[i][j][l] = 0.f;

    const int lr = tid >> 2, lu = (tid & 3) * 2;
    const uint32_t d00 = SWZ128(lr*128 + lu*16),        d01 = SWZ128(lr*128 + (lu+1)*16);
    const uint32_t d10 = SWZ128((lr+64)*128 + lu*16),   d11 = SWZ128((lr+64)*128 + (lu+1)*16);

    auto load_stage = [&](int buf, int k0) {
        uint32_t base = sb + buf * STAGE_B;
        CP_ASYNC16(base + d00, Xh + (size_t)(m0 + lr)*D_MODEL + k0 + lu*8);
        CP_ASYNC16(base + d01, Xh + (size_t)(m0 + lr)*D_MODEL + k0 + lu*8 + 8);
        CP_ASYNC16(base + d10, Xh + (size_t)(m0 + lr + 64)*D_MODEL + k0 + lu*8);
        CP_ASYNC16(base + d11, Xh + (size_t)(m0 + lr + 64)*D_MODEL + k0 + lu*8 + 8);
        base += TILE_B;
        CP_ASYNC16(base + d00, Wh + (size_t)(n0 + lr)*D_MODEL + k0 + lu*8);
        CP_ASYNC16(base + d01, Wh + (size_t)(n0 + lr)*D_MODEL + k0 + lu*8 + 8);
        CP_ASYNC16(base + d10, Wh + (size_t)(n0 + lr + 64)*D_MODEL + k0 + lu*8);
        CP_ASYNC16(base + d11, Wh + (size_t)(n0 + lr + 64)*D_MODEL + k0 + lu*8 + 8);
        CP_COMMIT();
    };

    load_stage(0, 0);
    load_stage(1, 64);

    for (int kc = 0; kc < NSTG; kc++) {
        if (kc < NSTG-1) { CP_WAIT1(); } else { CP_WAIT0(); }
        __syncthreads();
        if (kc + 2 < NSTG) load_stage((kc + 2) % 3, (kc + 2) * 64);

        const uint32_t base = sb + (kc % 3) * STAGE_B;
        #pragma unroll
        for (int ks = 0; ks < 4; ks++) {
            uint32_t ah[4][4], bh[2][4];
            #pragma unroll
            for (int mt = 0; mt < 4; mt++) {
                const int rA = wm*64 + mt*16 + (lane & 15);
                const uint32_t offA = SWZ128(rA*128 + ((lane >> 4) + 2*ks)*16);
                ldsm4(ah[mt], base + offA);
            }
            #pragma unroll
            for (int op = 0; op < 2; op++) {
                const int rB = wn*32 + op*16 + ((lane >> 4) << 3) + (lane & 7);
                const uint32_t offB = SWZ128(rB*128 + (((lane >> 3) & 1) + 2*ks)*16);
                ldsm4(bh[op], base + TILE_B + offB);
            }
            #pragma unroll
            for (int mt = 0; mt < 4; mt++)
                #pragma unroll
                for (int nt = 0; nt < 4; nt++) {
                    const uint32_t* bhp = &bh[nt >> 1][(nt & 1) * 2];
                    mma16816h(acc[mt][nt], ah[mt], bhp);
                }
        }
    }
    __syncthreads();

    // ---- epilogue (acc is 32x scaled) ----
    const float INV32 = 1.f/32.f;
    const int m_base = m0 + wm*64;
    #pragma unroll
    for (int mt = 0; mt < 4; mt++) {
        #pragma unroll
        for (int nt = 0; nt < 4; nt++) {
            const int n = n0 + wn*32 + nt*8 + (lane & 3)*2;
            const float b0v = bias[n], b1v = bias[n+1];
            #pragma unroll
            for (int half = 0; half < 2; half++) {
                const int m = m_base + mt*16 + (lane >> 2) + half*8;
                float y0 = acc[mt][nt][half*2+0]*INV32 + b0v;
                float y1 = acc[mt][nt][half*2+1]*INV32 + b1v;
                if (ep <= 1) { y0 = phi_fn(y0); y1 = phi_fn(y1); }
                if (ep <= 2) {
                    const int h = n >> 6, d = n & 63;
                    const int b = m >> 11, t = m & (TSEQ-1);
                    const size_t off = ((size_t)((b*N_HEADS + h)*TSEQ + t))*DK + d;
                    if (ep == 0) {
                        *(__half2*)(g_qf + off) = __floats2half2_rn(y0, y1);
                    } else if (ep == 1) {
                        *(__half2*)(g_kf + off) = __floats2half2_rn(y0, y1);
                    } else {
                        __half h0,h1,l0,l1;
                        split_pair_h(y0,h0,l0); split_pair_h(y1,h1,l1);
                        __half2 ph{h0,h1}, pl{l0,l1};
                        *(__half2*)(g_vh + off) = ph;
                        *(__half2*)(g_vl + off) = pl;
                    }
                } else {
                    *(float2*)(outp + (size_t)m*D_MODEL + n) = make_float2(y0, y1);
                }
            }
        }
    }
}

__global__ __launch_bounds__(256, 2) void gemm_qkv(
    const float* __restrict__ bq, const float* __restrict__ bk,
    const float* __restrict__ bv)
{
    extern __shared__ char smem[];
    const int ep = blockIdx.z;
    const float* bias = (ep == 0) ? bq : (ep == 1) ? bk : bv;
    gemm_body(ep, g_xh, bias, nullptr, smem);
}
__global__ __launch_bounds__(256, 2) void gemm_wo(
    const float* __restrict__ bo, float* __restrict__ outp)
{
    extern __shared__ char smem[];
    gemm_body(3, g_ah, bo, outp, smem);
}

// ================= attention on tensor cores (fp16) =================
#define APITCH 144
#define ATILE (128*APITCH)
#define KVTILE (DK*APITCH)

// ---------------- per-chunk K^T V and k-sum ----------------
#define CKV_SMEM (3*ATILE)          /* K, Vh, Vl = 55296 */
__global__ __launch_bounds__(128, 4) void chunk_kv_mma()
{
    extern __shared__ char smem[];
    const uint32_t sb = smem_to_u32(smem);
    const uint32_t SK = 0, SVH = ATILE, SVL = 2*ATILE;
    const int blk = blockIdx.x;
    const int bh = blk >> 4, c = blk & 15;
    const int tid = threadIdx.x;
    const int lane = tid & 31, wid = tid >> 5;
    const size_t gbase = (size_t)bh*TSEQ*DK + (size_t)c*CHUNK*DK;

    #pragma unroll
    for (int it = 0; it < 8; it++) {
        int idx = tid + it*128;
        int r = idx >> 3, cc = idx & 7;
        const size_t so = gbase + (size_t)r*DK + cc*8;
        *(float4*)(smem + SK  + r*APITCH + cc*16) = *(const float4*)(g_kf + so);
        *(float4*)(smem + SVH + r*APITCH + cc*16) = *(const float4*)(g_vh + so);
        *(float4*)(smem + SVL + r*APITCH + cc*16) = *(const float4*)(g_vl + so);
    }
    {
        int r = tid;
        *(float4*)(smem + SVH + r*APITCH + 128) =
            make_float4(__uint_as_float(0x00003C00u), 0.f, 0.f, 0.f);
        *(float4*)(smem + SVL + r*APITCH + 128) = make_float4(0.f, 0.f, 0.f, 0.f);
    }
    __syncthreads();

    float f[8][4];
    #pragma unroll
    for (int n = 0; n < 8; n++)
        #pragma unroll
        for (int l = 0; l < 4; l++) f[n][l] = 0.f;
    float f8[4] = {0.f, 0.f, 0.f, 0.f};

    const uint32_t ka_rel = (uint32_t)(( ((lane>>4)&1)*8 + (lane&7) )*APITCH
                                       + (wid*16 + ((lane>>3)&1)*8)*2);
    const uint32_t vb_rel = (uint32_t)(( ((lane>>3)&1)*8 + (lane&7) )*APITCH
                                       + ((lane>>4)*8)*2);
    const uint32_t v2_rel = (uint32_t)(( ((lane>>3)&1)*8 + (lane&7) )*APITCH + 64*2);
    #pragma unroll
    for (int ks = 0; ks < 8; ks++) {
        const uint32_t krow = (uint32_t)(ks*16)*APITCH;
        uint32_t kah[4], vbh[4][4], vbl[4][4], v2h[2];
        ldsm4t(kah, sb + SK + krow + ka_rel);
        #pragma unroll
        for (int p = 0; p < 4; p++) {
            ldsm4t(vbh[p], sb + SVH + krow + vb_rel + (uint32_t)(p*16*2));
            ldsm4t(vbl[p], sb + SVL + krow + vb_rel + (uint32_t)(p*16*2));
        }
        ldsm2t(v2h, sb + SVH + krow + v2_rel);
        #pragma unroll
        for (int nt = 0; nt < 8; nt++) {
            const uint32_t* bhp = &vbh[nt>>1][(nt&1)*2];
            const uint32_t* blp = &vbl[nt>>1][(nt&1)*2];
            mma16816h(f[nt], kah, bhp);
            mma16816h(f[nt], kah, blp);
        }
        mma16816h(f8, kah, v2h);
    }

    float* kvout = g_kv + (size_t)blk*DK*DK;
    const int d0 = wid*16 + (lane>>2);
    #pragma unroll
    for (int nt = 0; nt < 8; nt++) {
        const int e = nt*8 + (lane&3)*2;
        *(float2*)(kvout + (size_t)d0*DK + e)     = make_float2(f[nt][0], f[nt][1]);
        *(float2*)(kvout + (size_t)(d0+8)*DK + e) = make_float2(f[nt][2], f[nt][3]);
    }
    if ((lane & 3) == 0) {
        g_ksum[(size_t)blk*DK + d0]     = f8[0];
        g_ksum[(size_t)blk*DK + d0 + 8] = f8[2];
    }
}

// ---------------- exclusive prefix scan: preload all chunks, then scan ----------------
__global__ __launch_bounds__(256) void chunk_scan_kernel()
{
    const int bh = blockIdx.x;
    const int pos = blockIdx.y * 256 + threadIdx.x;
    if (pos >= DK*KVE) return;
    const int d = pos / KVE, e = pos % KVE;

    // independent preloads (MLP=16)
    float vals[NCHUNK];
    #pragma unroll
    for (int c = 0; c < NCHUNK; c++) {
        const size_t blk = (size_t)(bh*NCHUNK + c);
        float v = 0.f;
        if (e < DK)       v = g_kv[blk*DK*DK + (size_t)d*DK + e];
        else if (e == DK) v = g_ksum[blk*DK + d];
        vals[c] = v;
    }
    // register-resident exclusive prefix + stores
    float run = 0.f;
    #pragma unroll
    for (int c = 0; c < NCHUNK; c++) {
        const size_t blk = (size_t)(bh*NCHUNK + c);
        __half h, l;
        split_pair_h(run, h, l);
        g_kvh[blk*DK*KVE + pos] = h;
        g_kvl[blk*DK*KVE + pos] = l;
        run += vals[c];
    }
}

// ---------------- per-chunk attention (fp16, causal) ----------------
#define ATT_SMEM (4*ATILE + 2*KVTILE)   /* 92160 */
__global__ __launch_bounds__(256) void attn_mma_kernel()
{
    extern __shared__ char smem[];
    const uint32_t sb = smem_to_u32(smem);
    const uint32_t SQ = 0, SK = ATILE, SVH = 2*ATILE, SVL = 3*ATILE;
    const uint32_t SGH = 4*ATILE, SGL = 4*ATILE + KVTILE;

    const int blk = blockIdx.x;
    const int bh = blk >> 4, c = blk & 15;
    const int tid = threadIdx.x;
    const int lane = tid & 31, wid = tid >> 5;
    const size_t gbase = (size_t)bh*TSEQ*DK + (size_t)c*CHUNK*DK;

    #pragma unroll
    for (int it = 0; it < 4; it++) {
        int idx = tid + it*256;
        int r = idx >> 3, cc = idx & 7;
        const size_t so = gbase + (size_t)r*DK + cc*8;
        const uint32_t doff = r*APITCH + cc*16;
        *(float4*)(smem + SQ  + doff) = *(const float4*)(g_qf + so);
        *(float4*)(smem + SK  + doff) = *(const float4*)(g_kf + so);
        *(float4*)(smem + SVH + doff) = *(const float4*)(g_vh + so);
        *(float4*)(smem + SVL + doff) = *(const float4*)(g_vl + so);
    }
    {
        const size_t kvbase = (size_t)blk*DK*KVE;
        for (int idx = tid; idx < 576; idx += 256) {
            int r = idx / 9, cc = idx % 9;
            *(float4*)(smem + SGH + r*APITCH + cc*16) = *(const float4*)(g_kvh + kvbase + (size_t)r*KVE + cc*8);
            *(float4*)(smem + SGL + r*APITCH + cc*16) = *(const float4*)(g_kvl + kvbase + (size_t)r*KVE + cc*8);
        }
    }
    __syncthreads();

    const int rbase = wid * 16;
    const uint32_t qa_rel = (uint32_t)((rbase + (lane & 15))*APITCH + (lane >> 4)*16);
    uint32_t qa[4][4];
    #pragma unroll
    for (int ks = 0; ks < 4; ks++)
        ldsm4(qa[ks], sb + SQ + qa_rel + ks*32);

    float o[9][4];
    #pragma unroll
    for (int n = 0; n < 9; n++)
        #pragma unroll
        for (int l = 0; l < 4; l++) o[n][l] = 0.f;

    // ---- inter-chunk: o += q @ KV_prev (fp16 hi/lo, 2 terms) ----
    const uint32_t gb_rel = (uint32_t)(( ((lane>>3)&1)*8 + (lane&7) )*APITCH + ((lane>>4)*8)*2);
    #pragma unroll
    for (int ks = 0; ks < 4; ks++) {
        const uint32_t krow = (uint32_t)(ks*16)*APITCH;
        uint32_t gbh[4][4], gbl[4][4], g2h[2], g2l[2];
        #pragma unroll
        for (int p = 0; p < 4; p++) {
            ldsm4t(gbh[p], sb + SGH + krow + gb_rel + (uint32_t)(p*16*2));
            ldsm4t(gbl[p], sb + SGL + krow + gb_rel + (uint32_t)(p*16*2));
        }
        const uint32_t g2_rel = (uint32_t)(( ((lane>>3)&1)*8 + (lane&7) )*APITCH + 64*2);
        ldsm2t(g2h, sb + SGH + krow + g2_rel);
        ldsm2t(g2l, sb + SGL + krow + g2_rel);
        #pragma unroll
        for (int nt = 0; nt < 8; nt++) {
            const uint32_t* bhp = &gbh[nt>>1][(nt&1)*2];
            const uint32_t* blp = &gbl[nt>>1][(nt&1)*2];
            mma16816h(o[nt], qa[ks], bhp);
            mma16816h(o[nt], qa[ks], blp);
        }
        mma16816h(o[8], qa[ks], g2h);
        mma16816h(o[8], qa[ks], g2l);
    }

    // ---- intra-chunk causal ----
    float zacc0 = 0.f, zacc1 = 0.f;
    const int row0 = rbase + (lane >> 2), row1 = row0 + 8;
    const int ncc = wid/2 + 1;
    const uint32_t kb_col = (uint32_t)(((lane>>3)&1)*16);
    const uint32_t vb_rel = (uint32_t)(( ((lane>>3)&1)*8 + (lane&7) )*APITCH + ((lane>>4)*8)*2);

    for (int cc = 0; cc < ncc; cc++) {
        const int c0 = cc*32;
        float s[4][4];
        #pragma unroll
        for (int n = 0; n < 4; n++)
            #pragma unroll
            for (int l = 0; l < 4; l++) s[n][l] = 0.f;
        #pragma unroll
        for (int ks = 0; ks < 4; ks++) {
            uint32_t kb[2][4];
            #pragma unroll
            for (int p = 0; p < 2; p++) {
                const uint32_t kbo = (uint32_t)((c0 + 16*p + ((lane>>4)<<3) + (lane&7))*APITCH)
                                     + kb_col + (uint32_t)(ks*32);
                ldsm4(kb[p], sb + SK + kbo);
            }
            #pragma unroll
            for (int nt = 0; nt < 4; nt++) {
                const uint32_t* bp = &kb[nt>>1][(nt&1)*2];
                mma16816h(s[nt], qa[ks], bp);
            }
        }
        uint32_t af[2][4];
        #pragma unroll
        for (int nt = 0; nt < 4; nt++) {
            const int colj = c0 + nt*8 + (lane&3)*2;
            float e0 = (colj   <= row0) ? s[nt][0] : 0.f;
            float e1 = (colj+1 <= row0) ? s[nt][1] : 0.f;
            float e2 = (colj   <= row1) ? s[nt][2] : 0.f;
            float e3 = (colj+1 <= row1) ? s[nt][3] : 0.f;
            zacc0 += e0 + e1;
            zacc1 += e2 + e3;
            const int kk = nt >> 1, half = nt & 1;
            af[kk][half*2+0] = pack_h(e0, e1);
            af[kk][half*2+1] = pack_h(e2, e3);
        }
        #pragma unroll
        for (int kk = 0; kk < 2; kk++) {
            const uint32_t krow = (uint32_t)((c0 + kk*16))*APITCH;
            uint32_t vbh[4][4], vbl[4][4];
            #pragma unroll
            for (int p = 0; p < 4; p++) {
                ldsm4t(vbh[p], sb + SVH + krow + vb_rel + (uint32_t)(p*16*2));
                ldsm4t(vbl[p], sb + SVL + krow + vb_rel + (uint32_t)(p*16*2));
            }
            #pragma unroll
            for (int nt = 0; nt < 8; nt++) {
                const uint32_t* bhp = &vbh[nt>>1][(nt&1)*2];
                const uint32_t* blp = &vbl[nt>>1][(nt&1)*2];
                mma16816h(o[nt], af[kk], bhp);
                mma16816h(o[nt], af[kk], blp);
            }
        }
    }

    float z0 = zacc0 + ((lane & 3) == 0 ? o[8][0] : 0.f);
    float z1 = zacc1 + ((lane & 3) == 0 ? o[8][2] : 0.f);
    z0 += __shfl_xor_sync(0xffffffff, z0, 1);
    z0 += __shfl_xor_sync(0xffffffff, z0, 2);
    z1 += __shfl_xor_sync(0xffffffff, z1, 1);
    z1 += __shfl_xor_sync(0xffffffff, z1, 2);
    const float inv0 = 1.f / (z0 + 1e-6f);
    const float inv1 = 1.f / (z1 + 1e-6f);

    const int b = bh >> 4, h = bh & 15;
    const size_t mbase0 = ((size_t)(b*TSEQ + c*CHUNK + row0))*D_MODEL + h*DK;
    const size_t mbase1 = ((size_t)(b*TSEQ + c*CHUNK + row1))*D_MODEL + h*DK;
    #pragma unroll
    for (int nt = 0; nt < 8; nt++) {
        const int e = nt*8 + (lane&3)*2;
        float y0 = o[nt][0]*inv0, y1 = o[nt][1]*inv0;
        float y2 = o[nt][2]*inv1, y3 = o[nt][3]*inv1;
        *(__half2*)(g_ah + mbase0 + e) = __floats2half2_rn(y0, y1);
        *(__half2*)(g_ah + mbase1 + e) = __floats2half2_rn(y2, y3);
    }
}

// ---------------- launch ----------------
extern "C" void kernel_launch(void* const* d_in, const int* in_sizes, int n_in,
                              void* d_out, int out_size)
{
    (void)in_sizes; (void)n_in; (void)out_size;
    const float* x  = (const float*)d_in[0];
    const float* Wq = (const float*)d_in[1];
    const float* bq = (const float*)d_in[2];
    const float* Wk = (const float*)d_in[3];
    const float* bk = (const float*)d_in[4];
    const float* Wv = (const float*)d_in[5];
    const float* bv = (const float*)d_in[6];
    const float* Wo = (const float*)d_in[7];
    const float* bo = (const float*)d_in[8];
    float* out = (float*)d_out;

    cudaFuncSetAttribute(gemm_qkv, cudaFuncAttributeMaxDynamicSharedMemorySize, GEMM_SMEM);
    cudaFuncSetAttribute(gemm_wo,  cudaFuncAttributeMaxDynamicSharedMemorySize, GEMM_SMEM);
    cudaFuncSetAttribute(chunk_kv_mma,    cudaFuncAttributeMaxDynamicSharedMemorySize, CKV_SMEM);
    cudaFuncSetAttribute(attn_mma_kernel, cudaFuncAttributeMaxDynamicSharedMemorySize, ATT_SMEM);

    split_all_kernel<<<8192, 256>>>(x, Wq, Wk, Wv, Wo);

    dim3 gq(D_MODEL/128, MROWS/128, 3);   // (8, 32, 3)
    gemm_qkv<<<gq, 256, GEMM_SMEM>>>(bq, bk, bv);

    chunk_kv_mma<<<NBH*NCHUNK, 128, CKV_SMEM>>>();
    dim3 gs(NBH, (DK*KVE + 255)/256);     // (32, 18)
    chunk_scan_kernel<<<gs, 256>>>();
    attn_mma_kernel<<<NBH*NCHUNK, 256, ATT_SMEM>>>();

    dim3 go(D_MODEL/128, MROWS/128);      // (8, 32)
    gemm_wo<<<go, 256, GEMM_SMEM>>>(bo, out);
}

// round 14
// speedup vs baseline: 7.8214x; 1.0817x over previous
#include <cuda_runtime.h>
#include <cuda_bf16.h>
#include <cuda_fp16.h>
#include <cstdint>

#define D_MODEL 1024
#define N_HEADS 16
#define DK 64
#define BATCH 2
#define TSEQ 2048
#define MROWS (BATCH*TSEQ)   /* 4096 */
#define CHUNK 128
#define NCHUNK (TSEQ/CHUNK)  /* 16 */
#define NBH (BATCH*N_HEADS)  /* 32 */
#define KVE 72               /* KV ext cols: 64 + ksum + pad */

// ---------------- scratch (static device arrays; no allocation) ----------------
__device__ float g_kv[NBH*NCHUNK*DK*DK];
__device__ float g_ksum[NBH*NCHUNK*DK];
// fp16 GEMM operands (W pre-scaled by 32)
__device__ __half g_xh[MROWS*D_MODEL];
__device__ __half g_wh[4*D_MODEL*D_MODEL];
__device__ __half g_ah[MROWS*D_MODEL];
// fp16 attention operands (all single fp16)
__device__ __half g_qf[NBH*TSEQ*DK];
__device__ __half g_kf[NBH*TSEQ*DK];
__device__ __half g_vf[NBH*TSEQ*DK];
__device__ __half g_kvf[NBH*NCHUNK*DK*KVE];

__device__ __forceinline__ float phi_fn(float x) {
    return x > 0.f ? x + 1.f : __expf(x);
}
__device__ __forceinline__ uint32_t smem_to_u32(const void* smem_ptr) {
    uint32_t addr;
    asm("{ .reg .u64 tmp; cvta.to.shared.u64 tmp, %1; cvt.u32.u64 %0, tmp; }"
        : "=r"(addr) : "l"(smem_ptr));
    return addr;
}

// ---------------- mma / ldmatrix / cp.async primitives ----------------
__device__ __forceinline__ void mma16816h(float* d, const uint32_t* a, const uint32_t* b) {
    asm volatile(
        "mma.sync.aligned.m16n8k16.row.col.f32.f16.f16.f32 "
        "{%0,%1,%2,%3}, {%4,%5,%6,%7}, {%8,%9}, {%0,%1,%2,%3};"
        : "+f"(d[0]), "+f"(d[1]), "+f"(d[2]), "+f"(d[3])
        : "r"(a[0]), "r"(a[1]), "r"(a[2]), "r"(a[3]), "r"(b[0]), "r"(b[1]));
}
__device__ __forceinline__ void ldsm4(uint32_t* r, uint32_t addr) {
    asm volatile("ldmatrix.sync.aligned.m8n8.x4.shared.b16 {%0,%1,%2,%3}, [%4];"
        : "=r"(r[0]), "=r"(r[1]), "=r"(r[2]), "=r"(r[3]) : "r"(addr));
}
__device__ __forceinline__ void ldsm4t(uint32_t* r, uint32_t addr) {
    asm volatile("ldmatrix.sync.aligned.m8n8.x4.trans.shared.b16 {%0,%1,%2,%3}, [%4];"
        : "=r"(r[0]), "=r"(r[1]), "=r"(r[2]), "=r"(r[3]) : "r"(addr));
}
__device__ __forceinline__ void ldsm2t(uint32_t* r, uint32_t addr) {
    asm volatile("ldmatrix.sync.aligned.m8n8.x2.trans.shared.b16 {%0,%1}, [%2];"
        : "=r"(r[0]), "=r"(r[1]) : "r"(addr));
}
#define CP_ASYNC16(dst, src) \
    asm volatile("cp.async.cg.shared.global [%0], [%1], 16;" :: "r"(dst), "l"(src))
#define CP_COMMIT() asm volatile("cp.async.commit_group;" ::: "memory")
#define CP_WAIT1()  asm volatile("cp.async.wait_group 1;" ::: "memory")
#define CP_WAIT0()  asm volatile("cp.async.wait_group 0;" ::: "memory")

__device__ __forceinline__ uint32_t pack_h(float a, float b) {
    __half2 p = __floats2half2_rn(a, b);
    return *reinterpret_cast<uint32_t*>(&p);
}
#define SWZ128(off) ((uint32_t)(off) ^ ((((uint32_t)(off)) >> 3) & 0x70))

// ---------------- merged input conversion ----------------
__global__ __launch_bounds__(256) void split_all_kernel(
    const float* __restrict__ x,
    const float* __restrict__ w0, const float* __restrict__ w1,
    const float* __restrict__ w2, const float* __restrict__ w3)
{
    const int per = D_MODEL*D_MODEL/4;          // 262144
    int i = blockIdx.x * 256 + threadIdx.x;
    if (i < MROWS*D_MODEL/4) {
        float4 v = ((const float4*)x)[i];
        ((__half2*)(g_xh + 4*(size_t)i))[0] = __floats2half2_rn(v.x, v.y);
        ((__half2*)(g_xh + 4*(size_t)i))[1] = __floats2half2_rn(v.z, v.w);
    } else {
        int j = i - MROWS*D_MODEL/4;
        int sel = j >> 18, loc = j & (per - 1);
        const float* src = (sel == 0) ? w0 : (sel == 1) ? w1 : (sel == 2) ? w2 : w3;
        float4 v = ((const float4*)src)[loc];
        size_t o = (size_t)sel * D_MODEL * D_MODEL + 4*(size_t)loc;
        ((__half2*)(g_wh + o))[0] = __floats2half2_rn(v.x*32.f, v.y*32.f);
        ((__half2*)(g_wh + o))[1] = __floats2half2_rn(v.z*32.f, v.w*32.f);
    }
}

// ---------------- fp16 GEMM: BK=64, 3-stage, SW128, 2 CTAs/SM ----------------
#define TILE_B (128*128)
#define STAGE_B (2*TILE_B)
#define GEMM_SMEM (3*STAGE_B)       /* 98304 */
#define NSTG 16

__device__ __forceinline__ void gemm_body(
    int ep, const __half* __restrict__ Xh,
    const float* __restrict__ bias, float* __restrict__ outp, char* smem)
{
    const uint32_t sb = smem_to_u32(smem);
    const int tid = threadIdx.x;
    const int lane = tid & 31, wid = tid >> 5;
    const int wm = wid & 1, wn = wid >> 1;
    const int m0 = blockIdx.y * 128;
    const int n0 = blockIdx.x * 128;

    const __half* Wh = g_wh + (size_t)ep * D_MODEL * D_MODEL;

    float acc[4][4][4];
    #pragma unroll
    for (int i = 0; i < 4; i++)
        #pragma unroll
        for (int j = 0; j < 4; j++)
            #pragma unroll
            for (int l = 0; l < 4; l++) acc[i][j][l] = 0.f;

    const int lr = tid >> 2, lu = (tid & 3) * 2;
    const uint32_t d00 = SWZ128(lr*128 + lu*16),        d01 = SWZ128(lr*128 + (lu+1)*16);
    const uint32_t d10 = SWZ128((lr+64)*128 + lu*16),   d11 = SWZ128((lr+64)*128 + (lu+1)*16);

    auto load_stage = [&](int buf, int k0) {
        uint32_t base = sb + buf * STAGE_B;
        CP_ASYNC16(base + d00, Xh + (size_t)(m0 + lr)*D_MODEL + k0 + lu*8);
        CP_ASYNC16(base + d01, Xh + (size_t)(m0 + lr)*D_MODEL + k0 + lu*8 + 8);
        CP_ASYNC16(base + d10, Xh + (size_t)(m0 + lr + 64)*D_MODEL + k0 + lu*8);
        CP_ASYNC16(base + d11, Xh + (size_t)(m0 + lr + 64)*D_MODEL + k0 + lu*8 + 8);
        base += TILE_B;
        CP_ASYNC16(base + d00, Wh + (size_t)(n0 + lr)*D_MODEL + k0 + lu*8);
        CP_ASYNC16(base + d01, Wh + (size_t)(n0 + lr)*D_MODEL + k0 + lu*8 + 8);
        CP_ASYNC16(base + d10, Wh + (size_t)(n0 + lr + 64)*D_MODEL + k0 + lu*8);
        CP_ASYNC16(base + d11, Wh + (size_t)(n0 + lr + 64)*D_MODEL + k0 + lu*8 + 8);
        CP_COMMIT();
    };

    load_stage(0, 0);
    load_stage(1, 64);

    for (int kc = 0; kc < NSTG; kc++) {
        if (kc < NSTG-1) { CP_WAIT1(); } else { CP_WAIT0(); }
        __syncthreads();
        if (kc + 2 < NSTG) load_stage((kc + 2) % 3, (kc + 2) * 64);

        const uint32_t base = sb + (kc % 3) * STAGE_B;
        #pragma unroll
        for (int ks = 0; ks < 4; ks++) {
            uint32_t ah[4][4], bh[2][4];
            #pragma unroll
            for (int mt = 0; mt < 4; mt++) {
                const int rA = wm*64 + mt*16 + (lane & 15);
                const uint32_t offA = SWZ128(rA*128 + ((lane >> 4) + 2*ks)*16);
                ldsm4(ah[mt], base + offA);
            }
            #pragma unroll
            for (int op = 0; op < 2; op++) {
                const int rB = wn*32 + op*16 + ((lane >> 4) << 3) + (lane & 7);
                const uint32_t offB = SWZ128(rB*128 + (((lane >> 3) & 1) + 2*ks)*16);
                ldsm4(bh[op], base + TILE_B + offB);
            }
            #pragma unroll
            for (int mt = 0; mt < 4; mt++)
                #pragma unroll
                for (int nt = 0; nt < 4; nt++) {
                    const uint32_t* bhp = &bh[nt >> 1][(nt & 1) * 2];
                    mma16816h(acc[mt][nt], ah[mt], bhp);
                }
        }
    }
    __syncthreads();

    // ---- epilogue (acc is 32x scaled) ----
    const float INV32 = 1.f/32.f;
    const int m_base = m0 + wm*64;
    #pragma unroll
    for (int mt = 0; mt < 4; mt++) {
        #pragma unroll
        for (int nt = 0; nt < 4; nt++) {
            const int n = n0 + wn*32 + nt*8 + (lane & 3)*2;
            const float b0v = bias[n], b1v = bias[n+1];
            #pragma unroll
            for (int half = 0; half < 2; half++) {
                const int m = m_base + mt*16 + (lane >> 2) + half*8;
                float y0 = acc[mt][nt][half*2+0]*INV32 + b0v;
                float y1 = acc[mt][nt][half*2+1]*INV32 + b1v;
                if (ep <= 1) { y0 = phi_fn(y0); y1 = phi_fn(y1); }
                if (ep <= 2) {
                    const int h = n >> 6, d = n & 63;
                    const int b = m >> 11, t = m & (TSEQ-1);
                    const size_t off = ((size_t)((b*N_HEADS + h)*TSEQ + t))*DK + d;
                    __half* dst = (ep == 0) ? g_qf : (ep == 1) ? g_kf : g_vf;
                    *(__half2*)(dst + off) = __floats2half2_rn(y0, y1);
                } else {
                    *(float2*)(outp + (size_t)m*D_MODEL + n) = make_float2(y0, y1);
                }
            }
        }
    }
}

__global__ __launch_bounds__(256, 2) void gemm_qkv(
    const float* __restrict__ bq, const float* __restrict__ bk,
    const float* __restrict__ bv)
{
    extern __shared__ char smem[];
    const int ep = blockIdx.z;
    const float* bias = (ep == 0) ? bq : (ep == 1) ? bk : bv;
    gemm_body(ep, g_xh, bias, nullptr, smem);
}
__global__ __launch_bounds__(256, 2) void gemm_wo(
    const float* __restrict__ bo, float* __restrict__ outp)
{
    extern __shared__ char smem[];
    gemm_body(3, g_ah, bo, outp, smem);
}

// ================= attention on tensor cores (fp16, single precision level) =================
#define APITCH 144
#define ATILE (128*APITCH)
#define KVTILE (DK*APITCH)

// ---------------- per-chunk K^T V and k-sum ----------------
#define CKV_SMEM (2*ATILE)          /* K, V = 36864 */
__global__ __launch_bounds__(128, 4) void chunk_kv_mma()
{
    extern __shared__ char smem[];
    const uint32_t sb = smem_to_u32(smem);
    const uint32_t SK = 0, SV = ATILE;
    const int blk = blockIdx.x;
    const int bh = blk >> 4, c = blk & 15;
    const int tid = threadIdx.x;
    const int lane = tid & 31, wid = tid >> 5;
    const size_t gbase = (size_t)bh*TSEQ*DK + (size_t)c*CHUNK*DK;

    #pragma unroll
    for (int it = 0; it < 8; it++) {
        int idx = tid + it*128;
        int r = idx >> 3, cc = idx & 7;
        const size_t so = gbase + (size_t)r*DK + cc*8;
        *(float4*)(smem + SK + r*APITCH + cc*16) = *(const float4*)(g_kf + so);
        *(float4*)(smem + SV + r*APITCH + cc*16) = *(const float4*)(g_vf + so);
    }
    {
        int r = tid;
        *(float4*)(smem + SV + r*APITCH + 128) =
            make_float4(__uint_as_float(0x00003C00u), 0.f, 0.f, 0.f);
    }
    __syncthreads();

    float f[8][4];
    #pragma unroll
    for (int n = 0; n < 8; n++)
        #pragma unroll
        for (int l = 0; l < 4; l++) f[n][l] = 0.f;
    float f8[4] = {0.f, 0.f, 0.f, 0.f};

    const uint32_t ka_rel = (uint32_t)(( ((lane>>4)&1)*8 + (lane&7) )*APITCH
                                       + (wid*16 + ((lane>>3)&1)*8)*2);
    const uint32_t vb_rel = (uint32_t)(( ((lane>>3)&1)*8 + (lane&7) )*APITCH
                                       + ((lane>>4)*8)*2);
    const uint32_t v2_rel = (uint32_t)(( ((lane>>3)&1)*8 + (lane&7) )*APITCH + 64*2);
    #pragma unroll
    for (int ks = 0; ks < 8; ks++) {
        const uint32_t krow = (uint32_t)(ks*16)*APITCH;
        uint32_t kah[4], vb[4][4], v2[2];
        ldsm4t(kah, sb + SK + krow + ka_rel);
        #pragma unroll
        for (int p = 0; p < 4; p++)
            ldsm4t(vb[p], sb + SV + krow + vb_rel + (uint32_t)(p*16*2));
        ldsm2t(v2, sb + SV + krow + v2_rel);
        #pragma unroll
        for (int nt = 0; nt < 8; nt++)
            mma16816h(f[nt], kah, &vb[nt>>1][(nt&1)*2]);
        mma16816h(f8, kah, v2);
    }

    float* kvout = g_kv + (size_t)blk*DK*DK;
    const int d0 = wid*16 + (lane>>2);
    #pragma unroll
    for (int nt = 0; nt < 8; nt++) {
        const int e = nt*8 + (lane&3)*2;
        *(float2*)(kvout + (size_t)d0*DK + e)     = make_float2(f[nt][0], f[nt][1]);
        *(float2*)(kvout + (size_t)(d0+8)*DK + e) = make_float2(f[nt][2], f[nt][3]);
    }
    if ((lane & 3) == 0) {
        g_ksum[(size_t)blk*DK + d0]     = f8[0];
        g_ksum[(size_t)blk*DK + d0 + 8] = f8[2];
    }
}

// ---------------- exclusive prefix scan: preload all chunks, then scan ----------------
__global__ __launch_bounds__(256) void chunk_scan_kernel()
{
    const int bh = blockIdx.x;
    const int pos = blockIdx.y * 256 + threadIdx.x;
    if (pos >= DK*KVE) return;
    const int d = pos / KVE, e = pos % KVE;

    float vals[NCHUNK];
    #pragma unroll
    for (int c = 0; c < NCHUNK; c++) {
        const size_t blk = (size_t)(bh*NCHUNK + c);
        float v = 0.f;
        if (e < DK)       v = g_kv[blk*DK*DK + (size_t)d*DK + e];
        else if (e == DK) v = g_ksum[blk*DK + d];
        vals[c] = v;
    }
    float run = 0.f;
    #pragma unroll
    for (int c = 0; c < NCHUNK; c++) {
        const size_t blk = (size_t)(bh*NCHUNK + c);
        g_kvf[blk*DK*KVE + pos] = __float2half(run);
        run += vals[c];
    }
}

// ---------------- per-chunk attention (fp16, causal) ----------------
#define ATT_SMEM (3*ATILE + KVTILE)   /* 64512 -> 2 CTAs/SM */
__global__ __launch_bounds__(256, 2) void attn_mma_kernel()
{
    extern __shared__ char smem[];
    const uint32_t sb = smem_to_u32(smem);
    const uint32_t SQ = 0, SK = ATILE, SV = 2*ATILE;
    const uint32_t SG = 3*ATILE;

    const int blk = blockIdx.x;
    const int bh = blk >> 4, c = blk & 15;
    const int tid = threadIdx.x;
    const int lane = tid & 31, wid = tid >> 5;
    const size_t gbase = (size_t)bh*TSEQ*DK + (size_t)c*CHUNK*DK;

    #pragma unroll
    for (int it = 0; it < 4; it++) {
        int idx = tid + it*256;
        int r = idx >> 3, cc = idx & 7;
        const size_t so = gbase + (size_t)r*DK + cc*8;
        const uint32_t doff = r*APITCH + cc*16;
        *(float4*)(smem + SQ + doff) = *(const float4*)(g_qf + so);
        *(float4*)(smem + SK + doff) = *(const float4*)(g_kf + so);
        *(float4*)(smem + SV + doff) = *(const float4*)(g_vf + so);
    }
    {
        const size_t kvbase = (size_t)blk*DK*KVE;
        for (int idx = tid; idx < 576; idx += 256) {
            int r = idx / 9, cc = idx % 9;
            *(float4*)(smem + SG + r*APITCH + cc*16) =
                *(const float4*)(g_kvf + kvbase + (size_t)r*KVE + cc*8);
        }
    }
    __syncthreads();

    const int rbase = wid * 16;
    const uint32_t qa_rel = (uint32_t)((rbase + (lane & 15))*APITCH + (lane >> 4)*16);
    uint32_t qa[4][4];
    #pragma unroll
    for (int ks = 0; ks < 4; ks++)
        ldsm4(qa[ks], sb + SQ + qa_rel + ks*32);

    float o[9][4];
    #pragma unroll
    for (int n = 0; n < 9; n++)
        #pragma unroll
        for (int l = 0; l < 4; l++) o[n][l] = 0.f;

    // ---- inter-chunk: o += q @ KV_prev ----
    const uint32_t gb_rel = (uint32_t)(( ((lane>>3)&1)*8 + (lane&7) )*APITCH + ((lane>>4)*8)*2);
    #pragma unroll
    for (int ks = 0; ks < 4; ks++) {
        const uint32_t krow = (uint32_t)(ks*16)*APITCH;
        uint32_t gb[4][4], g2[2];
        #pragma unroll
        for (int p = 0; p < 4; p++)
            ldsm4t(gb[p], sb + SG + krow + gb_rel + (uint32_t)(p*16*2));
        const uint32_t g2_rel = (uint32_t)(( ((lane>>3)&1)*8 + (lane&7) )*APITCH + 64*2);
        ldsm2t(g2, sb + SG + krow + g2_rel);
        #pragma unroll
        for (int nt = 0; nt < 8; nt++)
            mma16816h(o[nt], qa[ks], &gb[nt>>1][(nt&1)*2]);
        mma16816h(o[8], qa[ks], g2);
    }

    // ---- intra-chunk causal ----
    float zacc0 = 0.f, zacc1 = 0.f;
    const int row0 = rbase + (lane >> 2), row1 = row0 + 8;
    const int ncc = wid/2 + 1;
    const uint32_t kb_col = (uint32_t)(((lane>>3)&1)*16);
    const uint32_t vb_rel = (uint32_t)(( ((lane>>3)&1)*8 + (lane&7) )*APITCH + ((lane>>4)*8)*2);

    for (int cc = 0; cc < ncc; cc++) {
        const int c0 = cc*32;
        float s[4][4];
        #pragma unroll
        for (int n = 0; n < 4; n++)
            #pragma unroll
            for (int l = 0; l < 4; l++) s[n][l] = 0.f;
        #pragma unroll
        for (int ks = 0; ks < 4; ks++) {
            uint32_t kb[2][4];
            #pragma unroll
            for (int p = 0; p < 2; p++) {
                const uint32_t kbo = (uint32_t)((c0 + 16*p + ((lane>>4)<<3) + (lane&7))*APITCH)
                                     + kb_col + (uint32_t)(ks*32);
                ldsm4(kb[p], sb + SK + kbo);
            }
            #pragma unroll
            for (int nt = 0; nt < 4; nt++)
                mma16816h(s[nt], qa[ks], &kb[nt>>1][(nt&1)*2]);
        }
        uint32_t af[2][4];
        #pragma unroll
        for (int nt = 0; nt < 4; nt++) {
            const int colj = c0 + nt*8 + (lane&3)*2;
            float e0 = (colj   <= row0) ? s[nt][0] : 0.f;
            float e1 = (colj+1 <= row0) ? s[nt][1] : 0.f;
            float e2 = (colj   <= row1) ? s[nt][2] : 0.f;
            float e3 = (colj+1 <= row1) ? s[nt][3] : 0.f;
            zacc0 += e0 + e1;
            zacc1 += e2 + e3;
            const int kk = nt >> 1, half = nt & 1;
            af[kk][half*2+0] = pack_h(e0, e1);
            af[kk][half*2+1] = pack_h(e2, e3);
        }
        #pragma unroll
        for (int kk = 0; kk < 2; kk++) {
            const uint32_t krow = (uint32_t)((c0 + kk*16))*APITCH;
            uint32_t vb[4][4];
            #pragma unroll
            for (int p = 0; p < 4; p++)
                ldsm4t(vb[p], sb + SV + krow + vb_rel + (uint32_t)(p*16*2));
            #pragma unroll
            for (int nt = 0; nt < 8; nt++)
                mma16816h(o[nt], af[kk], &vb[nt>>1][(nt&1)*2]);
        }
    }

    float z0 = zacc0 + ((lane & 3) == 0 ? o[8][0] : 0.f);
    float z1 = zacc1 + ((lane & 3) == 0 ? o[8][2] : 0.f);
    z0 += __shfl_xor_sync(0xffffffff, z0, 1);
    z0 += __shfl_xor_sync(0xffffffff, z0, 2);
    z1 += __shfl_xor_sync(0xffffffff, z1, 1);
    z1 += __shfl_xor_sync(0xffffffff, z1, 2);
    const float inv0 = 1.f / (z0 + 1e-6f);
    const float inv1 = 1.f / (z1 + 1e-6f);

    const int b = bh >> 4, h = bh & 15;
    const size_t mbase0 = ((size_t)(b*TSEQ + c*CHUNK + row0))*D_MODEL + h*DK;
    const size_t mbase1 = ((size_t)(b*TSEQ + c*CHUNK + row1))*D_MODEL + h*DK;
    #pragma unroll
    for (int nt = 0; nt < 8; nt++) {
        const int e = nt*8 + (lane&3)*2;
        float y0 = o[nt][0]*inv0, y1 = o[nt][1]*inv0;
        float y2 = o[nt][2]*inv1, y3 = o[nt][3]*inv1;
        *(__half2*)(g_ah + mbase0 + e) = __floats2half2_rn(y0, y1);
        *(__half2*)(g_ah + mbase1 + e) = __floats2half2_rn(y2, y3);
    }
}

// ---------------- launch ----------------
extern "C" void kernel_launch(void* const* d_in, const int* in_sizes, int n_in,
                              void* d_out, int out_size)
{
    (void)in_sizes; (void)n_in; (void)out_size;
    const float* x  = (const float*)d_in[0];
    const float* Wq = (const float*)d_in[1];
    const float* bq = (const float*)d_in[2];
    const float* Wk = (const float*)d_in[3];
    const float* bk = (const float*)d_in[4];
    const float* Wv = (const float*)d_in[5];
    const float* bv = (const float*)d_in[6];
    const float* Wo = (const float*)d_in[7];
    const float* bo = (const float*)d_in[8];
    float* out = (float*)d_out;

    cudaFuncSetAttribute(gemm_qkv, cudaFuncAttributeMaxDynamicSharedMemorySize, GEMM_SMEM);
    cudaFuncSetAttribute(gemm_wo,  cudaFuncAttributeMaxDynamicSharedMemorySize, GEMM_SMEM);
    cudaFuncSetAttribute(chunk_kv_mma,    cudaFuncAttributeMaxDynamicSharedMemorySize, CKV_SMEM);
    cudaFuncSetAttribute(attn_mma_kernel, cudaFuncAttributeMaxDynamicSharedMemorySize, ATT_SMEM);

    split_all_kernel<<<8192, 256>>>(x, Wq, Wk, Wv, Wo);

    dim3 gq(D_MODEL/128, MROWS/128, 3);   // (8, 32, 3)
    gemm_qkv<<<gq, 256, GEMM_SMEM>>>(bq, bk, bv);

    chunk_kv_mma<<<NBH*NCHUNK, 128, CKV_SMEM>>>();
    dim3 gs(NBH, (DK*KVE + 255)/256);     // (32, 18)
    chunk_scan_kernel<<<gs, 256>>>();
    attn_mma_kernel<<<NBH*NCHUNK, 256, ATT_SMEM>>>();

    dim3 go(D_MODEL/128, MROWS/128);      // (8, 32)
    gemm_wo<<<go, 256, GEMM_SMEM>>>(bo, out);
}